// round 9
// baseline (speedup 1.0000x reference)
#include <cuda_runtime.h>
#include <cuda_bf16.h>
#include <math.h>
#include <stdint.h>

#define B_SZ   2
#define S_LEN  2048
#define HID_   2048
#define NH     32
#define NKV    8
#define D_HEAD 64
#define M_FEAT 256
#define NC     16
#define CHUNK  128
#define QKVW   3072

// ---------------- scratch (device globals; no allocations allowed) ----------------
__device__ float g_qkv [(size_t)B_SZ * S_LEN * QKVW];
__device__ float g_xpk [(size_t)B_SZ * NKV * S_LEN * M_FEAT];
__device__ float g_sqk [B_SZ * NKV * S_LEN];
__device__ float g_stab[B_SZ * NKV];
__device__ float g_kv  [B_SZ * NKV * NC * M_FEAT * D_HEAD];
__device__ float g_kz  [B_SZ * NKV * NC * M_FEAT];

#define PHIQ_E ((size_t)B_SZ * NH  * S_LEN * M_FEAT)
#define PHIK_E ((size_t)B_SZ * NKV * S_LEN * M_FEAT)
#define HS_ELEMS  (B_SZ * S_LEN * HID_)
#define W_ELEMS   (QKVW * HID_ + HID_ * HID_)
__device__ __align__(16) __nv_bfloat16 g_pqh[PHIQ_E];
__device__ __align__(16) __nv_bfloat16 g_pql[PHIQ_E];
__device__ __align__(16) __nv_bfloat16 g_pkh[PHIK_E];
__device__ __align__(16) __nv_bfloat16 g_pkl[PHIK_E];
__device__ __align__(16) __nv_bfloat16 g_hsh[HS_ELEMS];
__device__ __align__(16) __nv_bfloat16 g_hsl[HS_ELEMS];
__device__ __align__(16) __nv_bfloat16 g_ath[HS_ELEMS];
__device__ __align__(16) __nv_bfloat16 g_atl[HS_ELEMS];
__device__ __align__(16) __nv_bfloat16 g_wh [W_ELEMS];
__device__ __align__(16) __nv_bfloat16 g_wl [W_ELEMS];

#define WQ_OFF 0
#define WK_OFF (HID_ * HID_)
#define WV_OFF (WK_OFF + 512 * HID_)
#define WO_OFF (WV_OFF + 512 * HID_)

// =================== fp32 -> bf16 hi/lo split (elementwise, x4 vec) ================
__global__ void split_bf16(const float* __restrict__ x, __nv_bfloat16* __restrict__ h,
                           __nv_bfloat16* __restrict__ l, int n4)
{
    int i = blockIdx.x * blockDim.x + threadIdx.x;
    if (i >= n4) return;
    float4 v = ((const float4*)x)[i];
    __nv_bfloat16 h0 = __float2bfloat16(v.x), h1 = __float2bfloat16(v.y);
    __nv_bfloat16 h2 = __float2bfloat16(v.z), h3 = __float2bfloat16(v.w);
    __nv_bfloat162* hp = (__nv_bfloat162*)h;
    hp[2 * i]     = __nv_bfloat162(h0, h1);
    hp[2 * i + 1] = __nv_bfloat162(h2, h3);
    __nv_bfloat162* lp = (__nv_bfloat162*)l;
    lp[2 * i]     = __nv_bfloat162(__float2bfloat16(v.x - __bfloat162float(h0)),
                                   __float2bfloat16(v.y - __bfloat162float(h1)));
    lp[2 * i + 1] = __nv_bfloat162(__float2bfloat16(v.z - __bfloat162float(h2)),
                                   __float2bfloat16(v.w - __bfloat162float(h3)));
}

// ===================== shared helpers for tensor-core kernels ======================
__device__ __forceinline__ uint32_t smem_u32g(const void* p)
{
    uint32_t a;
    asm("{ .reg .u64 t; cvta.to.shared.u64 t, %1; cvt.u32.u64 %0, t; }" : "=r"(a) : "l"(p));
    return a;
}

#define LDSM4(r, a) \
    asm volatile("ldmatrix.sync.aligned.m8n8.x4.shared.b16 {%0,%1,%2,%3}, [%4];" \
                 : "=r"((r)[0]), "=r"((r)[1]), "=r"((r)[2]), "=r"((r)[3]) : "r"(a))

#define CP_ASYNC16(dst, src) \
    asm volatile("cp.async.cg.shared.global [%0], [%1], 16;" :: "r"(dst), "l"(src) : "memory")
#define CP_COMMIT() asm volatile("cp.async.commit_group;" ::: "memory")
#define CP_WAIT(n)  asm volatile("cp.async.wait_group %0;" :: "n"(n) : "memory")

__device__ __forceinline__ void mma_bf16(float c[4], const uint32_t a[4], const uint32_t b[2])
{
    asm volatile("mma.sync.aligned.m16n8k16.row.col.f32.bf16.bf16.f32 "
                 "{%0,%1,%2,%3}, {%4,%5,%6,%7}, {%8,%9}, {%0,%1,%2,%3};"
                 : "+f"(c[0]), "+f"(c[1]), "+f"(c[2]), "+f"(c[3])
                 : "r"(a[0]), "r"(a[1]), "r"(a[2]), "r"(a[3]), "r"(b[0]), "r"(b[1]));
}

__device__ __forceinline__ void pack8(const float* f, uint4& hv, uint4& lv)
{
    uint32_t hw[4], lw[4];
#pragma unroll
    for (int e = 0; e < 4; e++) {
        __nv_bfloat16 h0 = __float2bfloat16(f[2 * e]);
        __nv_bfloat16 h1 = __float2bfloat16(f[2 * e + 1]);
        __nv_bfloat162 hp(h0, h1);
        hw[e] = *(uint32_t*)&hp;
        __nv_bfloat162 lp(__float2bfloat16(f[2 * e]     - __bfloat162float(h0)),
                          __float2bfloat16(f[2 * e + 1] - __bfloat162float(h1)));
        lw[e] = *(uint32_t*)&lp;
    }
    hv = make_uint4(hw[0], hw[1], hw[2], hw[3]);
    lv = make_uint4(lw[0], lw[1], lw[2], lw[3]);
}

// ======== bf16 3-pass split GEMM v3: 256x256 tile, cp.async, ldmatrix ==============
// C(M,N) = A(M,K) @ W(N,K)^T, C = Ah*Bh + Ah*Bl + Al*Bh (fp32 accum).
// 512 threads (16 warps, 4m x 4n; warp = 64m x 64n). BK=32, double-buffered.
// Buffer (64KB): Ah[0,16K) Al[16,32K) Bh[32,48K) Bl[48,64K); 256 rows x 64B, swizzled.
#define GK 2048
#define BK 32
#define NKT (GK / BK)
#define GBUF 65536
#define SMEM_GEMM (2 * GBUF)

__global__ __launch_bounds__(512, 1) void gemm_bf16x3(const __nv_bfloat16* __restrict__ Ah,
                                                      const __nv_bfloat16* __restrict__ Al,
                                                      const __nv_bfloat16* __restrict__ Bh,
                                                      const __nv_bfloat16* __restrict__ Bl,
                                                      float* __restrict__ C, int N)
{
    extern __shared__ char smc[];
    const uint32_t sb = smem_u32g(smc);
    const int tid  = threadIdx.x;
    const int warp = tid >> 5, lane = tid & 31;
    const int gid  = lane >> 2, tig = lane & 3;
    const int wm   = (warp & 3) * 64;
    const int wn   = (warp >> 2) * 64;
    const int rowA = blockIdx.y * 256;
    const int rowB = blockIdx.x * 256;

    // staging: 2 chunks/thread/section; chunk -> row = chunk>>2, slot = chunk&3
    const int c0 = tid,        r0s = c0 >> 2, s0s = c0 & 3;
    const int c1 = tid + 512,  r1s = c1 >> 2, s1s = c1 & 3;
    const uint32_t so0 = (uint32_t)(r0s * 64 + ((s0s ^ ((r0s >> 1) & 3)) * 16));
    const uint32_t so1 = (uint32_t)(r1s * 64 + ((s1s ^ ((r1s >> 1) & 3)) * 16));

    const int swm   = ((lane & 7) >> 1) & 3;
    const int rlocA = (lane & 7) + (((lane >> 3) & 1) << 3);
    const int shA   = lane >> 4;
    const int rlocB = (lane & 7) + ((lane >> 4) << 3);
    const int shB   = (lane >> 3) & 1;

    float acc[4][8][4];
#pragma unroll
    for (int i = 0; i < 4; i++)
#pragma unroll
        for (int j = 0; j < 8; j++)
#pragma unroll
            for (int r = 0; r < 4; r++) acc[i][j][r] = 0.f;

    auto stage = [&](int kt, int b) {
        const uint32_t bb = sb + b * GBUF;
        const int kb = kt * BK;
        CP_ASYNC16(bb + so0,         (const char*)(Ah + (size_t)(rowA + r0s) * GK + kb + s0s * 8));
        CP_ASYNC16(bb + so1,         (const char*)(Ah + (size_t)(rowA + r1s) * GK + kb + s1s * 8));
        CP_ASYNC16(bb + 16384 + so0, (const char*)(Al + (size_t)(rowA + r0s) * GK + kb + s0s * 8));
        CP_ASYNC16(bb + 16384 + so1, (const char*)(Al + (size_t)(rowA + r1s) * GK + kb + s1s * 8));
        CP_ASYNC16(bb + 32768 + so0, (const char*)(Bh + (size_t)(rowB + r0s) * GK + kb + s0s * 8));
        CP_ASYNC16(bb + 32768 + so1, (const char*)(Bh + (size_t)(rowB + r1s) * GK + kb + s1s * 8));
        CP_ASYNC16(bb + 49152 + so0, (const char*)(Bl + (size_t)(rowB + r0s) * GK + kb + s0s * 8));
        CP_ASYNC16(bb + 49152 + so1, (const char*)(Bl + (size_t)(rowB + r1s) * GK + kb + s1s * 8));
        CP_COMMIT();
    };

    stage(0, 0);

    for (int kt = 0; kt < NKT; kt++) {
        if (kt + 1 < NKT) {
            stage(kt + 1, (kt + 1) & 1);
            CP_WAIT(1);
        } else {
            CP_WAIT(0);
        }
        __syncthreads();

        const uint32_t base = sb + (kt & 1) * GBUF;
#pragma unroll
        for (int kb = 0; kb < 2; kb++) {
            uint32_t ah[4][4], al[4][4];
#pragma unroll
            for (int tm = 0; tm < 4; tm++) {
                const int r = wm + tm * 16 + rlocA;
                const uint32_t off = (uint32_t)(r * 64 + (((2 * kb + shA) ^ swm) * 16));
                LDSM4(ah[tm], base + off);
                LDSM4(al[tm], base + 16384 + off);
            }
#pragma unroll
            for (int p = 0; p < 4; p++) {
                uint32_t bhf[4], blf[4];
                const int r = wn + p * 16 + rlocB;
                const uint32_t off = (uint32_t)(r * 64 + (((2 * kb + shB) ^ swm) * 16));
                LDSM4(bhf, base + 32768 + off);
                LDSM4(blf, base + 49152 + off);
#pragma unroll
                for (int tm = 0; tm < 4; tm++)
#pragma unroll
                    for (int tq = 0; tq < 2; tq++) {
                        const int tn = p * 2 + tq;
                        mma_bf16(acc[tm][tn], ah[tm], &bhf[tq * 2]);
                        mma_bf16(acc[tm][tn], ah[tm], &blf[tq * 2]);
                        mma_bf16(acc[tm][tn], al[tm], &bhf[tq * 2]);
                    }
            }
        }
        __syncthreads();
    }

    // ---- epilogue ----
#pragma unroll
    for (int tm = 0; tm < 4; tm++) {
        const size_t r0 = (size_t)rowA + wm + tm * 16 + gid;
#pragma unroll
        for (int tn = 0; tn < 8; tn++) {
            const int cn = rowB + wn + tn * 8 + tig * 2;
            *(float2*)(C + r0 * N + cn)       = make_float2(acc[tm][tn][0], acc[tm][tn][1]);
            *(float2*)(C + (r0 + 8) * N + cn) = make_float2(acc[tm][tn][2], acc[tm][tn][3]);
        }
    }
}

// ---------------- RoPE, in place on combined buffer --------------------------------
__global__ void rope_kernel(float* __restrict__ x, const float* __restrict__ cosp,
                            const float* __restrict__ sinp, int stride, int coloff)
{
    const int row = blockIdx.x;
    const int h = threadIdx.x >> 5, p = threadIdx.x & 31;
    const float c1 = cosp[row * 64 + p],      s1 = sinp[row * 64 + p];
    const float c2 = cosp[row * 64 + 32 + p], s2 = sinp[row * 64 + 32 + p];
    float* xr = x + (size_t)row * stride + coloff + h * 64;
    const float x1 = xr[p], x2 = xr[p + 32];
    xr[p]      = x1 * c1 - x2 * s1;
    xr[p + 32] = x2 * c2 + x1 * s2;
}

__device__ void atomicMaxFloat(float* addr, float val)
{
    int* ia = (int*)addr;
    int old = *ia;
    while (__int_as_float(old) < val) {
        int assumed = old;
        old = atomicCAS(ia, assumed, __float_as_int(val));
        if (old == assumed) break;
    }
}

__global__ void init_stab_kernel(float* stab)
{
    if (threadIdx.x < B_SZ * NKV) stab[threadIdx.x] = -3.4e38f;
}

// ---------------- favor xp -----------------------------------------------------
__global__ __launch_bounds__(256) void favor_xp(const float* __restrict__ x,
                                                const float* __restrict__ proj,
                                                float* __restrict__ xp,
                                                __nv_bfloat16* __restrict__ ph,
                                                __nv_bfloat16* __restrict__ pl,
                                                float* __restrict__ sq,
                                                float* __restrict__ stab,
                                                int nheads, int xstride, int xcoloff)
{
    __shared__ float As[32 * 68];
    __shared__ float Bs[16][256];
    __shared__ float red[256];
    __shared__ float sqsh[32];
    const float DN = 0.35355339059327373f;
    const int s0 = blockIdx.x * 32, h = blockIdx.y, b = blockIdx.z;
    const int tid = threadIdx.x;

#pragma unroll
    for (int r = 0; r < 2; r++) {
        int l = tid + r * 256;
        int tok = l >> 4, q4 = (l & 15) << 2;
        float4 vv = *(const float4*)(x + (size_t)(b * S_LEN + s0 + tok) * xstride + xcoloff + h * 64 + q4);
        As[tok * 68 + q4 + 0] = vv.x * DN;
        As[tok * 68 + q4 + 1] = vv.y * DN;
        As[tok * 68 + q4 + 2] = vv.z * DN;
        As[tok * 68 + q4 + 3] = vv.w * DN;
    }
    __syncthreads();
    if (tid < 32) {
        float ssum = 0.f;
#pragma unroll
        for (int d = 0; d < 64; d++) { float vv = As[tid * 68 + d]; ssum += vv * vv; }
        sqsh[tid] = 0.5f * ssum;
        if (sq) sq[((size_t)(b * nheads + h)) * S_LEN + s0 + tid] = 0.5f * ssum;
    }

    const int tg = tid >> 5, mg = tid & 31;
    float acc[4][8];
#pragma unroll
    for (int i = 0; i < 4; i++)
#pragma unroll
        for (int j = 0; j < 8; j++) acc[i][j] = 0.f;

    for (int k0 = 0; k0 < 64; k0 += 16) {
#pragma unroll
        for (int j = 0; j < 4; j++) {
            float4 p = *(const float4*)(proj + tid * 64 + k0 + j * 4);
            Bs[j * 4 + 0][tid] = p.x; Bs[j * 4 + 1][tid] = p.y;
            Bs[j * 4 + 2][tid] = p.z; Bs[j * 4 + 3][tid] = p.w;
        }
        __syncthreads();
#pragma unroll
        for (int kk = 0; kk < 16; kk++) {
            float a[4];
#pragma unroll
            for (int i = 0; i < 4; i++) a[i] = As[(tg * 4 + i) * 68 + k0 + kk];
            float bb[8];
            *(float4*)&bb[0] = *(const float4*)&Bs[kk][mg * 8];
            *(float4*)&bb[4] = *(const float4*)&Bs[kk][mg * 8 + 4];
#pragma unroll
            for (int i = 0; i < 4; i++)
#pragma unroll
                for (int j = 0; j < 8; j++) acc[i][j] += a[i] * bb[j];
        }
        __syncthreads();
    }

    const size_t rowbase = (size_t)(b * nheads + h) * S_LEN + s0;
    if (stab == nullptr) {
#pragma unroll
        for (int i = 0; i < 4; i++) {
            float m = acc[i][0];
#pragma unroll
            for (int j = 1; j < 8; j++) m = fmaxf(m, acc[i][j]);
#pragma unroll
            for (int o = 16; o > 0; o >>= 1) m = fmaxf(m, __shfl_xor_sync(0xffffffffu, m, o));
            const float sv = sqsh[tg * 4 + i];
#pragma unroll
            for (int j = 0; j < 8; j++)
                acc[i][j] = (__expf(acc[i][j] - sv - m) + 1e-6f) * 0.0625f;
            uint4 hv, lv;
            pack8(acc[i], hv, lv);
            *(uint4*)(ph + (rowbase + tg * 4 + i) * M_FEAT + mg * 8) = hv;
            *(uint4*)(pl + (rowbase + tg * 4 + i) * M_FEAT + mg * 8) = lv;
        }
    } else {
        float mx = -3.4e38f;
#pragma unroll
        for (int i = 0; i < 4; i++) {
            *(float4*)(xp + (rowbase + tg * 4 + i) * M_FEAT + mg * 8) =
                make_float4(acc[i][0], acc[i][1], acc[i][2], acc[i][3]);
            *(float4*)(xp + (rowbase + tg * 4 + i) * M_FEAT + mg * 8 + 4) =
                make_float4(acc[i][4], acc[i][5], acc[i][6], acc[i][7]);
#pragma unroll
            for (int j = 0; j < 8; j++) mx = fmaxf(mx, acc[i][j]);
        }
        red[tid] = mx;
        __syncthreads();
        for (int st = 128; st > 0; st >>= 1) {
            if (tid < st) red[tid] = fmaxf(red[tid], red[tid + st]);
            __syncthreads();
        }
        if (tid == 0) atomicMaxFloat(&stab[b * nheads + h], red[0]);
    }
}

// ---------------- k finalize: exp + split to bf16 hi/lo ----------------------------
__global__ void favor_fin(const float* __restrict__ xp, const float* __restrict__ sq,
                          const float* __restrict__ stab,
                          __nv_bfloat16* __restrict__ ph, __nv_bfloat16* __restrict__ pl,
                          int nrows)
{
    const int warp = (blockIdx.x * blockDim.x + threadIdx.x) >> 5;
    const int lane = threadIdx.x & 31;
    if (warp >= nrows) return;
    const float* row = xp + (size_t)warp * M_FEAT;
    const float mx  = stab[warp / S_LEN];
    const float sqv = sq[warp];
    float f[8];
    *(float4*)&f[0] = *(const float4*)(row + lane * 8);
    *(float4*)&f[4] = *(const float4*)(row + lane * 8 + 4);
#pragma unroll
    for (int k = 0; k < 8; k++) f[k] = (__expf(f[k] - sqv - mx) + 1e-6f) * 0.0625f;
    uint4 hv, lv;
    pack8(f, hv, lv);
    *(uint4*)(ph + (size_t)warp * M_FEAT + lane * 8) = hv;
    *(uint4*)(pl + (size_t)warp * M_FEAT + lane * 8) = lv;
}

// ---------------- per-chunk kv (M x D) and kz (M). grid (NC, NKV, B) ---------------
__global__ __launch_bounds__(256) void kv_chunk(const __nv_bfloat16* __restrict__ pkh,
                                                const __nv_bfloat16* __restrict__ pkl,
                                                const float* __restrict__ qkv,
                                                float* __restrict__ kv,
                                                float* __restrict__ kz)
{
    __shared__ float ps[16][256];
    __shared__ float vs[16][64];
    const int c = blockIdx.x, h = blockIdx.y, b = blockIdx.z;
    const int tid = threadIdx.x;
    float acc[64];
#pragma unroll
    for (int d = 0; d < 64; d++) acc[d] = 0.f;
    float accz = 0.f;
    const size_t prow = (size_t)(b * NKV + h) * S_LEN + c * CHUNK;
    const size_t vrow = (size_t)b * S_LEN + c * CHUNK;

    for (int i0 = 0; i0 < CHUNK; i0 += 16) {
#pragma unroll
        for (int ii = 0; ii < 16; ii++) {
            const size_t idx = (prow + i0 + ii) * M_FEAT + tid;
            ps[ii][tid] = __bfloat162float(pkh[idx]) + __bfloat162float(pkl[idx]);
        }
#pragma unroll
        for (int j = 0; j < 4; j++) {
            int l = tid + j * 256;
            int ii = l >> 6, d = l & 63;
            vs[ii][d] = qkv[(vrow + i0 + ii) * QKVW + 2560 + h * 64 + d];
        }
        __syncthreads();
#pragma unroll
        for (int ii = 0; ii < 16; ii++) {
            float a = ps[ii][tid];
            accz += a;
#pragma unroll
            for (int d4 = 0; d4 < 64; d4 += 4) {
                float4 vv = *(const float4*)&vs[ii][d4];
                acc[d4 + 0] += a * vv.x; acc[d4 + 1] += a * vv.y;
                acc[d4 + 2] += a * vv.z; acc[d4 + 3] += a * vv.w;
            }
        }
        __syncthreads();
    }
    const size_t ob = (((size_t)(b * NKV + h) * NC + c) * M_FEAT + tid) * D_HEAD;
#pragma unroll
    for (int d4 = 0; d4 < 64; d4 += 4)
        *(float4*)(kv + ob + d4) = make_float4(acc[d4], acc[d4 + 1], acc[d4 + 2], acc[d4 + 3]);
    kz[((size_t)(b * NKV + h) * NC + c) * M_FEAT + tid] = accz;
}

// ---------------- exclusive prefix over chunk axis, in place ----------------------
__global__ void cumsum_k(float* __restrict__ kv, float* __restrict__ kz)
{
    const int tid = blockIdx.x * blockDim.x + threadIdx.x;
    const int KVSZ = M_FEAT * D_HEAD;
    if (tid < B_SZ * NKV * KVSZ) {
        int bh = tid / KVSZ, md = tid % KVSZ;
        float run = 0.f;
        for (int c = 0; c < NC; c++) {
            size_t idx = ((size_t)bh * NC + c) * KVSZ + md;
            float t = kv[idx]; kv[idx] = run; run += t;
        }
    } else {
        int t2 = tid - B_SZ * NKV * KVSZ;
        if (t2 < B_SZ * NKV * M_FEAT) {
            int bh = t2 / M_FEAT, m = t2 % M_FEAT;
            float run = 0.f;
            for (int c = 0; c < NC; c++) {
                size_t idx = ((size_t)bh * NC + c) * M_FEAT + m;
                float tz = kz[idx]; kz[idx] = run; run += tz;
            }
        }
    }
}

// ============ tensor-core chunked causal linear attention. grid (NC, NH, B) ========
#define SPITCH 132
#define SMEM_ATTN (128 * SPITCH * 4 + 4 * 8192 + 512)

__global__ __launch_bounds__(256, 1) void attn_tc(
    const __nv_bfloat16* __restrict__ pqh, const __nv_bfloat16* __restrict__ pql,
    const __nv_bfloat16* __restrict__ pkh, const __nv_bfloat16* __restrict__ pkl,
    const float* __restrict__ qkv, const float* __restrict__ kvpre,
    const float* __restrict__ kzpre,
    __nv_bfloat16* __restrict__ ath, __nv_bfloat16* __restrict__ atl)
{
    extern __shared__ float sm[];
    float* Ss = sm;
    char* Ah = (char*)(sm + 128 * SPITCH);
    char* Al = Ah + 8192;
    char* Bh = Al + 8192;
    char* Bl = Bh + 8192;
    float* Zs = (float*)(Bl + 8192);

    const uint32_t sbAh = smem_u32g(Ah), sbAl = smem_u32g(Al);
    const uint32_t sbBh = smem_u32g(Bh), sbBl = smem_u32g(Bl);

    const int c = blockIdx.x, h = blockIdx.y, b = blockIdx.z;
    const int kvh = h >> 2;
    const int tid = threadIdx.x;
    const int warp = tid >> 5, lane = tid & 31;
    const int gid = lane >> 2, tig = lane & 3;

    const size_t qbase  = (size_t)(b * NH + h) * S_LEN + c * CHUNK;
    const size_t kbase  = (size_t)(b * NKV + kvh) * S_LEN + c * CHUNK;
    const size_t vrow0  = (size_t)b * S_LEN + c * CHUNK;
    const size_t kvbase = ((size_t)(b * NKV + kvh) * NC + c) * (size_t)(M_FEAT * D_HEAD);
    const size_t kzbase = ((size_t)(b * NKV + kvh) * NC + c) * M_FEAT;

    const int strow = tid & 127;
    const int s0 = tid >> 7;

    const int swm   = ((lane & 7) >> 1) & 3;
    const int rlocA = (lane & 7) + (((lane >> 3) & 1) << 3);
    const int shA   = lane >> 4;
    const int rlocB = (lane & 7) + ((lane >> 4) << 3);
    const int shB   = (lane >> 3) & 1;

    // ======================= Phase 1: scores =======================
    {
        const int wm = (warp & 1) * 64, wn = (warp >> 1) * 32;
        float acc[4][4][4];
#pragma unroll
        for (int i = 0; i < 4; i++)
#pragma unroll
            for (int j = 0; j < 4; j++)
#pragma unroll
                for (int r = 0; r < 4; r++) acc[i][j][r] = 0.f;

        for (int m0 = 0; m0 < M_FEAT; m0 += 32) {
#pragma unroll
            for (int si = 0; si < 2; si++) {
                const int s = s0 + si * 2;
                const uint32_t off = (uint32_t)(strow * 64 + ((s ^ ((strow >> 1) & 3)) * 16));
                const size_t ia = (qbase + strow) * M_FEAT + m0 + s * 8;
                *(uint4*)(Ah + off) = *(const uint4*)(pqh + ia);
                *(uint4*)(Al + off) = *(const uint4*)(pql + ia);
                const size_t ib = (kbase + strow) * M_FEAT + m0 + s * 8;
                *(uint4*)(Bh + off) = *(const uint4*)(pkh + ib);
                *(uint4*)(Bl + off) = *(const uint4*)(pkl + ib);
            }
            __syncthreads();
#pragma unroll
            for (int kb = 0; kb < 2; kb++) {
                uint32_t ah[4][4], al[4][4];
#pragma unroll
                for (int tm = 0; tm < 4; tm++) {
                    const int r = wm + tm * 16 + rlocA;
                    const uint32_t off = (uint32_t)(r * 64 + (((2 * kb + shA) ^ swm) * 16));
                    LDSM4(ah[tm], sbAh + off);
                    LDSM4(al[tm], sbAl + off);
                }
                uint32_t bhf[2][4], blf[2][4];
#pragma unroll
                for (int p = 0; p < 2; p++) {
                    const int r = wn + p * 16 + rlocB;
                    const uint32_t off = (uint32_t)(r * 64 + (((2 * kb + shB) ^ swm) * 16));
                    LDSM4(bhf[p], sbBh + off);
                    LDSM4(blf[p], sbBl + off);
                }
#pragma unroll
                for (int tm = 0; tm < 4; tm++)
#pragma unroll
                    for (int tn = 0; tn < 4; tn++) {
                        const uint32_t* bh2 = &bhf[tn >> 1][(tn & 1) * 2];
                        const uint32_t* bl2 = &blf[tn >> 1][(tn & 1) * 2];
                        mma_bf16(acc[tm][tn], ah[tm], bh2);
                        mma_bf16(acc[tm][tn], ah[tm], bl2);
                        mma_bf16(acc[tm][tn], al[tm], bh2);
                    }
            }
            __syncthreads();
        }
#pragma unroll
        for (int tm = 0; tm < 4; tm++) {
            const int r0 = wm + tm * 16 + gid;
            const int r1 = r0 + 8;
#pragma unroll
            for (int tn = 0; tn < 4; tn++) {
                const int col = wn + tn * 8 + tig * 2;
                Ss[r0 * SPITCH + col]     = (col     <= r0) ? acc[tm][tn][0] : 0.f;
                Ss[r0 * SPITCH + col + 1] = (col + 1 <= r0) ? acc[tm][tn][1] : 0.f;
                Ss[r1 * SPITCH + col]     = (col     <= r1) ? acc[tm][tn][2] : 0.f;
                Ss[r1 * SPITCH + col + 1] = (col + 1 <= r1) ? acc[tm][tn][3] : 0.f;
            }
        }
    }
    __syncthreads();

    // ======================= Phase 2: inter+intra (+z col 64) =======================
    const int wm2 = (warp & 3) * 32, wn2 = (warp >> 2) * 40;
    float acc2[2][5][4];
#pragma unroll
    for (int i = 0; i < 2; i++)
#pragma unroll
        for (int j = 0; j < 5; j++)
#pragma unroll
            for (int r = 0; r < 4; r++) acc2[i][j][r] = 0.f;

    for (int cc = 0; cc < 12; cc++) {
#pragma unroll
        for (int si = 0; si < 2; si++) {
            const int s = s0 + si * 2;
            const uint32_t off = (uint32_t)(strow * 64 + ((s ^ ((strow >> 1) & 3)) * 16));
            if (cc < 8) {
                const size_t ia = (qbase + strow) * M_FEAT + cc * 32 + s * 8;
                *(uint4*)(Ah + off) = *(const uint4*)(pqh + ia);
                *(uint4*)(Al + off) = *(const uint4*)(pql + ia);
            } else {
                float f[8];
                const float* pa = Ss + strow * SPITCH + (cc - 8) * 32 + s * 8;
                *(float4*)&f[0] = *(const float4*)pa;
                *(float4*)&f[4] = *(const float4*)(pa + 4);
                uint4 hv, lv;
                pack8(f, hv, lv);
                *(uint4*)(Ah + off) = hv;
                *(uint4*)(Al + off) = lv;
            }

            if (strow < 96) {
                float g[8];
                if (strow < 64) {
                    if (cc < 8) {
#pragma unroll
                        for (int e = 0; e < 8; e++)
                            g[e] = kvpre[kvbase + (size_t)(cc * 32 + s * 8 + e) * 64 + strow];
                    } else {
#pragma unroll
                        for (int e = 0; e < 8; e++)
                            g[e] = qkv[(vrow0 + (cc - 8) * 32 + s * 8 + e) * QKVW + 2560 + kvh * 64 + strow];
                    }
                } else if (strow == 64) {
                    if (cc < 8) {
#pragma unroll
                        for (int e = 0; e < 8; e++)
                            g[e] = kzpre[kzbase + cc * 32 + s * 8 + e];
                    } else {
#pragma unroll
                        for (int e = 0; e < 8; e++) g[e] = 1.f;
                    }
                } else {
#pragma unroll
                    for (int e = 0; e < 8; e++) g[e] = 0.f;
                }
                uint4 hv, lv;
                pack8(g, hv, lv);
                *(uint4*)(Bh + off) = hv;
                *(uint4*)(Bl + off) = lv;
            }
        }
        __syncthreads();
#pragma unroll
        for (int kb = 0; kb < 2; kb++) {
            uint32_t ah2[2][4], al2[2][4], bh2[3][4], bl2[3][4];
#pragma unroll
            for (int tm = 0; tm < 2; tm++) {
                const int r = wm2 + tm * 16 + rlocA;
                const uint32_t off = (uint32_t)(r * 64 + (((2 * kb + shA) ^ swm) * 16));
                LDSM4(ah2[tm], sbAh + off);
                LDSM4(al2[tm], sbAl + off);
            }
#pragma unroll
            for (int p = 0; p < 3; p++) {
                const int r = wn2 + p * 16 + rlocB;
                const uint32_t off = (uint32_t)(r * 64 + (((2 * kb + shB) ^ swm) * 16));
                LDSM4(bh2[p], sbBh + off);
                LDSM4(bl2[p], sbBl + off);
            }
#pragma unroll
            for (int tm = 0; tm < 2; tm++)
#pragma unroll
                for (int tn = 0; tn < 5; tn++) {
                    const uint32_t* bh_ = &bh2[tn >> 1][(tn & 1) * 2];
                    const uint32_t* bl_ = &bl2[tn >> 1][(tn & 1) * 2];
                    mma_bf16(acc2[tm][tn], ah2[tm], bh_);
                    mma_bf16(acc2[tm][tn], ah2[tm], bl_);
                    mma_bf16(acc2[tm][tn], al2[tm], bh_);
                }
        }
        __syncthreads();
    }

    if ((warp >> 2) == 1 && tig == 0) {
#pragma unroll
        for (int tm = 0; tm < 2; tm++) {
            const int r = wm2 + tm * 16 + gid;
            Zs[r]     = acc2[tm][3][0];
            Zs[r + 8] = acc2[tm][3][2];
        }
    }
    __syncthreads();

#pragma unroll
    for (int tm = 0; tm < 2; tm++) {
        const int r = wm2 + tm * 16 + gid;
        const float d0 = 1.f / (Zs[r] + 1e-6f);
        const float d1 = 1.f / (Zs[r + 8] + 1e-6f);
#pragma unroll
        for (int tn = 0; tn < 5; tn++) {
            const int col = wn2 + tn * 8 + tig * 2;
            if (col < 64) {
                const size_t ro = ((size_t)b * S_LEN + c * CHUNK + r) * (NH * D_HEAD) + h * 64 + col;
                const size_t ro8 = ro + 8 * (NH * D_HEAD);
                float o0 = acc2[tm][tn][0] * d0, o1 = acc2[tm][tn][1] * d0;
                float o2 = acc2[tm][tn][2] * d1, o3 = acc2[tm][tn][3] * d1;
                __nv_bfloat16 h0 = __float2bfloat16(o0), h1 = __float2bfloat16(o1);
                __nv_bfloat16 h2 = __float2bfloat16(o2), h3 = __float2bfloat16(o3);
                *(__nv_bfloat162*)(ath + ro)  = __nv_bfloat162(h0, h1);
                *(__nv_bfloat162*)(ath + ro8) = __nv_bfloat162(h2, h3);
                *(__nv_bfloat162*)(atl + ro)  =
                    __nv_bfloat162(__float2bfloat16(o0 - __bfloat162float(h0)),
                                   __float2bfloat16(o1 - __bfloat162float(h1)));
                *(__nv_bfloat162*)(atl + ro8) =
                    __nv_bfloat162(__float2bfloat16(o2 - __bfloat162float(h2)),
                                   __float2bfloat16(o3 - __bfloat162float(h3)));
            }
        }
    }
}

// ----------------------------------- launch ---------------------------------------
extern "C" void kernel_launch(void* const* d_in, const int* in_sizes, int n_in,
                              void* d_out, int out_size)
{
    const float* hs   = (const float*)d_in[0];
    const float* cosp = (const float*)d_in[1];
    const float* sinp = (const float*)d_in[2];
    const float* Wq   = (const float*)d_in[3];
    const float* Wk   = (const float*)d_in[4];
    const float* Wv   = (const float*)d_in[5];
    const float* Wo   = (const float*)d_in[6];
    const float* proj = (const float*)d_in[7];
    float* out = (float*)d_out;

    float *qkvp, *xpkp, *sqkp, *stabp, *kvp, *kzp;
    cudaGetSymbolAddress((void**)&qkvp,  g_qkv);
    cudaGetSymbolAddress((void**)&xpkp,  g_xpk);
    cudaGetSymbolAddress((void**)&sqkp,  g_sqk);
    cudaGetSymbolAddress((void**)&stabp, g_stab);
    cudaGetSymbolAddress((void**)&kvp,   g_kv);
    cudaGetSymbolAddress((void**)&kzp,   g_kz);

    __nv_bfloat16 *pqh, *pql, *pkh, *pkl, *hsh, *hsl, *ath, *atl, *wh, *wl;
    cudaGetSymbolAddress((void**)&pqh, g_pqh);
    cudaGetSymbolAddress((void**)&pql, g_pql);
    cudaGetSymbolAddress((void**)&pkh, g_pkh);
    cudaGetSymbolAddress((void**)&pkl, g_pkl);
    cudaGetSymbolAddress((void**)&hsh, g_hsh);
    cudaGetSymbolAddress((void**)&hsl, g_hsl);
    cudaGetSymbolAddress((void**)&ath, g_ath);
    cudaGetSymbolAddress((void**)&atl, g_atl);
    cudaGetSymbolAddress((void**)&wh,  g_wh);
    cudaGetSymbolAddress((void**)&wl,  g_wl);

    cudaFuncSetAttribute(gemm_bf16x3, cudaFuncAttributeMaxDynamicSharedMemorySize, SMEM_GEMM);
    cudaFuncSetAttribute(attn_tc, cudaFuncAttributeMaxDynamicSharedMemorySize, SMEM_ATTN);

    // ---- splits ----
    split_bf16<<<(HS_ELEMS / 4 + 255) / 256, 256>>>(hs, hsh, hsl, HS_ELEMS / 4);
    split_bf16<<<(HID_ * HID_ / 4 + 255) / 256, 256>>>(Wq, wh + WQ_OFF, wl + WQ_OFF, HID_ * HID_ / 4);
    split_bf16<<<(512 * HID_ / 4 + 255) / 256, 256>>>(Wk, wh + WK_OFF, wl + WK_OFF, 512 * HID_ / 4);
    split_bf16<<<(512 * HID_ / 4 + 255) / 256, 256>>>(Wv, wh + WV_OFF, wl + WV_OFF, 512 * HID_ / 4);
    split_bf16<<<(HID_ * HID_ / 4 + 255) / 256, 256>>>(Wo, wh + WO_OFF, wl + WO_OFF, HID_ * HID_ / 4);

    // ---- fused QKV projection (256x256 tiles) ----
    gemm_bf16x3<<<dim3(QKVW / 256, 4096 / 256), 512, SMEM_GEMM>>>(hsh, hsl, wh, wl, qkvp, QKVW);

    // ---- RoPE ----
    rope_kernel<<<B_SZ * S_LEN, NH * 32>>>(qkvp, cosp, sinp, QKVW, 0);
    rope_kernel<<<B_SZ * S_LEN, NKV * 32>>>(qkvp, cosp, sinp, QKVW, 2048);

    // ---- favor features ----
    init_stab_kernel<<<1, 32>>>(stabp);
    favor_xp<<<dim3(S_LEN / 32, NH, B_SZ), 256>>>(qkvp, proj, nullptr, pqh, pql, nullptr, nullptr, NH, QKVW, 0);
    favor_xp<<<dim3(S_LEN / 32, NKV, B_SZ), 256>>>(qkvp, proj, xpkp, nullptr, nullptr, sqkp, stabp, NKV, QKVW, 2048);
    favor_fin<<<(B_SZ * NKV * S_LEN) / 8, 256>>>(xpkp, sqkp, stabp, pkh, pkl, B_SZ * NKV * S_LEN);

    // ---- chunked linear attention ----
    kv_chunk<<<dim3(NC, NKV, B_SZ), 256>>>(pkh, pkl, qkvp, kvp, kzp);
    cumsum_k<<<(B_SZ * NKV * (M_FEAT * D_HEAD + M_FEAT) + 255) / 256, 256>>>(kvp, kzp);
    attn_tc<<<dim3(NC, NH, B_SZ), 256, SMEM_ATTN>>>(pqh, pql, pkh, pkl, qkvp, kvp, kzp, ath, atl);

    // ---- output projection (256x256 tiles) ----
    gemm_bf16x3<<<dim3(2048 / 256, 4096 / 256), 512, SMEM_GEMM>>>(ath, atl, wh + WO_OFF, wl + WO_OFF, out, 2048);
}

// round 10
// speedup vs baseline: 1.5947x; 1.5947x over previous
#include <cuda_runtime.h>
#include <cuda_bf16.h>
#include <math.h>
#include <stdint.h>

#define B_SZ   2
#define S_LEN  2048
#define HID_   2048
#define NH     32
#define NKV    8
#define D_HEAD 64
#define M_FEAT 256
#define NC     16
#define CHUNK  128
#define QKVW   3072

// ---------------- scratch (device globals; no allocations allowed) ----------------
__device__ float g_qkv [(size_t)B_SZ * S_LEN * QKVW];
__device__ float g_xpk [(size_t)B_SZ * NKV * S_LEN * M_FEAT];
__device__ float g_sqk [B_SZ * NKV * S_LEN];
__device__ float g_stab[B_SZ * NKV];
__device__ float g_kv  [B_SZ * NKV * NC * M_FEAT * D_HEAD];
__device__ float g_kz  [B_SZ * NKV * NC * M_FEAT];

#define PHIQ_E ((size_t)B_SZ * NH  * S_LEN * M_FEAT)
#define PHIK_E ((size_t)B_SZ * NKV * S_LEN * M_FEAT)
#define HS_ELEMS  (B_SZ * S_LEN * HID_)
#define W_ELEMS   (QKVW * HID_ + HID_ * HID_)
__device__ __align__(16) __nv_bfloat16 g_pqh[PHIQ_E];
__device__ __align__(16) __nv_bfloat16 g_pql[PHIQ_E];
__device__ __align__(16) __nv_bfloat16 g_pkh[PHIK_E];
__device__ __align__(16) __nv_bfloat16 g_pkl[PHIK_E];
__device__ __align__(16) __nv_bfloat16 g_hsh[HS_ELEMS];
__device__ __align__(16) __nv_bfloat16 g_hsl[HS_ELEMS];
__device__ __align__(16) __nv_bfloat16 g_ath[HS_ELEMS];
__device__ __align__(16) __nv_bfloat16 g_atl[HS_ELEMS];
__device__ __align__(16) __nv_bfloat16 g_wh [W_ELEMS];
__device__ __align__(16) __nv_bfloat16 g_wl [W_ELEMS];

#define WQ_OFF 0
#define WK_OFF (HID_ * HID_)
#define WV_OFF (WK_OFF + 512 * HID_)
#define WO_OFF (WV_OFF + 512 * HID_)

// =================== fp32 -> bf16 hi/lo split (elementwise, x4 vec) ================
__global__ void split_bf16(const float* __restrict__ x, __nv_bfloat16* __restrict__ h,
                           __nv_bfloat16* __restrict__ l, int n4)
{
    int i = blockIdx.x * blockDim.x + threadIdx.x;
    if (i >= n4) return;
    float4 v = ((const float4*)x)[i];
    __nv_bfloat16 h0 = __float2bfloat16(v.x), h1 = __float2bfloat16(v.y);
    __nv_bfloat16 h2 = __float2bfloat16(v.z), h3 = __float2bfloat16(v.w);
    __nv_bfloat162* hp = (__nv_bfloat162*)h;
    hp[2 * i]     = __nv_bfloat162(h0, h1);
    hp[2 * i + 1] = __nv_bfloat162(h2, h3);
    __nv_bfloat162* lp = (__nv_bfloat162*)l;
    lp[2 * i]     = __nv_bfloat162(__float2bfloat16(v.x - __bfloat162float(h0)),
                                   __float2bfloat16(v.y - __bfloat162float(h1)));
    lp[2 * i + 1] = __nv_bfloat162(__float2bfloat16(v.z - __bfloat162float(h2)),
                                   __float2bfloat16(v.w - __bfloat162float(h3)));
}

// ===================== shared helpers for tensor-core kernels ======================
__device__ __forceinline__ uint32_t smem_u32g(const void* p)
{
    uint32_t a;
    asm("{ .reg .u64 t; cvta.to.shared.u64 t, %1; cvt.u32.u64 %0, t; }" : "=r"(a) : "l"(p));
    return a;
}

#define LDSM4(r, a) \
    asm volatile("ldmatrix.sync.aligned.m8n8.x4.shared.b16 {%0,%1,%2,%3}, [%4];" \
                 : "=r"((r)[0]), "=r"((r)[1]), "=r"((r)[2]), "=r"((r)[3]) : "r"(a))

__device__ __forceinline__ void mma_bf16(float c[4], const uint32_t a[4], const uint32_t b[2])
{
    asm volatile("mma.sync.aligned.m16n8k16.row.col.f32.bf16.bf16.f32 "
                 "{%0,%1,%2,%3}, {%4,%5,%6,%7}, {%8,%9}, {%0,%1,%2,%3};"
                 : "+f"(c[0]), "+f"(c[1]), "+f"(c[2]), "+f"(c[3])
                 : "r"(a[0]), "r"(a[1]), "r"(a[2]), "r"(a[3]), "r"(b[0]), "r"(b[1]));
}

__device__ __forceinline__ void pack8(const float* f, uint4& hv, uint4& lv)
{
    uint32_t hw[4], lw[4];
#pragma unroll
    for (int e = 0; e < 4; e++) {
        __nv_bfloat16 h0 = __float2bfloat16(f[2 * e]);
        __nv_bfloat16 h1 = __float2bfloat16(f[2 * e + 1]);
        __nv_bfloat162 hp(h0, h1);
        hw[e] = *(uint32_t*)&hp;
        __nv_bfloat162 lp(__float2bfloat16(f[2 * e]     - __bfloat162float(h0)),
                          __float2bfloat16(f[2 * e + 1] - __bfloat162float(h1)));
        lw[e] = *(uint32_t*)&lp;
    }
    hv = make_uint4(hw[0], hw[1], hw[2], hw[3]);
    lv = make_uint4(lw[0], lw[1], lw[2], lw[3]);
}

// ======== bf16 3-pass split GEMM: 128x128 tile, ldmatrix + swizzled smem ===========
#define GK 2048
#define BK 32
#define NKT (GK / BK)
#define GBUF 32768
#define SMEM_GEMM (2 * GBUF)

__global__ __launch_bounds__(256, 1) void gemm_bf16x3(const __nv_bfloat16* __restrict__ Ah,
                                                      const __nv_bfloat16* __restrict__ Al,
                                                      const __nv_bfloat16* __restrict__ Bh,
                                                      const __nv_bfloat16* __restrict__ Bl,
                                                      float* __restrict__ C, int N)
{
    extern __shared__ char smc[];
    const uint32_t sb = smem_u32g(smc);
    const int tid  = threadIdx.x;
    const int warp = tid >> 5, lane = tid & 31;
    const int gid  = lane >> 2, tig = lane & 3;
    const int wm   = (warp & 1) * 64;
    const int wn   = (warp >> 1) * 32;
    const int rowA = blockIdx.y * 128;
    const int rowB = blockIdx.x * 128;

    const int st_row  = tid >> 2;
    const int st_slot = tid & 3;
    const uint32_t st_off0 = (uint32_t)(st_row * 64 + ((st_slot ^ ((st_row >> 1) & 3)) * 16));
    const int st_row1 = st_row + 64;
    const uint32_t st_off1 = (uint32_t)(st_row1 * 64 + ((st_slot ^ ((st_row1 >> 1) & 3)) * 16));

    const int swm   = ((lane & 7) >> 1) & 3;
    const int rlocA = (lane & 7) + (((lane >> 3) & 1) << 3);
    const int shA   = lane >> 4;
    const int rlocB = (lane & 7) + ((lane >> 4) << 3);
    const int shB   = (lane >> 3) & 1;

    float acc[4][4][4];
#pragma unroll
    for (int i = 0; i < 4; i++)
#pragma unroll
        for (int j = 0; j < 4; j++)
#pragma unroll
            for (int r = 0; r < 4; r++) acc[i][j][r] = 0.f;

    uint4 pAh[2], pAl[2], pBh[2], pBl[2];

    auto prefetch = [&](int kt) {
        const int kb = kt * BK;
        pAh[0] = *(const uint4*)(Ah + (size_t)(rowA + st_row)  * GK + kb + st_slot * 8);
        pAh[1] = *(const uint4*)(Ah + (size_t)(rowA + st_row1) * GK + kb + st_slot * 8);
        pAl[0] = *(const uint4*)(Al + (size_t)(rowA + st_row)  * GK + kb + st_slot * 8);
        pAl[1] = *(const uint4*)(Al + (size_t)(rowA + st_row1) * GK + kb + st_slot * 8);
        pBh[0] = *(const uint4*)(Bh + (size_t)(rowB + st_row)  * GK + kb + st_slot * 8);
        pBh[1] = *(const uint4*)(Bh + (size_t)(rowB + st_row1) * GK + kb + st_slot * 8);
        pBl[0] = *(const uint4*)(Bl + (size_t)(rowB + st_row)  * GK + kb + st_slot * 8);
        pBl[1] = *(const uint4*)(Bl + (size_t)(rowB + st_row1) * GK + kb + st_slot * 8);
    };
    auto commit = [&](int b) {
        char* buf = smc + b * GBUF;
        *(uint4*)(buf + st_off0)         = pAh[0];
        *(uint4*)(buf + st_off1)         = pAh[1];
        *(uint4*)(buf + 8192  + st_off0) = pAl[0];
        *(uint4*)(buf + 8192  + st_off1) = pAl[1];
        *(uint4*)(buf + 16384 + st_off0) = pBh[0];
        *(uint4*)(buf + 16384 + st_off1) = pBh[1];
        *(uint4*)(buf + 24576 + st_off0) = pBl[0];
        *(uint4*)(buf + 24576 + st_off1) = pBl[1];
    };

    prefetch(0);
    commit(0);
    __syncthreads();

    for (int kt = 0; kt < NKT; kt++) {
        const uint32_t base = sb + (kt & 1) * GBUF;
        if (kt + 1 < NKT) prefetch(kt + 1);

#pragma unroll
        for (int kb = 0; kb < 2; kb++) {
            uint32_t ah[4][4], al[4][4];
#pragma unroll
            for (int tm = 0; tm < 4; tm++) {
                const int r = wm + tm * 16 + rlocA;
                const uint32_t off = (uint32_t)(r * 64 + (((2 * kb + shA) ^ swm) * 16));
                LDSM4(ah[tm], base + off);
                LDSM4(al[tm], base + 8192 + off);
            }
            uint32_t bhf[2][4], blf[2][4];
#pragma unroll
            for (int p = 0; p < 2; p++) {
                const int r = wn + p * 16 + rlocB;
                const uint32_t off = (uint32_t)(r * 64 + (((2 * kb + shB) ^ swm) * 16));
                LDSM4(bhf[p], base + 16384 + off);
                LDSM4(blf[p], base + 24576 + off);
            }
#pragma unroll
            for (int tm = 0; tm < 4; tm++)
#pragma unroll
                for (int tn = 0; tn < 4; tn++) {
                    const uint32_t* bh2 = &bhf[tn >> 1][(tn & 1) * 2];
                    const uint32_t* bl2 = &blf[tn >> 1][(tn & 1) * 2];
                    mma_bf16(acc[tm][tn], ah[tm], bh2);
                    mma_bf16(acc[tm][tn], ah[tm], bl2);
                    mma_bf16(acc[tm][tn], al[tm], bh2);
                }
        }
        if (kt + 1 < NKT) commit((kt + 1) & 1);
        __syncthreads();
    }

#pragma unroll
    for (int tm = 0; tm < 4; tm++) {
        const size_t r0 = (size_t)rowA + wm + tm * 16 + gid;
#pragma unroll
        for (int tn = 0; tn < 4; tn++) {
            const int cn = rowB + wn + tn * 8 + tig * 2;
            *(float2*)(C + r0 * N + cn)       = make_float2(acc[tm][tn][0], acc[tm][tn][1]);
            *(float2*)(C + (r0 + 8) * N + cn) = make_float2(acc[tm][tn][2], acc[tm][tn][3]);
        }
    }
}

// ---------------- RoPE, in place on combined buffer --------------------------------
__global__ void rope_kernel(float* __restrict__ x, const float* __restrict__ cosp,
                            const float* __restrict__ sinp, int stride, int coloff)
{
    const int row = blockIdx.x;
    const int h = threadIdx.x >> 5, p = threadIdx.x & 31;
    const float c1 = cosp[row * 64 + p],      s1 = sinp[row * 64 + p];
    const float c2 = cosp[row * 64 + 32 + p], s2 = sinp[row * 64 + 32 + p];
    float* xr = x + (size_t)row * stride + coloff + h * 64;
    const float x1 = xr[p], x2 = xr[p + 32];
    xr[p]      = x1 * c1 - x2 * s1;
    xr[p + 32] = x2 * c2 + x1 * s2;
}

__device__ void atomicMaxFloat(float* addr, float val)
{
    int* ia = (int*)addr;
    int old = *ia;
    while (__int_as_float(old) < val) {
        int assumed = old;
        old = atomicCAS(ia, assumed, __float_as_int(val));
        if (old == assumed) break;
    }
}

__global__ void init_stab_kernel(float* stab)
{
    if (threadIdx.x < B_SZ * NKV) stab[threadIdx.x] = -3.4e38f;
}

// ---------------- favor xp -----------------------------------------------------
__global__ __launch_bounds__(256) void favor_xp(const float* __restrict__ x,
                                                const float* __restrict__ proj,
                                                float* __restrict__ xp,
                                                __nv_bfloat16* __restrict__ ph,
                                                __nv_bfloat16* __restrict__ pl,
                                                float* __restrict__ sq,
                                                float* __restrict__ stab,
                                                int nheads, int xstride, int xcoloff)
{
    __shared__ float As[32 * 68];
    __shared__ float Bs[16][256];
    __shared__ float red[256];
    __shared__ float sqsh[32];
    const float DN = 0.35355339059327373f;
    const int s0 = blockIdx.x * 32, h = blockIdx.y, b = blockIdx.z;
    const int tid = threadIdx.x;

#pragma unroll
    for (int r = 0; r < 2; r++) {
        int l = tid + r * 256;
        int tok = l >> 4, q4 = (l & 15) << 2;
        float4 vv = *(const float4*)(x + (size_t)(b * S_LEN + s0 + tok) * xstride + xcoloff + h * 64 + q4);
        As[tok * 68 + q4 + 0] = vv.x * DN;
        As[tok * 68 + q4 + 1] = vv.y * DN;
        As[tok * 68 + q4 + 2] = vv.z * DN;
        As[tok * 68 + q4 + 3] = vv.w * DN;
    }
    __syncthreads();
    if (tid < 32) {
        float ssum = 0.f;
#pragma unroll
        for (int d = 0; d < 64; d++) { float vv = As[tid * 68 + d]; ssum += vv * vv; }
        sqsh[tid] = 0.5f * ssum;
        if (sq) sq[((size_t)(b * nheads + h)) * S_LEN + s0 + tid] = 0.5f * ssum;
    }

    const int tg = tid >> 5, mg = tid & 31;
    float acc[4][8];
#pragma unroll
    for (int i = 0; i < 4; i++)
#pragma unroll
        for (int j = 0; j < 8; j++) acc[i][j] = 0.f;

    for (int k0 = 0; k0 < 64; k0 += 16) {
#pragma unroll
        for (int j = 0; j < 4; j++) {
            float4 p = *(const float4*)(proj + tid * 64 + k0 + j * 4);
            Bs[j * 4 + 0][tid] = p.x; Bs[j * 4 + 1][tid] = p.y;
            Bs[j * 4 + 2][tid] = p.z; Bs[j * 4 + 3][tid] = p.w;
        }
        __syncthreads();
#pragma unroll
        for (int kk = 0; kk < 16; kk++) {
            float a[4];
#pragma unroll
            for (int i = 0; i < 4; i++) a[i] = As[(tg * 4 + i) * 68 + k0 + kk];
            float bb[8];
            *(float4*)&bb[0] = *(const float4*)&Bs[kk][mg * 8];
            *(float4*)&bb[4] = *(const float4*)&Bs[kk][mg * 8 + 4];
#pragma unroll
            for (int i = 0; i < 4; i++)
#pragma unroll
                for (int j = 0; j < 8; j++) acc[i][j] += a[i] * bb[j];
        }
        __syncthreads();
    }

    const size_t rowbase = (size_t)(b * nheads + h) * S_LEN + s0;
    if (stab == nullptr) {
#pragma unroll
        for (int i = 0; i < 4; i++) {
            float m = acc[i][0];
#pragma unroll
            for (int j = 1; j < 8; j++) m = fmaxf(m, acc[i][j]);
#pragma unroll
            for (int o = 16; o > 0; o >>= 1) m = fmaxf(m, __shfl_xor_sync(0xffffffffu, m, o));
            const float sv = sqsh[tg * 4 + i];
#pragma unroll
            for (int j = 0; j < 8; j++)
                acc[i][j] = (__expf(acc[i][j] - sv - m) + 1e-6f) * 0.0625f;
            uint4 hv, lv;
            pack8(acc[i], hv, lv);
            *(uint4*)(ph + (rowbase + tg * 4 + i) * M_FEAT + mg * 8) = hv;
            *(uint4*)(pl + (rowbase + tg * 4 + i) * M_FEAT + mg * 8) = lv;
        }
    } else {
        float mx = -3.4e38f;
#pragma unroll
        for (int i = 0; i < 4; i++) {
            *(float4*)(xp + (rowbase + tg * 4 + i) * M_FEAT + mg * 8) =
                make_float4(acc[i][0], acc[i][1], acc[i][2], acc[i][3]);
            *(float4*)(xp + (rowbase + tg * 4 + i) * M_FEAT + mg * 8 + 4) =
                make_float4(acc[i][4], acc[i][5], acc[i][6], acc[i][7]);
#pragma unroll
            for (int j = 0; j < 8; j++) mx = fmaxf(mx, acc[i][j]);
        }
        red[tid] = mx;
        __syncthreads();
        for (int st = 128; st > 0; st >>= 1) {
            if (tid < st) red[tid] = fmaxf(red[tid], red[tid + st]);
            __syncthreads();
        }
        if (tid == 0) atomicMaxFloat(&stab[b * nheads + h], red[0]);
    }
}

// ---------------- k finalize: exp + split to bf16 hi/lo ----------------------------
__global__ void favor_fin(const float* __restrict__ xp, const float* __restrict__ sq,
                          const float* __restrict__ stab,
                          __nv_bfloat16* __restrict__ ph, __nv_bfloat16* __restrict__ pl,
                          int nrows)
{
    const int warp = (blockIdx.x * blockDim.x + threadIdx.x) >> 5;
    const int lane = threadIdx.x & 31;
    if (warp >= nrows) return;
    const float* row = xp + (size_t)warp * M_FEAT;
    const float mx  = stab[warp / S_LEN];
    const float sqv = sq[warp];
    float f[8];
    *(float4*)&f[0] = *(const float4*)(row + lane * 8);
    *(float4*)&f[4] = *(const float4*)(row + lane * 8 + 4);
#pragma unroll
    for (int k = 0; k < 8; k++) f[k] = (__expf(f[k] - sqv - mx) + 1e-6f) * 0.0625f;
    uint4 hv, lv;
    pack8(f, hv, lv);
    *(uint4*)(ph + (size_t)warp * M_FEAT + lane * 8) = hv;
    *(uint4*)(pl + (size_t)warp * M_FEAT + lane * 8) = lv;
}

// ---------------- per-chunk kv (M x D) and kz (M). grid (NC, NKV, B) ---------------
__global__ __launch_bounds__(256) void kv_chunk(const __nv_bfloat16* __restrict__ pkh,
                                                const __nv_bfloat16* __restrict__ pkl,
                                                const float* __restrict__ qkv,
                                                float* __restrict__ kv,
                                                float* __restrict__ kz)
{
    __shared__ float ps[16][256];
    __shared__ float vs[16][64];
    const int c = blockIdx.x, h = blockIdx.y, b = blockIdx.z;
    const int tid = threadIdx.x;
    float acc[64];
#pragma unroll
    for (int d = 0; d < 64; d++) acc[d] = 0.f;
    float accz = 0.f;
    const size_t prow = (size_t)(b * NKV + h) * S_LEN + c * CHUNK;
    const size_t vrow = (size_t)b * S_LEN + c * CHUNK;

    for (int i0 = 0; i0 < CHUNK; i0 += 16) {
#pragma unroll
        for (int ii = 0; ii < 16; ii++) {
            const size_t idx = (prow + i0 + ii) * M_FEAT + tid;
            ps[ii][tid] = __bfloat162float(pkh[idx]) + __bfloat162float(pkl[idx]);
        }
#pragma unroll
        for (int j = 0; j < 4; j++) {
            int l = tid + j * 256;
            int ii = l >> 6, d = l & 63;
            vs[ii][d] = qkv[(vrow + i0 + ii) * QKVW + 2560 + h * 64 + d];
        }
        __syncthreads();
#pragma unroll
        for (int ii = 0; ii < 16; ii++) {
            float a = ps[ii][tid];
            accz += a;
#pragma unroll
            for (int d4 = 0; d4 < 64; d4 += 4) {
                float4 vv = *(const float4*)&vs[ii][d4];
                acc[d4 + 0] += a * vv.x; acc[d4 + 1] += a * vv.y;
                acc[d4 + 2] += a * vv.z; acc[d4 + 3] += a * vv.w;
            }
        }
        __syncthreads();
    }
    const size_t ob = (((size_t)(b * NKV + h) * NC + c) * M_FEAT + tid) * D_HEAD;
#pragma unroll
    for (int d4 = 0; d4 < 64; d4 += 4)
        *(float4*)(kv + ob + d4) = make_float4(acc[d4], acc[d4 + 1], acc[d4 + 2], acc[d4 + 3]);
    kz[((size_t)(b * NKV + h) * NC + c) * M_FEAT + tid] = accz;
}

// ---------------- exclusive prefix over chunk axis, in place ----------------------
__global__ void cumsum_k(float* __restrict__ kv, float* __restrict__ kz)
{
    const int tid = blockIdx.x * blockDim.x + threadIdx.x;
    const int KVSZ = M_FEAT * D_HEAD;
    if (tid < B_SZ * NKV * KVSZ) {
        int bh = tid / KVSZ, md = tid % KVSZ;
        float run = 0.f;
        for (int c = 0; c < NC; c++) {
            size_t idx = ((size_t)bh * NC + c) * KVSZ + md;
            float t = kv[idx]; kv[idx] = run; run += t;
        }
    } else {
        int t2 = tid - B_SZ * NKV * KVSZ;
        if (t2 < B_SZ * NKV * M_FEAT) {
            int bh = t2 / M_FEAT, m = t2 % M_FEAT;
            float run = 0.f;
            for (int c = 0; c < NC; c++) {
                size_t idx = ((size_t)bh * NC + c) * M_FEAT + m;
                float tz = kz[idx]; kz[idx] = run; run += tz;
            }
        }
    }
}

// ============ tensor-core chunked causal linear attention. grid (NC, NH, B) ========
#define SPITCH 132
#define SMEM_ATTN (128 * SPITCH * 4 + 4 * 8192 + 512)

__global__ __launch_bounds__(256, 1) void attn_tc(
    const __nv_bfloat16* __restrict__ pqh, const __nv_bfloat16* __restrict__ pql,
    const __nv_bfloat16* __restrict__ pkh, const __nv_bfloat16* __restrict__ pkl,
    const float* __restrict__ qkv, const float* __restrict__ kvpre,
    const float* __restrict__ kzpre,
    __nv_bfloat16* __restrict__ ath, __nv_bfloat16* __restrict__ atl)
{
    extern __shared__ float sm[];
    float* Ss = sm;
    char* Ah = (char*)(sm + 128 * SPITCH);
    char* Al = Ah + 8192;
    char* Bh = Al + 8192;
    char* Bl = Bh + 8192;
    float* Zs = (float*)(Bl + 8192);

    const uint32_t sbAh = smem_u32g(Ah), sbAl = smem_u32g(Al);
    const uint32_t sbBh = smem_u32g(Bh), sbBl = smem_u32g(Bl);

    const int c = blockIdx.x, h = blockIdx.y, b = blockIdx.z;
    const int kvh = h >> 2;
    const int tid = threadIdx.x;
    const int warp = tid >> 5, lane = tid & 31;
    const int gid = lane >> 2, tig = lane & 3;

    const size_t qbase  = (size_t)(b * NH + h) * S_LEN + c * CHUNK;
    const size_t kbase  = (size_t)(b * NKV + kvh) * S_LEN + c * CHUNK;
    const size_t vrow0  = (size_t)b * S_LEN + c * CHUNK;
    const size_t kvbase = ((size_t)(b * NKV + kvh) * NC + c) * (size_t)(M_FEAT * D_HEAD);
    const size_t kzbase = ((size_t)(b * NKV + kvh) * NC + c) * M_FEAT;

    const int strow = tid & 127;
    const int s0 = tid >> 7;

    const int swm   = ((lane & 7) >> 1) & 3;
    const int rlocA = (lane & 7) + (((lane >> 3) & 1) << 3);
    const int shA   = lane >> 4;
    const int rlocB = (lane & 7) + ((lane >> 4) << 3);
    const int shB   = (lane >> 3) & 1;

    // ======================= Phase 1: scores =======================
    {
        const int wm = (warp & 1) * 64, wn = (warp >> 1) * 32;
        float acc[4][4][4];
#pragma unroll
        for (int i = 0; i < 4; i++)
#pragma unroll
            for (int j = 0; j < 4; j++)
#pragma unroll
                for (int r = 0; r < 4; r++) acc[i][j][r] = 0.f;

        for (int m0 = 0; m0 < M_FEAT; m0 += 32) {
#pragma unroll
            for (int si = 0; si < 2; si++) {
                const int s = s0 + si * 2;
                const uint32_t off = (uint32_t)(strow * 64 + ((s ^ ((strow >> 1) & 3)) * 16));
                const size_t ia = (qbase + strow) * M_FEAT + m0 + s * 8;
                *(uint4*)(Ah + off) = *(const uint4*)(pqh + ia);
                *(uint4*)(Al + off) = *(const uint4*)(pql + ia);
                const size_t ib = (kbase + strow) * M_FEAT + m0 + s * 8;
                *(uint4*)(Bh + off) = *(const uint4*)(pkh + ib);
                *(uint4*)(Bl + off) = *(const uint4*)(pkl + ib);
            }
            __syncthreads();
#pragma unroll
            for (int kb = 0; kb < 2; kb++) {
                uint32_t ah[4][4], al[4][4];
#pragma unroll
                for (int tm = 0; tm < 4; tm++) {
                    const int r = wm + tm * 16 + rlocA;
                    const uint32_t off = (uint32_t)(r * 64 + (((2 * kb + shA) ^ swm) * 16));
                    LDSM4(ah[tm], sbAh + off);
                    LDSM4(al[tm], sbAl + off);
                }
                uint32_t bhf[2][4], blf[2][4];
#pragma unroll
                for (int p = 0; p < 2; p++) {
                    const int r = wn + p * 16 + rlocB;
                    const uint32_t off = (uint32_t)(r * 64 + (((2 * kb + shB) ^ swm) * 16));
                    LDSM4(bhf[p], sbBh + off);
                    LDSM4(blf[p], sbBl + off);
                }
#pragma unroll
                for (int tm = 0; tm < 4; tm++)
#pragma unroll
                    for (int tn = 0; tn < 4; tn++) {
                        const uint32_t* bh2 = &bhf[tn >> 1][(tn & 1) * 2];
                        const uint32_t* bl2 = &blf[tn >> 1][(tn & 1) * 2];
                        mma_bf16(acc[tm][tn], ah[tm], bh2);
                        mma_bf16(acc[tm][tn], ah[tm], bl2);
                        mma_bf16(acc[tm][tn], al[tm], bh2);
                    }
            }
            __syncthreads();
        }
#pragma unroll
        for (int tm = 0; tm < 4; tm++) {
            const int r0 = wm + tm * 16 + gid;
            const int r1 = r0 + 8;
#pragma unroll
            for (int tn = 0; tn < 4; tn++) {
                const int col = wn + tn * 8 + tig * 2;
                Ss[r0 * SPITCH + col]     = (col     <= r0) ? acc[tm][tn][0] : 0.f;
                Ss[r0 * SPITCH + col + 1] = (col + 1 <= r0) ? acc[tm][tn][1] : 0.f;
                Ss[r1 * SPITCH + col]     = (col     <= r1) ? acc[tm][tn][2] : 0.f;
                Ss[r1 * SPITCH + col + 1] = (col + 1 <= r1) ? acc[tm][tn][3] : 0.f;
            }
        }
    }
    __syncthreads();

    // ======================= Phase 2: inter+intra (+z col 64) =======================
    const int wm2 = (warp & 3) * 32, wn2 = (warp >> 2) * 40;
    float acc2[2][5][4];
#pragma unroll
    for (int i = 0; i < 2; i++)
#pragma unroll
        for (int j = 0; j < 5; j++)
#pragma unroll
            for (int r = 0; r < 4; r++) acc2[i][j][r] = 0.f;

    for (int cc = 0; cc < 12; cc++) {
#pragma unroll
        for (int si = 0; si < 2; si++) {
            const int s = s0 + si * 2;
            const uint32_t off = (uint32_t)(strow * 64 + ((s ^ ((strow >> 1) & 3)) * 16));
            if (cc < 8) {
                const size_t ia = (qbase + strow) * M_FEAT + cc * 32 + s * 8;
                *(uint4*)(Ah + off) = *(const uint4*)(pqh + ia);
                *(uint4*)(Al + off) = *(const uint4*)(pql + ia);
            } else {
                float f[8];
                const float* pa = Ss + strow * SPITCH + (cc - 8) * 32 + s * 8;
                *(float4*)&f[0] = *(const float4*)pa;
                *(float4*)&f[4] = *(const float4*)(pa + 4);
                uint4 hv, lv;
                pack8(f, hv, lv);
                *(uint4*)(Ah + off) = hv;
                *(uint4*)(Al + off) = lv;
            }

            if (strow < 96) {
                float g[8];
                if (strow < 64) {
                    if (cc < 8) {
#pragma unroll
                        for (int e = 0; e < 8; e++)
                            g[e] = kvpre[kvbase + (size_t)(cc * 32 + s * 8 + e) * 64 + strow];
                    } else {
#pragma unroll
                        for (int e = 0; e < 8; e++)
                            g[e] = qkv[(vrow0 + (cc - 8) * 32 + s * 8 + e) * QKVW + 2560 + kvh * 64 + strow];
                    }
                } else if (strow == 64) {
                    if (cc < 8) {
#pragma unroll
                        for (int e = 0; e < 8; e++)
                            g[e] = kzpre[kzbase + cc * 32 + s * 8 + e];
                    } else {
#pragma unroll
                        for (int e = 0; e < 8; e++) g[e] = 1.f;
                    }
                } else {
#pragma unroll
                    for (int e = 0; e < 8; e++) g[e] = 0.f;
                }
                uint4 hv, lv;
                pack8(g, hv, lv);
                *(uint4*)(Bh + off) = hv;
                *(uint4*)(Bl + off) = lv;
            }
        }
        __syncthreads();
#pragma unroll
        for (int kb = 0; kb < 2; kb++) {
            uint32_t ah2[2][4], al2[2][4], bh2[3][4], bl2[3][4];
#pragma unroll
            for (int tm = 0; tm < 2; tm++) {
                const int r = wm2 + tm * 16 + rlocA;
                const uint32_t off = (uint32_t)(r * 64 + (((2 * kb + shA) ^ swm) * 16));
                LDSM4(ah2[tm], sbAh + off);
                LDSM4(al2[tm], sbAl + off);
            }
#pragma unroll
            for (int p = 0; p < 3; p++) {
                const int r = wn2 + p * 16 + rlocB;
                const uint32_t off = (uint32_t)(r * 64 + (((2 * kb + shB) ^ swm) * 16));
                LDSM4(bh2[p], sbBh + off);
                LDSM4(bl2[p], sbBl + off);
            }
#pragma unroll
            for (int tm = 0; tm < 2; tm++)
#pragma unroll
                for (int tn = 0; tn < 5; tn++) {
                    const uint32_t* bh_ = &bh2[tn >> 1][(tn & 1) * 2];
                    const uint32_t* bl_ = &bl2[tn >> 1][(tn & 1) * 2];
                    mma_bf16(acc2[tm][tn], ah2[tm], bh_);
                    mma_bf16(acc2[tm][tn], ah2[tm], bl_);
                    mma_bf16(acc2[tm][tn], al2[tm], bh_);
                }
        }
        __syncthreads();
    }

    if ((warp >> 2) == 1 && tig == 0) {
#pragma unroll
        for (int tm = 0; tm < 2; tm++) {
            const int r = wm2 + tm * 16 + gid;
            Zs[r]     = acc2[tm][3][0];
            Zs[r + 8] = acc2[tm][3][2];
        }
    }
    __syncthreads();

#pragma unroll
    for (int tm = 0; tm < 2; tm++) {
        const int r = wm2 + tm * 16 + gid;
        const float d0 = 1.f / (Zs[r] + 1e-6f);
        const float d1 = 1.f / (Zs[r + 8] + 1e-6f);
#pragma unroll
        for (int tn = 0; tn < 5; tn++) {
            const int col = wn2 + tn * 8 + tig * 2;
            if (col < 64) {
                const size_t ro = ((size_t)b * S_LEN + c * CHUNK + r) * (NH * D_HEAD) + h * 64 + col;
                const size_t ro8 = ro + 8 * (NH * D_HEAD);
                float o0 = acc2[tm][tn][0] * d0, o1 = acc2[tm][tn][1] * d0;
                float o2 = acc2[tm][tn][2] * d1, o3 = acc2[tm][tn][3] * d1;
                __nv_bfloat16 h0 = __float2bfloat16(o0), h1 = __float2bfloat16(o1);
                __nv_bfloat16 h2 = __float2bfloat16(o2), h3 = __float2bfloat16(o3);
                *(__nv_bfloat162*)(ath + ro)  = __nv_bfloat162(h0, h1);
                *(__nv_bfloat162*)(ath + ro8) = __nv_bfloat162(h2, h3);
                *(__nv_bfloat162*)(atl + ro)  =
                    __nv_bfloat162(__float2bfloat16(o0 - __bfloat162float(h0)),
                                   __float2bfloat16(o1 - __bfloat162float(h1)));
                *(__nv_bfloat162*)(atl + ro8) =
                    __nv_bfloat162(__float2bfloat16(o2 - __bfloat162float(h2)),
                                   __float2bfloat16(o3 - __bfloat162float(h3)));
            }
        }
    }
}

// ----------------------------------- launch ---------------------------------------
extern "C" void kernel_launch(void* const* d_in, const int* in_sizes, int n_in,
                              void* d_out, int out_size)
{
    const float* hs   = (const float*)d_in[0];
    const float* cosp = (const float*)d_in[1];
    const float* sinp = (const float*)d_in[2];
    const float* Wq   = (const float*)d_in[3];
    const float* Wk   = (const float*)d_in[4];
    const float* Wv   = (const float*)d_in[5];
    const float* Wo   = (const float*)d_in[6];
    const float* proj = (const float*)d_in[7];
    float* out = (float*)d_out;

    float *qkvp, *xpkp, *sqkp, *stabp, *kvp, *kzp;
    cudaGetSymbolAddress((void**)&qkvp,  g_qkv);
    cudaGetSymbolAddress((void**)&xpkp,  g_xpk);
    cudaGetSymbolAddress((void**)&sqkp,  g_sqk);
    cudaGetSymbolAddress((void**)&stabp, g_stab);
    cudaGetSymbolAddress((void**)&kvp,   g_kv);
    cudaGetSymbolAddress((void**)&kzp,   g_kz);

    __nv_bfloat16 *pqh, *pql, *pkh, *pkl, *hsh, *hsl, *ath, *atl, *wh, *wl;
    cudaGetSymbolAddress((void**)&pqh, g_pqh);
    cudaGetSymbolAddress((void**)&pql, g_pql);
    cudaGetSymbolAddress((void**)&pkh, g_pkh);
    cudaGetSymbolAddress((void**)&pkl, g_pkl);
    cudaGetSymbolAddress((void**)&hsh, g_hsh);
    cudaGetSymbolAddress((void**)&hsl, g_hsl);
    cudaGetSymbolAddress((void**)&ath, g_ath);
    cudaGetSymbolAddress((void**)&atl, g_atl);
    cudaGetSymbolAddress((void**)&wh,  g_wh);
    cudaGetSymbolAddress((void**)&wl,  g_wl);

    cudaFuncSetAttribute(gemm_bf16x3, cudaFuncAttributeMaxDynamicSharedMemorySize, SMEM_GEMM);
    cudaFuncSetAttribute(attn_tc, cudaFuncAttributeMaxDynamicSharedMemorySize, SMEM_ATTN);

    // ---- splits ----
    split_bf16<<<(HS_ELEMS / 4 + 255) / 256, 256>>>(hs, hsh, hsl, HS_ELEMS / 4);
    split_bf16<<<(HID_ * HID_ / 4 + 255) / 256, 256>>>(Wq, wh + WQ_OFF, wl + WQ_OFF, HID_ * HID_ / 4);
    split_bf16<<<(512 * HID_ / 4 + 255) / 256, 256>>>(Wk, wh + WK_OFF, wl + WK_OFF, 512 * HID_ / 4);
    split_bf16<<<(512 * HID_ / 4 + 255) / 256, 256>>>(Wv, wh + WV_OFF, wl + WV_OFF, 512 * HID_ / 4);
    split_bf16<<<(HID_ * HID_ / 4 + 255) / 256, 256>>>(Wo, wh + WO_OFF, wl + WO_OFF, HID_ * HID_ / 4);

    // ---- fused QKV projection (128x128 tiles) ----
    gemm_bf16x3<<<dim3(QKVW / 128, 32), 256, SMEM_GEMM>>>(hsh, hsl, wh, wl, qkvp, QKVW);

    // ---- RoPE ----
    rope_kernel<<<B_SZ * S_LEN, NH * 32>>>(qkvp, cosp, sinp, QKVW, 0);
    rope_kernel<<<B_SZ * S_LEN, NKV * 32>>>(qkvp, cosp, sinp, QKVW, 2048);

    // ---- favor features ----
    init_stab_kernel<<<1, 32>>>(stabp);
    favor_xp<<<dim3(S_LEN / 32, NH, B_SZ), 256>>>(qkvp, proj, nullptr, pqh, pql, nullptr, nullptr, NH, QKVW, 0);
    favor_xp<<<dim3(S_LEN / 32, NKV, B_SZ), 256>>>(qkvp, proj, xpkp, nullptr, nullptr, sqkp, stabp, NKV, QKVW, 2048);
    favor_fin<<<(B_SZ * NKV * S_LEN) / 8, 256>>>(xpkp, sqkp, stabp, pkh, pkl, B_SZ * NKV * S_LEN);

    // ---- chunked linear attention ----
    kv_chunk<<<dim3(NC, NKV, B_SZ), 256>>>(pkh, pkl, qkvp, kvp, kzp);
    cumsum_k<<<(B_SZ * NKV * (M_FEAT * D_HEAD + M_FEAT) + 255) / 256, 256>>>(kvp, kzp);
    attn_tc<<<dim3(NC, NH, B_SZ), 256, SMEM_ATTN>>>(pqh, pql, pkh, pkl, qkvp, kvp, kzp, ath, atl);

    // ---- output projection (128x128 tiles) ----
    gemm_bf16x3<<<dim3(16, 32), 256, SMEM_GEMM>>>(ath, atl, wh + WO_OFF, wl + WO_OFF, out, 2048);
}

// round 11
// speedup vs baseline: 1.6064x; 1.0074x over previous
#include <cuda_runtime.h>
#include <cuda_bf16.h>
#include <math.h>
#include <stdint.h>

#define B_SZ   2
#define S_LEN  2048
#define HID_   2048
#define NH     32
#define NKV    8
#define D_HEAD 64
#define M_FEAT 256
#define NC     16
#define CHUNK  128
#define QKVW   3072

// ---------------- scratch (device globals; no allocations allowed) ----------------
__device__ float g_qkv [(size_t)B_SZ * S_LEN * QKVW];
__device__ float g_xpk [(size_t)B_SZ * NKV * S_LEN * M_FEAT];
__device__ float g_sqk [B_SZ * NKV * S_LEN];
__device__ float g_stab[B_SZ * NKV];
__device__ float g_kv  [B_SZ * NKV * NC * M_FEAT * D_HEAD];
__device__ float g_kz  [B_SZ * NKV * NC * M_FEAT];

#define PHIQ_E ((size_t)B_SZ * NH  * S_LEN * M_FEAT)
#define PHIK_E ((size_t)B_SZ * NKV * S_LEN * M_FEAT)
#define HS_ELEMS  (B_SZ * S_LEN * HID_)
#define W_ELEMS   (QKVW * HID_ + HID_ * HID_)
__device__ __align__(16) __nv_bfloat16 g_pqh[PHIQ_E];
__device__ __align__(16) __nv_bfloat16 g_pql[PHIQ_E];
__device__ __align__(16) __nv_bfloat16 g_pkh[PHIK_E];
__device__ __align__(16) __nv_bfloat16 g_pkl[PHIK_E];
__device__ __align__(16) __nv_bfloat16 g_hsh[HS_ELEMS];
__device__ __align__(16) __nv_bfloat16 g_hsl[HS_ELEMS];
__device__ __align__(16) __nv_bfloat16 g_ath[HS_ELEMS];
__device__ __align__(16) __nv_bfloat16 g_atl[HS_ELEMS];
__device__ __align__(16) __nv_bfloat16 g_wh [W_ELEMS];
__device__ __align__(16) __nv_bfloat16 g_wl [W_ELEMS];

#define WQ_OFF 0
#define WK_OFF (HID_ * HID_)
#define WV_OFF (WK_OFF + 512 * HID_)
#define WO_OFF (WV_OFF + 512 * HID_)

// =================== fp32 -> bf16 hi/lo split (elementwise, x4 vec) ================
__global__ void split_bf16(const float* __restrict__ x, __nv_bfloat16* __restrict__ h,
                           __nv_bfloat16* __restrict__ l, int n4)
{
    int i = blockIdx.x * blockDim.x + threadIdx.x;
    if (i >= n4) return;
    float4 v = ((const float4*)x)[i];
    __nv_bfloat16 h0 = __float2bfloat16(v.x), h1 = __float2bfloat16(v.y);
    __nv_bfloat16 h2 = __float2bfloat16(v.z), h3 = __float2bfloat16(v.w);
    __nv_bfloat162* hp = (__nv_bfloat162*)h;
    hp[2 * i]     = __nv_bfloat162(h0, h1);
    hp[2 * i + 1] = __nv_bfloat162(h2, h3);
    __nv_bfloat162* lp = (__nv_bfloat162*)l;
    lp[2 * i]     = __nv_bfloat162(__float2bfloat16(v.x - __bfloat162float(h0)),
                                   __float2bfloat16(v.y - __bfloat162float(h1)));
    lp[2 * i + 1] = __nv_bfloat162(__float2bfloat16(v.z - __bfloat162float(h2)),
                                   __float2bfloat16(v.w - __bfloat162float(h3)));
}

// ===================== shared helpers for tensor-core kernels ======================
__device__ __forceinline__ uint32_t smem_u32g(const void* p)
{
    uint32_t a;
    asm("{ .reg .u64 t; cvta.to.shared.u64 t, %1; cvt.u32.u64 %0, t; }" : "=r"(a) : "l"(p));
    return a;
}

#define LDSM4(r, a) \
    asm volatile("ldmatrix.sync.aligned.m8n8.x4.shared.b16 {%0,%1,%2,%3}, [%4];" \
                 : "=r"((r)[0]), "=r"((r)[1]), "=r"((r)[2]), "=r"((r)[3]) : "r"(a))

#define CP_ASYNC16(dst, src) \
    asm volatile("cp.async.cg.shared.global [%0], [%1], 16;" :: "r"(dst), "l"(src) : "memory")
#define CP_COMMIT() asm volatile("cp.async.commit_group;" ::: "memory")
#define CP_WAIT(n)  asm volatile("cp.async.wait_group %0;" :: "n"(n) : "memory")

__device__ __forceinline__ void mma_bf16(float c[4], const uint32_t a[4], const uint32_t b[2])
{
    asm volatile("mma.sync.aligned.m16n8k16.row.col.f32.bf16.bf16.f32 "
                 "{%0,%1,%2,%3}, {%4,%5,%6,%7}, {%8,%9}, {%0,%1,%2,%3};"
                 : "+f"(c[0]), "+f"(c[1]), "+f"(c[2]), "+f"(c[3])
                 : "r"(a[0]), "r"(a[1]), "r"(a[2]), "r"(a[3]), "r"(b[0]), "r"(b[1]));
}

__device__ __forceinline__ void pack8(const float* f, uint4& hv, uint4& lv)
{
    uint32_t hw[4], lw[4];
#pragma unroll
    for (int e = 0; e < 4; e++) {
        __nv_bfloat16 h0 = __float2bfloat16(f[2 * e]);
        __nv_bfloat16 h1 = __float2bfloat16(f[2 * e + 1]);
        __nv_bfloat162 hp(h0, h1);
        hw[e] = *(uint32_t*)&hp;
        __nv_bfloat162 lp(__float2bfloat16(f[2 * e]     - __bfloat162float(h0)),
                          __float2bfloat16(f[2 * e + 1] - __bfloat162float(h1)));
        lw[e] = *(uint32_t*)&lp;
    }
    hv = make_uint4(hw[0], hw[1], hw[2], hw[3]);
    lv = make_uint4(lw[0], lw[1], lw[2], lw[3]);
}

// ======== bf16 3-pass split GEMM: 128x128 tile, cp.async, ldmatrix =================
#define GK 2048
#define BK 32
#define NKT (GK / BK)
#define GBUF 32768
#define SMEM_GEMM (2 * GBUF)

__global__ __launch_bounds__(256, 2) void gemm_bf16x3(const __nv_bfloat16* __restrict__ Ah,
                                                      const __nv_bfloat16* __restrict__ Al,
                                                      const __nv_bfloat16* __restrict__ Bh,
                                                      const __nv_bfloat16* __restrict__ Bl,
                                                      float* __restrict__ C, int N)
{
    extern __shared__ char smc[];
    const uint32_t sb = smem_u32g(smc);
    const int tid  = threadIdx.x;
    const int warp = tid >> 5, lane = tid & 31;
    const int gid  = lane >> 2, tig = lane & 3;
    const int wm   = (warp & 1) * 64;
    const int wn   = (warp >> 1) * 32;
    const int rowA = blockIdx.y * 128;
    const int rowB = blockIdx.x * 128;

    // staging chunks: thread handles chunk tid and tid+256; chunk -> row=c>>2, slot=c&3
    const int r0s = tid >> 2,        s0s = tid & 3;
    const int r1s = (tid + 256) >> 2, s1s = tid & 3;   // +256 => row + 64, same slot
    const uint32_t so0 = (uint32_t)(r0s * 64 + ((s0s ^ ((r0s >> 1) & 3)) * 16));
    const uint32_t so1 = (uint32_t)(r1s * 64 + ((s1s ^ ((r1s >> 1) & 3)) * 16));

    const int swm   = ((lane & 7) >> 1) & 3;
    const int rlocA = (lane & 7) + (((lane >> 3) & 1) << 3);
    const int shA   = lane >> 4;
    const int rlocB = (lane & 7) + ((lane >> 4) << 3);
    const int shB   = (lane >> 3) & 1;

    float acc[4][4][4];
#pragma unroll
    for (int i = 0; i < 4; i++)
#pragma unroll
        for (int j = 0; j < 4; j++)
#pragma unroll
            for (int r = 0; r < 4; r++) acc[i][j][r] = 0.f;

    auto stage = [&](int kt, int b) {
        const uint32_t bb = sb + b * GBUF;
        const int kb = kt * BK;
        CP_ASYNC16(bb + so0,         (const char*)(Ah + (size_t)(rowA + r0s) * GK + kb + s0s * 8));
        CP_ASYNC16(bb + so1,         (const char*)(Ah + (size_t)(rowA + r1s) * GK + kb + s1s * 8));
        CP_ASYNC16(bb + 8192  + so0, (const char*)(Al + (size_t)(rowA + r0s) * GK + kb + s0s * 8));
        CP_ASYNC16(bb + 8192  + so1, (const char*)(Al + (size_t)(rowA + r1s) * GK + kb + s1s * 8));
        CP_ASYNC16(bb + 16384 + so0, (const char*)(Bh + (size_t)(rowB + r0s) * GK + kb + s0s * 8));
        CP_ASYNC16(bb + 16384 + so1, (const char*)(Bh + (size_t)(rowB + r1s) * GK + kb + s1s * 8));
        CP_ASYNC16(bb + 24576 + so0, (const char*)(Bl + (size_t)(rowB + r0s) * GK + kb + s0s * 8));
        CP_ASYNC16(bb + 24576 + so1, (const char*)(Bl + (size_t)(rowB + r1s) * GK + kb + s1s * 8));
        CP_COMMIT();
    };

    stage(0, 0);

    for (int kt = 0; kt < NKT; kt++) {
        if (kt + 1 < NKT) {
            stage(kt + 1, (kt + 1) & 1);
            CP_WAIT(1);
        } else {
            CP_WAIT(0);
        }
        __syncthreads();

        const uint32_t base = sb + (kt & 1) * GBUF;
#pragma unroll
        for (int kb = 0; kb < 2; kb++) {
            uint32_t ah[4][4], al[4][4];
#pragma unroll
            for (int tm = 0; tm < 4; tm++) {
                const int r = wm + tm * 16 + rlocA;
                const uint32_t off = (uint32_t)(r * 64 + (((2 * kb + shA) ^ swm) * 16));
                LDSM4(ah[tm], base + off);
                LDSM4(al[tm], base + 8192 + off);
            }
            uint32_t bhf[2][4], blf[2][4];
#pragma unroll
            for (int p = 0; p < 2; p++) {
                const int r = wn + p * 16 + rlocB;
                const uint32_t off = (uint32_t)(r * 64 + (((2 * kb + shB) ^ swm) * 16));
                LDSM4(bhf[p], base + 16384 + off);
                LDSM4(blf[p], base + 24576 + off);
            }
#pragma unroll
            for (int tm = 0; tm < 4; tm++)
#pragma unroll
                for (int tn = 0; tn < 4; tn++) {
                    const uint32_t* bh2 = &bhf[tn >> 1][(tn & 1) * 2];
                    const uint32_t* bl2 = &blf[tn >> 1][(tn & 1) * 2];
                    mma_bf16(acc[tm][tn], ah[tm], bh2);
                    mma_bf16(acc[tm][tn], ah[tm], bl2);
                    mma_bf16(acc[tm][tn], al[tm], bh2);
                }
        }
        __syncthreads();
    }

#pragma unroll
    for (int tm = 0; tm < 4; tm++) {
        const size_t r0 = (size_t)rowA + wm + tm * 16 + gid;
#pragma unroll
        for (int tn = 0; tn < 4; tn++) {
            const int cn = rowB + wn + tn * 8 + tig * 2;
            *(float2*)(C + r0 * N + cn)       = make_float2(acc[tm][tn][0], acc[tm][tn][1]);
            *(float2*)(C + (r0 + 8) * N + cn) = make_float2(acc[tm][tn][2], acc[tm][tn][3]);
        }
    }
}

__device__ void atomicMaxFloat(float* addr, float val)
{
    int* ia = (int*)addr;
    int old = *ia;
    while (__int_as_float(old) < val) {
        int assumed = old;
        old = atomicCAS(ia, assumed, __float_as_int(val));
        if (old == assumed) break;
    }
}

__global__ void init_stab_kernel(float* stab)
{
    if (threadIdx.x < B_SZ * NKV) stab[threadIdx.x] = -3.4e38f;
}

// ---------------- favor xp (RoPE fused in-smem) ------------------------------------
// q path (stab==null): fused exp, writes bf16 hi/lo phi directly.
// k path: writes fp32 xp (+ sq, head max).
__global__ __launch_bounds__(256) void favor_xp(const float* __restrict__ x,
                                                const float* __restrict__ cosp,
                                                const float* __restrict__ sinp,
                                                const float* __restrict__ proj,
                                                float* __restrict__ xp,
                                                __nv_bfloat16* __restrict__ ph,
                                                __nv_bfloat16* __restrict__ pl,
                                                float* __restrict__ sq,
                                                float* __restrict__ stab,
                                                int nheads, int xstride, int xcoloff)
{
    __shared__ float As[32 * 68];
    __shared__ float Bs[16][256];
    __shared__ float red[256];
    __shared__ float sqsh[32];
    const float DN = 0.35355339059327373f;
    const int s0 = blockIdx.x * 32, h = blockIdx.y, b = blockIdx.z;
    const int tid = threadIdx.x;

    // stage x*DN
#pragma unroll
    for (int r = 0; r < 2; r++) {
        int l = tid + r * 256;
        int tok = l >> 4, q4 = (l & 15) << 2;
        float4 vv = *(const float4*)(x + (size_t)(b * S_LEN + s0 + tok) * xstride + xcoloff + h * 64 + q4);
        As[tok * 68 + q4 + 0] = vv.x * DN;
        As[tok * 68 + q4 + 1] = vv.y * DN;
        As[tok * 68 + q4 + 2] = vv.z * DN;
        As[tok * 68 + q4 + 3] = vv.w * DN;
    }
    __syncthreads();

    // fused RoPE: 1024 pairs (32 tok x 32 p), each thread owns its pairs (no hazard)
#pragma unroll
    for (int r = 0; r < 4; r++) {
        int idx = tid + r * 256;
        int tok = idx >> 5, p = idx & 31;
        const size_t crow = (size_t)(b * S_LEN + s0 + tok) * 64;
        const float c1 = cosp[crow + p],      sn1 = sinp[crow + p];
        const float c2 = cosp[crow + 32 + p], sn2 = sinp[crow + 32 + p];
        float a  = As[tok * 68 + p];
        float b2 = As[tok * 68 + p + 32];
        As[tok * 68 + p]      = a * c1 - b2 * sn1;
        As[tok * 68 + p + 32] = b2 * c2 + a * sn2;
    }
    __syncthreads();

    if (tid < 32) {
        float ssum = 0.f;
#pragma unroll
        for (int d = 0; d < 64; d++) { float vv = As[tid * 68 + d]; ssum += vv * vv; }
        sqsh[tid] = 0.5f * ssum;
        if (sq) sq[((size_t)(b * nheads + h)) * S_LEN + s0 + tid] = 0.5f * ssum;
    }

    const int tg = tid >> 5, mg = tid & 31;
    float acc[4][8];
#pragma unroll
    for (int i = 0; i < 4; i++)
#pragma unroll
        for (int j = 0; j < 8; j++) acc[i][j] = 0.f;

    for (int k0 = 0; k0 < 64; k0 += 16) {
#pragma unroll
        for (int j = 0; j < 4; j++) {
            float4 p = *(const float4*)(proj + tid * 64 + k0 + j * 4);
            Bs[j * 4 + 0][tid] = p.x; Bs[j * 4 + 1][tid] = p.y;
            Bs[j * 4 + 2][tid] = p.z; Bs[j * 4 + 3][tid] = p.w;
        }
        __syncthreads();
#pragma unroll
        for (int kk = 0; kk < 16; kk++) {
            float a[4];
#pragma unroll
            for (int i = 0; i < 4; i++) a[i] = As[(tg * 4 + i) * 68 + k0 + kk];
            float bb[8];
            *(float4*)&bb[0] = *(const float4*)&Bs[kk][mg * 8];
            *(float4*)&bb[4] = *(const float4*)&Bs[kk][mg * 8 + 4];
#pragma unroll
            for (int i = 0; i < 4; i++)
#pragma unroll
                for (int j = 0; j < 8; j++) acc[i][j] += a[i] * bb[j];
        }
        __syncthreads();
    }

    const size_t rowbase = (size_t)(b * nheads + h) * S_LEN + s0;
    if (stab == nullptr) {
#pragma unroll
        for (int i = 0; i < 4; i++) {
            float m = acc[i][0];
#pragma unroll
            for (int j = 1; j < 8; j++) m = fmaxf(m, acc[i][j]);
#pragma unroll
            for (int o = 16; o > 0; o >>= 1) m = fmaxf(m, __shfl_xor_sync(0xffffffffu, m, o));
            const float sv = sqsh[tg * 4 + i];
#pragma unroll
            for (int j = 0; j < 8; j++)
                acc[i][j] = (__expf(acc[i][j] - sv - m) + 1e-6f) * 0.0625f;
            uint4 hv, lv;
            pack8(acc[i], hv, lv);
            *(uint4*)(ph + (rowbase + tg * 4 + i) * M_FEAT + mg * 8) = hv;
            *(uint4*)(pl + (rowbase + tg * 4 + i) * M_FEAT + mg * 8) = lv;
        }
    } else {
        float mx = -3.4e38f;
#pragma unroll
        for (int i = 0; i < 4; i++) {
            *(float4*)(xp + (rowbase + tg * 4 + i) * M_FEAT + mg * 8) =
                make_float4(acc[i][0], acc[i][1], acc[i][2], acc[i][3]);
            *(float4*)(xp + (rowbase + tg * 4 + i) * M_FEAT + mg * 8 + 4) =
                make_float4(acc[i][4], acc[i][5], acc[i][6], acc[i][7]);
#pragma unroll
            for (int j = 0; j < 8; j++) mx = fmaxf(mx, acc[i][j]);
        }
        red[tid] = mx;
        __syncthreads();
        for (int st = 128; st > 0; st >>= 1) {
            if (tid < st) red[tid] = fmaxf(red[tid], red[tid + st]);
            __syncthreads();
        }
        if (tid == 0) atomicMaxFloat(&stab[b * nheads + h], red[0]);
    }
}

// ---------------- k finalize: exp + split to bf16 hi/lo ----------------------------
__global__ void favor_fin(const float* __restrict__ xp, const float* __restrict__ sq,
                          const float* __restrict__ stab,
                          __nv_bfloat16* __restrict__ ph, __nv_bfloat16* __restrict__ pl,
                          int nrows)
{
    const int warp = (blockIdx.x * blockDim.x + threadIdx.x) >> 5;
    const int lane = threadIdx.x & 31;
    if (warp >= nrows) return;
    const float* row = xp + (size_t)warp * M_FEAT;
    const float mx  = stab[warp / S_LEN];
    const float sqv = sq[warp];
    float f[8];
    *(float4*)&f[0] = *(const float4*)(row + lane * 8);
    *(float4*)&f[4] = *(const float4*)(row + lane * 8 + 4);
#pragma unroll
    for (int k = 0; k < 8; k++) f[k] = (__expf(f[k] - sqv - mx) + 1e-6f) * 0.0625f;
    uint4 hv, lv;
    pack8(f, hv, lv);
    *(uint4*)(ph + (size_t)warp * M_FEAT + lane * 8) = hv;
    *(uint4*)(pl + (size_t)warp * M_FEAT + lane * 8) = lv;
}

// ---------------- per-chunk kv (M x D) and kz (M). grid (NC, NKV, B) ---------------
__global__ __launch_bounds__(256) void kv_chunk(const __nv_bfloat16* __restrict__ pkh,
                                                const __nv_bfloat16* __restrict__ pkl,
                                                const float* __restrict__ qkv,
                                                float* __restrict__ kv,
                                                float* __restrict__ kz)
{
    __shared__ float ps[16][256];
    __shared__ float vs[16][64];
    const int c = blockIdx.x, h = blockIdx.y, b = blockIdx.z;
    const int tid = threadIdx.x;
    float acc[64];
#pragma unroll
    for (int d = 0; d < 64; d++) acc[d] = 0.f;
    float accz = 0.f;
    const size_t prow = (size_t)(b * NKV + h) * S_LEN + c * CHUNK;
    const size_t vrow = (size_t)b * S_LEN + c * CHUNK;

    for (int i0 = 0; i0 < CHUNK; i0 += 16) {
#pragma unroll
        for (int ii = 0; ii < 16; ii++) {
            const size_t idx = (prow + i0 + ii) * M_FEAT + tid;
            ps[ii][tid] = __bfloat162float(pkh[idx]) + __bfloat162float(pkl[idx]);
        }
#pragma unroll
        for (int j = 0; j < 4; j++) {
            int l = tid + j * 256;
            int ii = l >> 6, d = l & 63;
            vs[ii][d] = qkv[(vrow + i0 + ii) * QKVW + 2560 + h * 64 + d];
        }
        __syncthreads();
#pragma unroll
        for (int ii = 0; ii < 16; ii++) {
            float a = ps[ii][tid];
            accz += a;
#pragma unroll
            for (int d4 = 0; d4 < 64; d4 += 4) {
                float4 vv = *(const float4*)&vs[ii][d4];
                acc[d4 + 0] += a * vv.x; acc[d4 + 1] += a * vv.y;
                acc[d4 + 2] += a * vv.z; acc[d4 + 3] += a * vv.w;
            }
        }
        __syncthreads();
    }
    const size_t ob = (((size_t)(b * NKV + h) * NC + c) * M_FEAT + tid) * D_HEAD;
#pragma unroll
    for (int d4 = 0; d4 < 64; d4 += 4)
        *(float4*)(kv + ob + d4) = make_float4(acc[d4], acc[d4 + 1], acc[d4 + 2], acc[d4 + 3]);
    kz[((size_t)(b * NKV + h) * NC + c) * M_FEAT + tid] = accz;
}

// ---------------- exclusive prefix over chunk axis, in place ----------------------
__global__ void cumsum_k(float* __restrict__ kv, float* __restrict__ kz)
{
    const int tid = blockIdx.x * blockDim.x + threadIdx.x;
    const int KVSZ = M_FEAT * D_HEAD;
    if (tid < B_SZ * NKV * KVSZ) {
        int bh = tid / KVSZ, md = tid % KVSZ;
        float run = 0.f;
        for (int c = 0; c < NC; c++) {
            size_t idx = ((size_t)bh * NC + c) * KVSZ + md;
            float t = kv[idx]; kv[idx] = run; run += t;
        }
    } else {
        int t2 = tid - B_SZ * NKV * KVSZ;
        if (t2 < B_SZ * NKV * M_FEAT) {
            int bh = t2 / M_FEAT, m = t2 % M_FEAT;
            float run = 0.f;
            for (int c = 0; c < NC; c++) {
                size_t idx = ((size_t)bh * NC + c) * M_FEAT + m;
                float tz = kz[idx]; kz[idx] = run; run += tz;
            }
        }
    }
}

// ============ tensor-core chunked causal linear attention. grid (NC, NH, B) ========
#define SPITCH 132
#define SMEM_ATTN (128 * SPITCH * 4 + 4 * 8192 + 512)

__global__ __launch_bounds__(256, 1) void attn_tc(
    const __nv_bfloat16* __restrict__ pqh, const __nv_bfloat16* __restrict__ pql,
    const __nv_bfloat16* __restrict__ pkh, const __nv_bfloat16* __restrict__ pkl,
    const float* __restrict__ qkv, const float* __restrict__ kvpre,
    const float* __restrict__ kzpre,
    __nv_bfloat16* __restrict__ ath, __nv_bfloat16* __restrict__ atl)
{
    extern __shared__ float sm[];
    float* Ss = sm;
    char* Ah = (char*)(sm + 128 * SPITCH);
    char* Al = Ah + 8192;
    char* Bh = Al + 8192;
    char* Bl = Bh + 8192;
    float* Zs = (float*)(Bl + 8192);

    const uint32_t sbAh = smem_u32g(Ah), sbAl = smem_u32g(Al);
    const uint32_t sbBh = smem_u32g(Bh), sbBl = smem_u32g(Bl);

    const int c = blockIdx.x, h = blockIdx.y, b = blockIdx.z;
    const int kvh = h >> 2;
    const int tid = threadIdx.x;
    const int warp = tid >> 5, lane = tid & 31;
    const int gid = lane >> 2, tig = lane & 3;

    const size_t qbase  = (size_t)(b * NH + h) * S_LEN + c * CHUNK;
    const size_t kbase  = (size_t)(b * NKV + kvh) * S_LEN + c * CHUNK;
    const size_t vrow0  = (size_t)b * S_LEN + c * CHUNK;
    const size_t kvbase = ((size_t)(b * NKV + kvh) * NC + c) * (size_t)(M_FEAT * D_HEAD);
    const size_t kzbase = ((size_t)(b * NKV + kvh) * NC + c) * M_FEAT;

    const int strow = tid & 127;
    const int s0 = tid >> 7;

    const int swm   = ((lane & 7) >> 1) & 3;
    const int rlocA = (lane & 7) + (((lane >> 3) & 1) << 3);
    const int shA   = lane >> 4;
    const int rlocB = (lane & 7) + ((lane >> 4) << 3);
    const int shB   = (lane >> 3) & 1;

    // ======================= Phase 1: scores =======================
    {
        const int wm = (warp & 1) * 64, wn = (warp >> 1) * 32;
        float acc[4][4][4];
#pragma unroll
        for (int i = 0; i < 4; i++)
#pragma unroll
            for (int j = 0; j < 4; j++)
#pragma unroll
                for (int r = 0; r < 4; r++) acc[i][j][r] = 0.f;

        for (int m0 = 0; m0 < M_FEAT; m0 += 32) {
#pragma unroll
            for (int si = 0; si < 2; si++) {
                const int s = s0 + si * 2;
                const uint32_t off = (uint32_t)(strow * 64 + ((s ^ ((strow >> 1) & 3)) * 16));
                const size_t ia = (qbase + strow) * M_FEAT + m0 + s * 8;
                *(uint4*)(Ah + off) = *(const uint4*)(pqh + ia);
                *(uint4*)(Al + off) = *(const uint4*)(pql + ia);
                const size_t ib = (kbase + strow) * M_FEAT + m0 + s * 8;
                *(uint4*)(Bh + off) = *(const uint4*)(pkh + ib);
                *(uint4*)(Bl + off) = *(const uint4*)(pkl + ib);
            }
            __syncthreads();
#pragma unroll
            for (int kb = 0; kb < 2; kb++) {
                uint32_t ah[4][4], al[4][4];
#pragma unroll
                for (int tm = 0; tm < 4; tm++) {
                    const int r = wm + tm * 16 + rlocA;
                    const uint32_t off = (uint32_t)(r * 64 + (((2 * kb + shA) ^ swm) * 16));
                    LDSM4(ah[tm], sbAh + off);
                    LDSM4(al[tm], sbAl + off);
                }
                uint32_t bhf[2][4], blf[2][4];
#pragma unroll
                for (int p = 0; p < 2; p++) {
                    const int r = wn + p * 16 + rlocB;
                    const uint32_t off = (uint32_t)(r * 64 + (((2 * kb + shB) ^ swm) * 16));
                    LDSM4(bhf[p], sbBh + off);
                    LDSM4(blf[p], sbBl + off);
                }
#pragma unroll
                for (int tm = 0; tm < 4; tm++)
#pragma unroll
                    for (int tn = 0; tn < 4; tn++) {
                        const uint32_t* bh2 = &bhf[tn >> 1][(tn & 1) * 2];
                        const uint32_t* bl2 = &blf[tn >> 1][(tn & 1) * 2];
                        mma_bf16(acc[tm][tn], ah[tm], bh2);
                        mma_bf16(acc[tm][tn], ah[tm], bl2);
                        mma_bf16(acc[tm][tn], al[tm], bh2);
                    }
            }
            __syncthreads();
        }
#pragma unroll
        for (int tm = 0; tm < 4; tm++) {
            const int r0 = wm + tm * 16 + gid;
            const int r1 = r0 + 8;
#pragma unroll
            for (int tn = 0; tn < 4; tn++) {
                const int col = wn + tn * 8 + tig * 2;
                Ss[r0 * SPITCH + col]     = (col     <= r0) ? acc[tm][tn][0] : 0.f;
                Ss[r0 * SPITCH + col + 1] = (col + 1 <= r0) ? acc[tm][tn][1] : 0.f;
                Ss[r1 * SPITCH + col]     = (col     <= r1) ? acc[tm][tn][2] : 0.f;
                Ss[r1 * SPITCH + col + 1] = (col + 1 <= r1) ? acc[tm][tn][3] : 0.f;
            }
        }
    }
    __syncthreads();

    // ======================= Phase 2: inter+intra (+z col 64) =======================
    const int wm2 = (warp & 3) * 32, wn2 = (warp >> 2) * 40;
    float acc2[2][5][4];
#pragma unroll
    for (int i = 0; i < 2; i++)
#pragma unroll
        for (int j = 0; j < 5; j++)
#pragma unroll
            for (int r = 0; r < 4; r++) acc2[i][j][r] = 0.f;

    for (int cc = 0; cc < 12; cc++) {
#pragma unroll
        for (int si = 0; si < 2; si++) {
            const int s = s0 + si * 2;
            const uint32_t off = (uint32_t)(strow * 64 + ((s ^ ((strow >> 1) & 3)) * 16));
            if (cc < 8) {
                const size_t ia = (qbase + strow) * M_FEAT + cc * 32 + s * 8;
                *(uint4*)(Ah + off) = *(const uint4*)(pqh + ia);
                *(uint4*)(Al + off) = *(const uint4*)(pql + ia);
            } else {
                float f[8];
                const float* pa = Ss + strow * SPITCH + (cc - 8) * 32 + s * 8;
                *(float4*)&f[0] = *(const float4*)pa;
                *(float4*)&f[4] = *(const float4*)(pa + 4);
                uint4 hv, lv;
                pack8(f, hv, lv);
                *(uint4*)(Ah + off) = hv;
                *(uint4*)(Al + off) = lv;
            }

            if (strow < 96) {
                float g[8];
                if (strow < 64) {
                    if (cc < 8) {
#pragma unroll
                        for (int e = 0; e < 8; e++)
                            g[e] = kvpre[kvbase + (size_t)(cc * 32 + s * 8 + e) * 64 + strow];
                    } else {
#pragma unroll
                        for (int e = 0; e < 8; e++)
                            g[e] = qkv[(vrow0 + (cc - 8) * 32 + s * 8 + e) * QKVW + 2560 + kvh * 64 + strow];
                    }
                } else if (strow == 64) {
                    if (cc < 8) {
#pragma unroll
                        for (int e = 0; e < 8; e++)
                            g[e] = kzpre[kzbase + cc * 32 + s * 8 + e];
                    } else {
#pragma unroll
                        for (int e = 0; e < 8; e++) g[e] = 1.f;
                    }
                } else {
#pragma unroll
                    for (int e = 0; e < 8; e++) g[e] = 0.f;
                }
                uint4 hv, lv;
                pack8(g, hv, lv);
                *(uint4*)(Bh + off) = hv;
                *(uint4*)(Bl + off) = lv;
            }
        }
        __syncthreads();
#pragma unroll
        for (int kb = 0; kb < 2; kb++) {
            uint32_t ah2[2][4], al2[2][4], bh2[3][4], bl2[3][4];
#pragma unroll
            for (int tm = 0; tm < 2; tm++) {
                const int r = wm2 + tm * 16 + rlocA;
                const uint32_t off = (uint32_t)(r * 64 + (((2 * kb + shA) ^ swm) * 16));
                LDSM4(ah2[tm], sbAh + off);
                LDSM4(al2[tm], sbAl + off);
            }
#pragma unroll
            for (int p = 0; p < 3; p++) {
                const int r = wn2 + p * 16 + rlocB;
                const uint32_t off = (uint32_t)(r * 64 + (((2 * kb + shB) ^ swm) * 16));
                LDSM4(bh2[p], sbBh + off);
                LDSM4(bl2[p], sbBl + off);
            }
#pragma unroll
            for (int tm = 0; tm < 2; tm++)
#pragma unroll
                for (int tn = 0; tn < 5; tn++) {
                    const uint32_t* bh_ = &bh2[tn >> 1][(tn & 1) * 2];
                    const uint32_t* bl_ = &bl2[tn >> 1][(tn & 1) * 2];
                    mma_bf16(acc2[tm][tn], ah2[tm], bh_);
                    mma_bf16(acc2[tm][tn], ah2[tm], bl_);
                    mma_bf16(acc2[tm][tn], al2[tm], bh_);
                }
        }
        __syncthreads();
    }

    if ((warp >> 2) == 1 && tig == 0) {
#pragma unroll
        for (int tm = 0; tm < 2; tm++) {
            const int r = wm2 + tm * 16 + gid;
            Zs[r]     = acc2[tm][3][0];
            Zs[r + 8] = acc2[tm][3][2];
        }
    }
    __syncthreads();

#pragma unroll
    for (int tm = 0; tm < 2; tm++) {
        const int r = wm2 + tm * 16 + gid;
        const float d0 = 1.f / (Zs[r] + 1e-6f);
        const float d1 = 1.f / (Zs[r + 8] + 1e-6f);
#pragma unroll
        for (int tn = 0; tn < 5; tn++) {
            const int col = wn2 + tn * 8 + tig * 2;
            if (col < 64) {
                const size_t ro = ((size_t)b * S_LEN + c * CHUNK + r) * (NH * D_HEAD) + h * 64 + col;
                const size_t ro8 = ro + 8 * (NH * D_HEAD);
                float o0 = acc2[tm][tn][0] * d0, o1 = acc2[tm][tn][1] * d0;
                float o2 = acc2[tm][tn][2] * d1, o3 = acc2[tm][tn][3] * d1;
                __nv_bfloat16 h0 = __float2bfloat16(o0), h1 = __float2bfloat16(o1);
                __nv_bfloat16 h2 = __float2bfloat16(o2), h3 = __float2bfloat16(o3);
                *(__nv_bfloat162*)(ath + ro)  = __nv_bfloat162(h0, h1);
                *(__nv_bfloat162*)(ath + ro8) = __nv_bfloat162(h2, h3);
                *(__nv_bfloat162*)(atl + ro)  =
                    __nv_bfloat162(__float2bfloat16(o0 - __bfloat162float(h0)),
                                   __float2bfloat16(o1 - __bfloat162float(h1)));
                *(__nv_bfloat162*)(atl + ro8) =
                    __nv_bfloat162(__float2bfloat16(o2 - __bfloat162float(h2)),
                                   __float2bfloat16(o3 - __bfloat162float(h3)));
            }
        }
    }
}

// ----------------------------------- launch ---------------------------------------
extern "C" void kernel_launch(void* const* d_in, const int* in_sizes, int n_in,
                              void* d_out, int out_size)
{
    const float* hs   = (const float*)d_in[0];
    const float* cosp = (const float*)d_in[1];
    const float* sinp = (const float*)d_in[2];
    const float* Wq   = (const float*)d_in[3];
    const float* Wk   = (const float*)d_in[4];
    const float* Wv   = (const float*)d_in[5];
    const float* Wo   = (const float*)d_in[6];
    const float* proj = (const float*)d_in[7];
    float* out = (float*)d_out;

    float *qkvp, *xpkp, *sqkp, *stabp, *kvp, *kzp;
    cudaGetSymbolAddress((void**)&qkvp,  g_qkv);
    cudaGetSymbolAddress((void**)&xpkp,  g_xpk);
    cudaGetSymbolAddress((void**)&sqkp,  g_sqk);
    cudaGetSymbolAddress((void**)&stabp, g_stab);
    cudaGetSymbolAddress((void**)&kvp,   g_kv);
    cudaGetSymbolAddress((void**)&kzp,   g_kz);

    __nv_bfloat16 *pqh, *pql, *pkh, *pkl, *hsh, *hsl, *ath, *atl, *wh, *wl;
    cudaGetSymbolAddress((void**)&pqh, g_pqh);
    cudaGetSymbolAddress((void**)&pql, g_pql);
    cudaGetSymbolAddress((void**)&pkh, g_pkh);
    cudaGetSymbolAddress((void**)&pkl, g_pkl);
    cudaGetSymbolAddress((void**)&hsh, g_hsh);
    cudaGetSymbolAddress((void**)&hsl, g_hsl);
    cudaGetSymbolAddress((void**)&ath, g_ath);
    cudaGetSymbolAddress((void**)&atl, g_atl);
    cudaGetSymbolAddress((void**)&wh,  g_wh);
    cudaGetSymbolAddress((void**)&wl,  g_wl);

    cudaFuncSetAttribute(gemm_bf16x3, cudaFuncAttributeMaxDynamicSharedMemorySize, SMEM_GEMM);
    cudaFuncSetAttribute(attn_tc, cudaFuncAttributeMaxDynamicSharedMemorySize, SMEM_ATTN);

    // ---- splits ----
    split_bf16<<<(HS_ELEMS / 4 + 255) / 256, 256>>>(hs, hsh, hsl, HS_ELEMS / 4);
    split_bf16<<<(HID_ * HID_ / 4 + 255) / 256, 256>>>(Wq, wh + WQ_OFF, wl + WQ_OFF, HID_ * HID_ / 4);
    split_bf16<<<(512 * HID_ / 4 + 255) / 256, 256>>>(Wk, wh + WK_OFF, wl + WK_OFF, 512 * HID_ / 4);
    split_bf16<<<(512 * HID_ / 4 + 255) / 256, 256>>>(Wv, wh + WV_OFF, wl + WV_OFF, 512 * HID_ / 4);
    split_bf16<<<(HID_ * HID_ / 4 + 255) / 256, 256>>>(Wo, wh + WO_OFF, wl + WO_OFF, HID_ * HID_ / 4);

    // ---- fused QKV projection ----
    gemm_bf16x3<<<dim3(QKVW / 128, 32), 256, SMEM_GEMM>>>(hsh, hsl, wh, wl, qkvp, QKVW);

    // ---- favor features (RoPE fused) ----
    init_stab_kernel<<<1, 32>>>(stabp);
    favor_xp<<<dim3(S_LEN / 32, NH, B_SZ), 256>>>(qkvp, cosp, sinp, proj, nullptr, pqh, pql, nullptr, nullptr, NH, QKVW, 0);
    favor_xp<<<dim3(S_LEN / 32, NKV, B_SZ), 256>>>(qkvp, cosp, sinp, proj, xpkp, nullptr, nullptr, sqkp, stabp, NKV, QKVW, 2048);
    favor_fin<<<(B_SZ * NKV * S_LEN) / 8, 256>>>(xpkp, sqkp, stabp, pkh, pkl, B_SZ * NKV * S_LEN);

    // ---- chunked linear attention ----
    kv_chunk<<<dim3(NC, NKV, B_SZ), 256>>>(pkh, pkl, qkvp, kvp, kzp);
    cumsum_k<<<(B_SZ * NKV * (M_FEAT * D_HEAD + M_FEAT) + 255) / 256, 256>>>(kvp, kzp);
    attn_tc<<<dim3(NC, NH, B_SZ), 256, SMEM_ATTN>>>(pqh, pql, pkh, pkl, qkvp, kvp, kzp, ath, atl);

    // ---- output projection ----
    gemm_bf16x3<<<dim3(16, 32), 256, SMEM_GEMM>>>(ath, atl, wh + WO_OFF, wl + WO_OFF, out, 2048);
}

// round 12
// speedup vs baseline: 1.6254x; 1.0118x over previous
#include <cuda_runtime.h>
#include <cuda_bf16.h>
#include <math.h>
#include <stdint.h>

#define B_SZ   2
#define S_LEN  2048
#define HID_   2048
#define NH     32
#define NKV    8
#define D_HEAD 64
#define M_FEAT 256
#define NC     16
#define CHUNK  128
#define QKVW   3072

// ---------------- scratch (device globals; no allocations allowed) ----------------
__device__ float g_qkv [(size_t)B_SZ * S_LEN * QKVW];
__device__ float g_xpk [(size_t)B_SZ * NKV * S_LEN * M_FEAT];
__device__ float g_sqk [B_SZ * NKV * S_LEN];
__device__ float g_stab[B_SZ * NKV];
__device__ float g_kv  [B_SZ * NKV * NC * M_FEAT * D_HEAD];
__device__ float g_kz  [B_SZ * NKV * NC * M_FEAT];

#define PHIQ_E ((size_t)B_SZ * NH  * S_LEN * M_FEAT)
#define PHIK_E ((size_t)B_SZ * NKV * S_LEN * M_FEAT)
#define HS_ELEMS  (B_SZ * S_LEN * HID_)
#define W_ELEMS   (QKVW * HID_ + HID_ * HID_)
__device__ __align__(16) __nv_bfloat16 g_pqh[PHIQ_E];
__device__ __align__(16) __nv_bfloat16 g_pql[PHIQ_E];
__device__ __align__(16) __nv_bfloat16 g_pkh[PHIK_E];
__device__ __align__(16) __nv_bfloat16 g_pkl[PHIK_E];
__device__ __align__(16) __nv_bfloat16 g_hsh[HS_ELEMS];
__device__ __align__(16) __nv_bfloat16 g_hsl[HS_ELEMS];
__device__ __align__(16) __nv_bfloat16 g_ath[HS_ELEMS];
__device__ __align__(16) __nv_bfloat16 g_atl[HS_ELEMS];
__device__ __align__(16) __nv_bfloat16 g_wh [W_ELEMS];
__device__ __align__(16) __nv_bfloat16 g_wl [W_ELEMS];

#define WQ_OFF 0
#define WK_OFF (HID_ * HID_)
#define WV_OFF (WK_OFF + 512 * HID_)
#define WO_OFF (WV_OFF + 512 * HID_)

// =================== fp32 -> bf16 hi/lo split (elementwise, x4 vec) ================
__global__ void split_bf16(const float* __restrict__ x, __nv_bfloat16* __restrict__ h,
                           __nv_bfloat16* __restrict__ l, int n4)
{
    int i = blockIdx.x * blockDim.x + threadIdx.x;
    if (i >= n4) return;
    float4 v = ((const float4*)x)[i];
    __nv_bfloat16 h0 = __float2bfloat16(v.x), h1 = __float2bfloat16(v.y);
    __nv_bfloat16 h2 = __float2bfloat16(v.z), h3 = __float2bfloat16(v.w);
    __nv_bfloat162* hp = (__nv_bfloat162*)h;
    hp[2 * i]     = __nv_bfloat162(h0, h1);
    hp[2 * i + 1] = __nv_bfloat162(h2, h3);
    __nv_bfloat162* lp = (__nv_bfloat162*)l;
    lp[2 * i]     = __nv_bfloat162(__float2bfloat16(v.x - __bfloat162float(h0)),
                                   __float2bfloat16(v.y - __bfloat162float(h1)));
    lp[2 * i + 1] = __nv_bfloat162(__float2bfloat16(v.z - __bfloat162float(h2)),
                                   __float2bfloat16(v.w - __bfloat162float(h3)));
}

// ===================== shared helpers for tensor-core kernels ======================
__device__ __forceinline__ uint32_t smem_u32g(const void* p)
{
    uint32_t a;
    asm("{ .reg .u64 t; cvta.to.shared.u64 t, %1; cvt.u32.u64 %0, t; }" : "=r"(a) : "l"(p));
    return a;
}

#define LDSM4(r, a) \
    asm volatile("ldmatrix.sync.aligned.m8n8.x4.shared.b16 {%0,%1,%2,%3}, [%4];" \
                 : "=r"((r)[0]), "=r"((r)[1]), "=r"((r)[2]), "=r"((r)[3]) : "r"(a))

#define CP_ASYNC16(dst, src) \
    asm volatile("cp.async.cg.shared.global [%0], [%1], 16;" :: "r"(dst), "l"(src) : "memory")
#define CP_COMMIT() asm volatile("cp.async.commit_group;" ::: "memory")
#define CP_WAIT(n)  asm volatile("cp.async.wait_group %0;" :: "n"(n) : "memory")

__device__ __forceinline__ void mma_bf16(float c[4], const uint32_t a[4], const uint32_t b[2])
{
    asm volatile("mma.sync.aligned.m16n8k16.row.col.f32.bf16.bf16.f32 "
                 "{%0,%1,%2,%3}, {%4,%5,%6,%7}, {%8,%9}, {%0,%1,%2,%3};"
                 : "+f"(c[0]), "+f"(c[1]), "+f"(c[2]), "+f"(c[3])
                 : "r"(a[0]), "r"(a[1]), "r"(a[2]), "r"(a[3]), "r"(b[0]), "r"(b[1]));
}

// cheap hi/lo split: hi = bf16-truncate (PRMT), lo = RN(residual) via one bf16x2 cvt
__device__ __forceinline__ void pack8(const float* f, uint4& hv, uint4& lv)
{
    uint32_t hw[4], lw[4];
#pragma unroll
    for (int e = 0; e < 4; e++) {
        const uint32_t u0 = __float_as_uint(f[2 * e]);
        const uint32_t u1 = __float_as_uint(f[2 * e + 1]);
        hw[e] = __byte_perm(u0, u1, 0x7632);            // {hi16(u0), hi16(u1)}
        const float t0 = __uint_as_float(u0 & 0xFFFF0000u);
        const float t1 = __uint_as_float(u1 & 0xFFFF0000u);
        const float r0 = f[2 * e] - t0;
        const float r1 = f[2 * e + 1] - t1;
        asm("cvt.rn.bf16x2.f32 %0, %1, %2;" : "=r"(lw[e]) : "f"(r1), "f"(r0));
    }
    hv = make_uint4(hw[0], hw[1], hw[2], hw[3]);
    lv = make_uint4(lw[0], lw[1], lw[2], lw[3]);
}

// ======== bf16 3-pass split GEMM: 128x128 tile, cp.async, ldmatrix =================
#define GK 2048
#define BK 32
#define NKT (GK / BK)
#define GBUF 32768
#define SMEM_GEMM (2 * GBUF)

__global__ __launch_bounds__(256, 2) void gemm_bf16x3(const __nv_bfloat16* __restrict__ Ah,
                                                      const __nv_bfloat16* __restrict__ Al,
                                                      const __nv_bfloat16* __restrict__ Bh,
                                                      const __nv_bfloat16* __restrict__ Bl,
                                                      float* __restrict__ C, int N)
{
    extern __shared__ char smc[];
    const uint32_t sb = smem_u32g(smc);
    const int tid  = threadIdx.x;
    const int warp = tid >> 5, lane = tid & 31;
    const int gid  = lane >> 2, tig = lane & 3;
    const int wm   = (warp & 1) * 64;
    const int wn   = (warp >> 1) * 32;
    const int rowA = blockIdx.y * 128;
    const int rowB = blockIdx.x * 128;

    const int r0s = tid >> 2,         s0s = tid & 3;
    const int r1s = (tid + 256) >> 2, s1s = tid & 3;
    const uint32_t so0 = (uint32_t)(r0s * 64 + ((s0s ^ ((r0s >> 1) & 3)) * 16));
    const uint32_t so1 = (uint32_t)(r1s * 64 + ((s1s ^ ((r1s >> 1) & 3)) * 16));

    const int swm   = ((lane & 7) >> 1) & 3;
    const int rlocA = (lane & 7) + (((lane >> 3) & 1) << 3);
    const int shA   = lane >> 4;
    const int rlocB = (lane & 7) + ((lane >> 4) << 3);
    const int shB   = (lane >> 3) & 1;

    float acc[4][4][4];
#pragma unroll
    for (int i = 0; i < 4; i++)
#pragma unroll
        for (int j = 0; j < 4; j++)
#pragma unroll
            for (int r = 0; r < 4; r++) acc[i][j][r] = 0.f;

    auto stage = [&](int kt, int b) {
        const uint32_t bb = sb + b * GBUF;
        const int kb = kt * BK;
        CP_ASYNC16(bb + so0,         (const char*)(Ah + (size_t)(rowA + r0s) * GK + kb + s0s * 8));
        CP_ASYNC16(bb + so1,         (const char*)(Ah + (size_t)(rowA + r1s) * GK + kb + s1s * 8));
        CP_ASYNC16(bb + 8192  + so0, (const char*)(Al + (size_t)(rowA + r0s) * GK + kb + s0s * 8));
        CP_ASYNC16(bb + 8192  + so1, (const char*)(Al + (size_t)(rowA + r1s) * GK + kb + s1s * 8));
        CP_ASYNC16(bb + 16384 + so0, (const char*)(Bh + (size_t)(rowB + r0s) * GK + kb + s0s * 8));
        CP_ASYNC16(bb + 16384 + so1, (const char*)(Bh + (size_t)(rowB + r1s) * GK + kb + s1s * 8));
        CP_ASYNC16(bb + 24576 + so0, (const char*)(Bl + (size_t)(rowB + r0s) * GK + kb + s0s * 8));
        CP_ASYNC16(bb + 24576 + so1, (const char*)(Bl + (size_t)(rowB + r1s) * GK + kb + s1s * 8));
        CP_COMMIT();
    };

    stage(0, 0);

    for (int kt = 0; kt < NKT; kt++) {
        if (kt + 1 < NKT) {
            stage(kt + 1, (kt + 1) & 1);
            CP_WAIT(1);
        } else {
            CP_WAIT(0);
        }
        __syncthreads();

        const uint32_t base = sb + (kt & 1) * GBUF;
#pragma unroll
        for (int kb = 0; kb < 2; kb++) {
            uint32_t ah[4][4], al[4][4];
#pragma unroll
            for (int tm = 0; tm < 4; tm++) {
                const int r = wm + tm * 16 + rlocA;
                const uint32_t off = (uint32_t)(r * 64 + (((2 * kb + shA) ^ swm) * 16));
                LDSM4(ah[tm], base + off);
                LDSM4(al[tm], base + 8192 + off);
            }
            uint32_t bhf[2][4], blf[2][4];
#pragma unroll
            for (int p = 0; p < 2; p++) {
                const int r = wn + p * 16 + rlocB;
                const uint32_t off = (uint32_t)(r * 64 + (((2 * kb + shB) ^ swm) * 16));
                LDSM4(bhf[p], base + 16384 + off);
                LDSM4(blf[p], base + 24576 + off);
            }
#pragma unroll
            for (int tm = 0; tm < 4; tm++)
#pragma unroll
                for (int tn = 0; tn < 4; tn++) {
                    const uint32_t* bh2 = &bhf[tn >> 1][(tn & 1) * 2];
                    const uint32_t* bl2 = &blf[tn >> 1][(tn & 1) * 2];
                    mma_bf16(acc[tm][tn], ah[tm], bh2);
                    mma_bf16(acc[tm][tn], ah[tm], bl2);
                    mma_bf16(acc[tm][tn], al[tm], bh2);
                }
        }
        __syncthreads();
    }

#pragma unroll
    for (int tm = 0; tm < 4; tm++) {
        const size_t r0 = (size_t)rowA + wm + tm * 16 + gid;
#pragma unroll
        for (int tn = 0; tn < 4; tn++) {
            const int cn = rowB + wn + tn * 8 + tig * 2;
            *(float2*)(C + r0 * N + cn)       = make_float2(acc[tm][tn][0], acc[tm][tn][1]);
            *(float2*)(C + (r0 + 8) * N + cn) = make_float2(acc[tm][tn][2], acc[tm][tn][3]);
        }
    }
}

__device__ void atomicMaxFloat(float* addr, float val)
{
    int* ia = (int*)addr;
    int old = *ia;
    while (__int_as_float(old) < val) {
        int assumed = old;
        old = atomicCAS(ia, assumed, __float_as_int(val));
        if (old == assumed) break;
    }
}

__global__ void init_stab_kernel(float* stab)
{
    if (threadIdx.x < B_SZ * NKV) stab[threadIdx.x] = -3.4e38f;
}

// ---------------- merged favor xp (q + k heads in one launch, RoPE fused) ----------
// blockIdx.y < NH: q head -> fused exp, bf16 hi/lo phi out.
// blockIdx.y >= NH: k head (h-NH) -> fp32 xp + sq + atomic head max.
__global__ __launch_bounds__(256) void favor_xp(const float* __restrict__ x,
                                                const float* __restrict__ cosp,
                                                const float* __restrict__ sinp,
                                                const float* __restrict__ proj,
                                                float* __restrict__ xpk,
                                                __nv_bfloat16* __restrict__ pqh,
                                                __nv_bfloat16* __restrict__ pql,
                                                float* __restrict__ sqk,
                                                float* __restrict__ stab)
{
    __shared__ float As[32 * 68];
    __shared__ float Bs[16][256];
    __shared__ float red[256];
    __shared__ float sqsh[32];
    const float DN = 0.35355339059327373f;
    const int s0 = blockIdx.x * 32, b = blockIdx.z;
    const int hy = blockIdx.y;
    const bool isq = (hy < NH);
    const int h = isq ? hy : hy - NH;
    const int xcol = isq ? (h * 64) : (2048 + h * 64);
    const int tid = threadIdx.x;

#pragma unroll
    for (int r = 0; r < 2; r++) {
        int l = tid + r * 256;
        int tok = l >> 4, q4 = (l & 15) << 2;
        float4 vv = *(const float4*)(x + (size_t)(b * S_LEN + s0 + tok) * QKVW + xcol + q4);
        As[tok * 68 + q4 + 0] = vv.x * DN;
        As[tok * 68 + q4 + 1] = vv.y * DN;
        As[tok * 68 + q4 + 2] = vv.z * DN;
        As[tok * 68 + q4 + 3] = vv.w * DN;
    }
    __syncthreads();

    // fused RoPE
#pragma unroll
    for (int r = 0; r < 4; r++) {
        int idx = tid + r * 256;
        int tok = idx >> 5, p = idx & 31;
        const size_t crow = (size_t)(b * S_LEN + s0 + tok) * 64;
        const float c1 = cosp[crow + p],      sn1 = sinp[crow + p];
        const float c2 = cosp[crow + 32 + p], sn2 = sinp[crow + 32 + p];
        float a  = As[tok * 68 + p];
        float b2 = As[tok * 68 + p + 32];
        As[tok * 68 + p]      = a * c1 - b2 * sn1;
        As[tok * 68 + p + 32] = b2 * c2 + a * sn2;
    }
    __syncthreads();

    if (tid < 32) {
        float ssum = 0.f;
#pragma unroll
        for (int d = 0; d < 64; d++) { float vv = As[tid * 68 + d]; ssum += vv * vv; }
        sqsh[tid] = 0.5f * ssum;
        if (!isq) sqk[((size_t)(b * NKV + h)) * S_LEN + s0 + tid] = 0.5f * ssum;
    }

    const int tg = tid >> 5, mg = tid & 31;
    float acc[4][8];
#pragma unroll
    for (int i = 0; i < 4; i++)
#pragma unroll
        for (int j = 0; j < 8; j++) acc[i][j] = 0.f;

    for (int k0 = 0; k0 < 64; k0 += 16) {
#pragma unroll
        for (int j = 0; j < 4; j++) {
            float4 p = *(const float4*)(proj + tid * 64 + k0 + j * 4);
            Bs[j * 4 + 0][tid] = p.x; Bs[j * 4 + 1][tid] = p.y;
            Bs[j * 4 + 2][tid] = p.z; Bs[j * 4 + 3][tid] = p.w;
        }
        __syncthreads();
#pragma unroll
        for (int kk = 0; kk < 16; kk++) {
            float a[4];
#pragma unroll
            for (int i = 0; i < 4; i++) a[i] = As[(tg * 4 + i) * 68 + k0 + kk];
            float bb[8];
            *(float4*)&bb[0] = *(const float4*)&Bs[kk][mg * 8];
            *(float4*)&bb[4] = *(const float4*)&Bs[kk][mg * 8 + 4];
#pragma unroll
            for (int i = 0; i < 4; i++)
#pragma unroll
                for (int j = 0; j < 8; j++) acc[i][j] += a[i] * bb[j];
        }
        __syncthreads();
    }

    if (isq) {
        const size_t rowbase = (size_t)(b * NH + h) * S_LEN + s0;
#pragma unroll
        for (int i = 0; i < 4; i++) {
            float m = acc[i][0];
#pragma unroll
            for (int j = 1; j < 8; j++) m = fmaxf(m, acc[i][j]);
#pragma unroll
            for (int o = 16; o > 0; o >>= 1) m = fmaxf(m, __shfl_xor_sync(0xffffffffu, m, o));
            const float sv = sqsh[tg * 4 + i];
#pragma unroll
            for (int j = 0; j < 8; j++)
                acc[i][j] = (__expf(acc[i][j] - sv - m) + 1e-6f) * 0.0625f;
            uint4 hv, lv;
            pack8(acc[i], hv, lv);
            *(uint4*)(pqh + (rowbase + tg * 4 + i) * M_FEAT + mg * 8) = hv;
            *(uint4*)(pql + (rowbase + tg * 4 + i) * M_FEAT + mg * 8) = lv;
        }
    } else {
        const size_t rowbase = (size_t)(b * NKV + h) * S_LEN + s0;
        float mx = -3.4e38f;
#pragma unroll
        for (int i = 0; i < 4; i++) {
            *(float4*)(xpk + (rowbase + tg * 4 + i) * M_FEAT + mg * 8) =
                make_float4(acc[i][0], acc[i][1], acc[i][2], acc[i][3]);
            *(float4*)(xpk + (rowbase + tg * 4 + i) * M_FEAT + mg * 8 + 4) =
                make_float4(acc[i][4], acc[i][5], acc[i][6], acc[i][7]);
#pragma unroll
            for (int j = 0; j < 8; j++) mx = fmaxf(mx, acc[i][j]);
        }
        red[tid] = mx;
        __syncthreads();
        for (int st = 128; st > 0; st >>= 1) {
            if (tid < st) red[tid] = fmaxf(red[tid], red[tid + st]);
            __syncthreads();
        }
        if (tid == 0) atomicMaxFloat(&stab[b * NKV + h], red[0]);
    }
}

// ------- per-chunk kv/kz with fused k-exp + phi_k hi/lo output. grid (NC,NKV,B) -----
__global__ __launch_bounds__(256) void kv_chunk(const float* __restrict__ xpk,
                                                const float* __restrict__ sqk,
                                                const float* __restrict__ stab,
                                                __nv_bfloat16* __restrict__ pkh,
                                                __nv_bfloat16* __restrict__ pkl,
                                                const float* __restrict__ qkv,
                                                float* __restrict__ kv,
                                                float* __restrict__ kz)
{
    __shared__ float ps[16][256];
    __shared__ float vs[16][64];
    const int c = blockIdx.x, h = blockIdx.y, b = blockIdx.z;
    const int tid = threadIdx.x;
    const float stabv = stab[b * NKV + h];
    float acc[64];
#pragma unroll
    for (int d = 0; d < 64; d++) acc[d] = 0.f;
    float accz = 0.f;
    const size_t prow = (size_t)(b * NKV + h) * S_LEN + c * CHUNK;
    const size_t vrow = (size_t)b * S_LEN + c * CHUNK;

    for (int i0 = 0; i0 < CHUNK; i0 += 16) {
#pragma unroll
        for (int ii = 0; ii < 16; ii++) {
            const size_t idx = (prow + i0 + ii) * M_FEAT + tid;
            const float sqv = sqk[prow + i0 + ii];
            const float v = (__expf(xpk[idx] - sqv - stabv) + 1e-6f) * 0.0625f;
            ps[ii][tid] = v;
            const uint32_t u = __float_as_uint(v);
            const float t = __uint_as_float(u & 0xFFFF0000u);
            pkh[idx] = __ushort_as_bfloat16((unsigned short)(u >> 16));
            pkl[idx] = __float2bfloat16(v - t);
        }
#pragma unroll
        for (int j = 0; j < 4; j++) {
            int l = tid + j * 256;
            int ii = l >> 6, d = l & 63;
            vs[ii][d] = qkv[(vrow + i0 + ii) * QKVW + 2560 + h * 64 + d];
        }
        __syncthreads();
#pragma unroll
        for (int ii = 0; ii < 16; ii++) {
            float a = ps[ii][tid];
            accz += a;
#pragma unroll
            for (int d4 = 0; d4 < 64; d4 += 4) {
                float4 vv = *(const float4*)&vs[ii][d4];
                acc[d4 + 0] += a * vv.x; acc[d4 + 1] += a * vv.y;
                acc[d4 + 2] += a * vv.z; acc[d4 + 3] += a * vv.w;
            }
        }
        __syncthreads();
    }
    const size_t ob = (((size_t)(b * NKV + h) * NC + c) * M_FEAT + tid) * D_HEAD;
#pragma unroll
    for (int d4 = 0; d4 < 64; d4 += 4)
        *(float4*)(kv + ob + d4) = make_float4(acc[d4], acc[d4 + 1], acc[d4 + 2], acc[d4 + 3]);
    kz[((size_t)(b * NKV + h) * NC + c) * M_FEAT + tid] = accz;
}

// ---------------- exclusive prefix over chunk axis, in place ----------------------
__global__ void cumsum_k(float* __restrict__ kv, float* __restrict__ kz)
{
    const int tid = blockIdx.x * blockDim.x + threadIdx.x;
    const int KVSZ = M_FEAT * D_HEAD;
    if (tid < B_SZ * NKV * KVSZ) {
        int bh = tid / KVSZ, md = tid % KVSZ;
        float run = 0.f;
        for (int c = 0; c < NC; c++) {
            size_t idx = ((size_t)bh * NC + c) * KVSZ + md;
            float t = kv[idx]; kv[idx] = run; run += t;
        }
    } else {
        int t2 = tid - B_SZ * NKV * KVSZ;
        if (t2 < B_SZ * NKV * M_FEAT) {
            int bh = t2 / M_FEAT, m = t2 % M_FEAT;
            float run = 0.f;
            for (int c = 0; c < NC; c++) {
                size_t idx = ((size_t)bh * NC + c) * M_FEAT + m;
                float tz = kz[idx]; kz[idx] = run; run += tz;
            }
        }
    }
}

// ============ tensor-core chunked causal linear attention. grid (NC, NH, B) ========
#define SPITCH 132
#define SMEM_ATTN (128 * SPITCH * 4 + 4 * 8192 + 512)

__global__ __launch_bounds__(256, 1) void attn_tc(
    const __nv_bfloat16* __restrict__ pqh, const __nv_bfloat16* __restrict__ pql,
    const __nv_bfloat16* __restrict__ pkh, const __nv_bfloat16* __restrict__ pkl,
    const float* __restrict__ qkv, const float* __restrict__ kvpre,
    const float* __restrict__ kzpre,
    __nv_bfloat16* __restrict__ ath, __nv_bfloat16* __restrict__ atl)
{
    extern __shared__ float sm[];
    float* Ss = sm;
    char* Ah = (char*)(sm + 128 * SPITCH);
    char* Al = Ah + 8192;
    char* Bh = Al + 8192;
    char* Bl = Bh + 8192;
    float* Zs = (float*)(Bl + 8192);

    const uint32_t sbAh = smem_u32g(Ah), sbAl = smem_u32g(Al);
    const uint32_t sbBh = smem_u32g(Bh), sbBl = smem_u32g(Bl);

    const int c = blockIdx.x, h = blockIdx.y, b = blockIdx.z;
    const int kvh = h >> 2;
    const int tid = threadIdx.x;
    const int warp = tid >> 5, lane = tid & 31;
    const int gid = lane >> 2, tig = lane & 3;

    const size_t qbase  = (size_t)(b * NH + h) * S_LEN + c * CHUNK;
    const size_t kbase  = (size_t)(b * NKV + kvh) * S_LEN + c * CHUNK;
    const size_t vrow0  = (size_t)b * S_LEN + c * CHUNK;
    const size_t kvbase = ((size_t)(b * NKV + kvh) * NC + c) * (size_t)(M_FEAT * D_HEAD);
    const size_t kzbase = ((size_t)(b * NKV + kvh) * NC + c) * M_FEAT;

    const int strow = tid & 127;
    const int s0 = tid >> 7;

    const int swm   = ((lane & 7) >> 1) & 3;
    const int rlocA = (lane & 7) + (((lane >> 3) & 1) << 3);
    const int shA   = lane >> 4;
    const int rlocB = (lane & 7) + ((lane >> 4) << 3);
    const int shB   = (lane >> 3) & 1;

    // ======================= Phase 1: scores =======================
    {
        const int wm = (warp & 1) * 64, wn = (warp >> 1) * 32;
        float acc[4][4][4];
#pragma unroll
        for (int i = 0; i < 4; i++)
#pragma unroll
            for (int j = 0; j < 4; j++)
#pragma unroll
                for (int r = 0; r < 4; r++) acc[i][j][r] = 0.f;

        for (int m0 = 0; m0 < M_FEAT; m0 += 32) {
#pragma unroll
            for (int si = 0; si < 2; si++) {
                const int s = s0 + si * 2;
                const uint32_t off = (uint32_t)(strow * 64 + ((s ^ ((strow >> 1) & 3)) * 16));
                const size_t ia = (qbase + strow) * M_FEAT + m0 + s * 8;
                *(uint4*)(Ah + off) = *(const uint4*)(pqh + ia);
                *(uint4*)(Al + off) = *(const uint4*)(pql + ia);
                const size_t ib = (kbase + strow) * M_FEAT + m0 + s * 8;
                *(uint4*)(Bh + off) = *(const uint4*)(pkh + ib);
                *(uint4*)(Bl + off) = *(const uint4*)(pkl + ib);
            }
            __syncthreads();
#pragma unroll
            for (int kb = 0; kb < 2; kb++) {
                uint32_t ah[4][4], al[4][4];
#pragma unroll
                for (int tm = 0; tm < 4; tm++) {
                    const int r = wm + tm * 16 + rlocA;
                    const uint32_t off = (uint32_t)(r * 64 + (((2 * kb + shA) ^ swm) * 16));
                    LDSM4(ah[tm], sbAh + off);
                    LDSM4(al[tm], sbAl + off);
                }
                uint32_t bhf[2][4], blf[2][4];
#pragma unroll
                for (int p = 0; p < 2; p++) {
                    const int r = wn + p * 16 + rlocB;
                    const uint32_t off = (uint32_t)(r * 64 + (((2 * kb + shB) ^ swm) * 16));
                    LDSM4(bhf[p], sbBh + off);
                    LDSM4(blf[p], sbBl + off);
                }
#pragma unroll
                for (int tm = 0; tm < 4; tm++)
#pragma unroll
                    for (int tn = 0; tn < 4; tn++) {
                        const uint32_t* bh2 = &bhf[tn >> 1][(tn & 1) * 2];
                        const uint32_t* bl2 = &blf[tn >> 1][(tn & 1) * 2];
                        mma_bf16(acc[tm][tn], ah[tm], bh2);
                        mma_bf16(acc[tm][tn], ah[tm], bl2);
                        mma_bf16(acc[tm][tn], al[tm], bh2);
                    }
            }
            __syncthreads();
        }
#pragma unroll
        for (int tm = 0; tm < 4; tm++) {
            const int r0 = wm + tm * 16 + gid;
            const int r1 = r0 + 8;
#pragma unroll
            for (int tn = 0; tn < 4; tn++) {
                const int col = wn + tn * 8 + tig * 2;
                Ss[r0 * SPITCH + col]     = (col     <= r0) ? acc[tm][tn][0] : 0.f;
                Ss[r0 * SPITCH + col + 1] = (col + 1 <= r0) ? acc[tm][tn][1] : 0.f;
                Ss[r1 * SPITCH + col]     = (col     <= r1) ? acc[tm][tn][2] : 0.f;
                Ss[r1 * SPITCH + col + 1] = (col + 1 <= r1) ? acc[tm][tn][3] : 0.f;
            }
        }
    }
    __syncthreads();

    // ======================= Phase 2: inter+intra (+z col 64) =======================
    const int wm2 = (warp & 3) * 32, wn2 = (warp >> 2) * 40;
    float acc2[2][5][4];
#pragma unroll
    for (int i = 0; i < 2; i++)
#pragma unroll
        for (int j = 0; j < 5; j++)
#pragma unroll
            for (int r = 0; r < 4; r++) acc2[i][j][r] = 0.f;

    for (int cc = 0; cc < 12; cc++) {
#pragma unroll
        for (int si = 0; si < 2; si++) {
            const int s = s0 + si * 2;
            const uint32_t off = (uint32_t)(strow * 64 + ((s ^ ((strow >> 1) & 3)) * 16));
            if (cc < 8) {
                const size_t ia = (qbase + strow) * M_FEAT + cc * 32 + s * 8;
                *(uint4*)(Ah + off) = *(const uint4*)(pqh + ia);
                *(uint4*)(Al + off) = *(const uint4*)(pql + ia);
            } else {
                float f[8];
                const float* pa = Ss + strow * SPITCH + (cc - 8) * 32 + s * 8;
                *(float4*)&f[0] = *(const float4*)pa;
                *(float4*)&f[4] = *(const float4*)(pa + 4);
                uint4 hv, lv;
                pack8(f, hv, lv);
                *(uint4*)(Ah + off) = hv;
                *(uint4*)(Al + off) = lv;
            }

            if (strow < 96) {
                float g[8];
                if (strow < 64) {
                    if (cc < 8) {
#pragma unroll
                        for (int e = 0; e < 8; e++)
                            g[e] = kvpre[kvbase + (size_t)(cc * 32 + s * 8 + e) * 64 + strow];
                    } else {
#pragma unroll
                        for (int e = 0; e < 8; e++)
                            g[e] = qkv[(vrow0 + (cc - 8) * 32 + s * 8 + e) * QKVW + 2560 + kvh * 64 + strow];
                    }
                } else if (strow == 64) {
                    if (cc < 8) {
#pragma unroll
                        for (int e = 0; e < 8; e++)
                            g[e] = kzpre[kzbase + cc * 32 + s * 8 + e];
                    } else {
#pragma unroll
                        for (int e = 0; e < 8; e++) g[e] = 1.f;
                    }
                } else {
#pragma unroll
                    for (int e = 0; e < 8; e++) g[e] = 0.f;
                }
                uint4 hv, lv;
                pack8(g, hv, lv);
                *(uint4*)(Bh + off) = hv;
                *(uint4*)(Bl + off) = lv;
            }
        }
        __syncthreads();
#pragma unroll
        for (int kb = 0; kb < 2; kb++) {
            uint32_t ah2[2][4], al2[2][4], bh2[3][4], bl2[3][4];
#pragma unroll
            for (int tm = 0; tm < 2; tm++) {
                const int r = wm2 + tm * 16 + rlocA;
                const uint32_t off = (uint32_t)(r * 64 + (((2 * kb + shA) ^ swm) * 16));
                LDSM4(ah2[tm], sbAh + off);
                LDSM4(al2[tm], sbAl + off);
            }
#pragma unroll
            for (int p = 0; p < 3; p++) {
                const int r = wn2 + p * 16 + rlocB;
                const uint32_t off = (uint32_t)(r * 64 + (((2 * kb + shB) ^ swm) * 16));
                LDSM4(bh2[p], sbBh + off);
                LDSM4(bl2[p], sbBl + off);
            }
#pragma unroll
            for (int tm = 0; tm < 2; tm++)
#pragma unroll
                for (int tn = 0; tn < 5; tn++) {
                    const uint32_t* bh_ = &bh2[tn >> 1][(tn & 1) * 2];
                    const uint32_t* bl_ = &bl2[tn >> 1][(tn & 1) * 2];
                    mma_bf16(acc2[tm][tn], ah2[tm], bh_);
                    mma_bf16(acc2[tm][tn], ah2[tm], bl_);
                    mma_bf16(acc2[tm][tn], al2[tm], bh_);
                }
        }
        __syncthreads();
    }

    if ((warp >> 2) == 1 && tig == 0) {
#pragma unroll
        for (int tm = 0; tm < 2; tm++) {
            const int r = wm2 + tm * 16 + gid;
            Zs[r]     = acc2[tm][3][0];
            Zs[r + 8] = acc2[tm][3][2];
        }
    }
    __syncthreads();

#pragma unroll
    for (int tm = 0; tm < 2; tm++) {
        const int r = wm2 + tm * 16 + gid;
        const float d0 = 1.f / (Zs[r] + 1e-6f);
        const float d1 = 1.f / (Zs[r + 8] + 1e-6f);
#pragma unroll
        for (int tn = 0; tn < 5; tn++) {
            const int col = wn2 + tn * 8 + tig * 2;
            if (col < 64) {
                const size_t ro = ((size_t)b * S_LEN + c * CHUNK + r) * (NH * D_HEAD) + h * 64 + col;
                const size_t ro8 = ro + 8 * (NH * D_HEAD);
                float o0 = acc2[tm][tn][0] * d0, o1 = acc2[tm][tn][1] * d0;
                float o2 = acc2[tm][tn][2] * d1, o3 = acc2[tm][tn][3] * d1;
                __nv_bfloat16 h0 = __float2bfloat16(o0), h1 = __float2bfloat16(o1);
                __nv_bfloat16 h2 = __float2bfloat16(o2), h3 = __float2bfloat16(o3);
                *(__nv_bfloat162*)(ath + ro)  = __nv_bfloat162(h0, h1);
                *(__nv_bfloat162*)(ath + ro8) = __nv_bfloat162(h2, h3);
                *(__nv_bfloat162*)(atl + ro)  =
                    __nv_bfloat162(__float2bfloat16(o0 - __bfloat162float(h0)),
                                   __float2bfloat16(o1 - __bfloat162float(h1)));
                *(__nv_bfloat162*)(atl + ro8) =
                    __nv_bfloat162(__float2bfloat16(o2 - __bfloat162float(h2)),
                                   __float2bfloat16(o3 - __bfloat162float(h3)));
            }
        }
    }
}

// ----------------------------------- launch ---------------------------------------
extern "C" void kernel_launch(void* const* d_in, const int* in_sizes, int n_in,
                              void* d_out, int out_size)
{
    const float* hs   = (const float*)d_in[0];
    const float* cosp = (const float*)d_in[1];
    const float* sinp = (const float*)d_in[2];
    const float* Wq   = (const float*)d_in[3];
    const float* Wk   = (const float*)d_in[4];
    const float* Wv   = (const float*)d_in[5];
    const float* Wo   = (const float*)d_in[6];
    const float* proj = (const float*)d_in[7];
    float* out = (float*)d_out;

    float *qkvp, *xpkp, *sqkp, *stabp, *kvp, *kzp;
    cudaGetSymbolAddress((void**)&qkvp,  g_qkv);
    cudaGetSymbolAddress((void**)&xpkp,  g_xpk);
    cudaGetSymbolAddress((void**)&sqkp,  g_sqk);
    cudaGetSymbolAddress((void**)&stabp, g_stab);
    cudaGetSymbolAddress((void**)&kvp,   g_kv);
    cudaGetSymbolAddress((void**)&kzp,   g_kz);

    __nv_bfloat16 *pqh, *pql, *pkh, *pkl, *hsh, *hsl, *ath, *atl, *wh, *wl;
    cudaGetSymbolAddress((void**)&pqh, g_pqh);
    cudaGetSymbolAddress((void**)&pql, g_pql);
    cudaGetSymbolAddress((void**)&pkh, g_pkh);
    cudaGetSymbolAddress((void**)&pkl, g_pkl);
    cudaGetSymbolAddress((void**)&hsh, g_hsh);
    cudaGetSymbolAddress((void**)&hsl, g_hsl);
    cudaGetSymbolAddress((void**)&ath, g_ath);
    cudaGetSymbolAddress((void**)&atl, g_atl);
    cudaGetSymbolAddress((void**)&wh,  g_wh);
    cudaGetSymbolAddress((void**)&wl,  g_wl);

    cudaFuncSetAttribute(gemm_bf16x3, cudaFuncAttributeMaxDynamicSharedMemorySize, SMEM_GEMM);
    cudaFuncSetAttribute(attn_tc, cudaFuncAttributeMaxDynamicSharedMemorySize, SMEM_ATTN);

    // ---- splits ----
    split_bf16<<<(HS_ELEMS / 4 + 255) / 256, 256>>>(hs, hsh, hsl, HS_ELEMS / 4);
    split_bf16<<<(HID_ * HID_ / 4 + 255) / 256, 256>>>(Wq, wh + WQ_OFF, wl + WQ_OFF, HID_ * HID_ / 4);
    split_bf16<<<(512 * HID_ / 4 + 255) / 256, 256>>>(Wk, wh + WK_OFF, wl + WK_OFF, 512 * HID_ / 4);
    split_bf16<<<(512 * HID_ / 4 + 255) / 256, 256>>>(Wv, wh + WV_OFF, wl + WV_OFF, 512 * HID_ / 4);
    split_bf16<<<(HID_ * HID_ / 4 + 255) / 256, 256>>>(Wo, wh + WO_OFF, wl + WO_OFF, HID_ * HID_ / 4);

    // ---- fused QKV projection ----
    gemm_bf16x3<<<dim3(QKVW / 128, 32), 256, SMEM_GEMM>>>(hsh, hsl, wh, wl, qkvp, QKVW);

    // ---- favor features (q+k merged, RoPE fused) ----
    init_stab_kernel<<<1, 32>>>(stabp);
    favor_xp<<<dim3(S_LEN / 32, NH + NKV, B_SZ), 256>>>(qkvp, cosp, sinp, proj,
                                                        xpkp, pqh, pql, sqkp, stabp);

    // ---- chunked linear attention (k-exp fused into kv_chunk) ----
    kv_chunk<<<dim3(NC, NKV, B_SZ), 256>>>(xpkp, sqkp, stabp, pkh, pkl, qkvp, kvp, kzp);
    cumsum_k<<<(B_SZ * NKV * (M_FEAT * D_HEAD + M_FEAT) + 255) / 256, 256>>>(kvp, kzp);
    attn_tc<<<dim3(NC, NH, B_SZ), 256, SMEM_ATTN>>>(pqh, pql, pkh, pkl, qkvp, kvp, kzp, ath, atl);

    // ---- output projection ----
    gemm_bf16x3<<<dim3(16, 32), 256, SMEM_GEMM>>>(ath, atl, wh + WO_OFF, wl + WO_OFF, out, 2048);
}

// round 14
// speedup vs baseline: 1.8129x; 1.1153x over previous
#include <cuda_runtime.h>
#include <cuda_bf16.h>
#include <math.h>
#include <stdint.h>

#define B_SZ   2
#define S_LEN  2048
#define HID_   2048
#define NH     32
#define NKV    8
#define D_HEAD 64
#define M_FEAT 256
#define NC     16
#define CHUNK  128
#define QKVW   3072

// ---------------- scratch (device globals; no allocations allowed) ----------------
__device__ float g_qkv [(size_t)B_SZ * S_LEN * QKVW];
__device__ float g_xpk [(size_t)B_SZ * NKV * S_LEN * M_FEAT];
__device__ float g_sqk [B_SZ * NKV * S_LEN];
__device__ float g_stab[B_SZ * NKV];
__device__ float g_kv  [B_SZ * NKV * NC * M_FEAT * D_HEAD];
__device__ float g_kz  [B_SZ * NKV * NC * M_FEAT];
__device__ __align__(16) char g_projimg[65536];   // pre-swizzled proj bf16 hi/lo tile image

#define PHIQ_E ((size_t)B_SZ * NH  * S_LEN * M_FEAT)
#define PHIK_E ((size_t)B_SZ * NKV * S_LEN * M_FEAT)
#define HS_ELEMS  (B_SZ * S_LEN * HID_)
#define W_ELEMS   (QKVW * HID_ + HID_ * HID_)
__device__ __align__(16) __nv_bfloat16 g_pqh[PHIQ_E];
__device__ __align__(16) __nv_bfloat16 g_pql[PHIQ_E];
__device__ __align__(16) __nv_bfloat16 g_pkh[PHIK_E];
__device__ __align__(16) __nv_bfloat16 g_pkl[PHIK_E];
__device__ __align__(16) __nv_bfloat16 g_hsh[HS_ELEMS];
__device__ __align__(16) __nv_bfloat16 g_hsl[HS_ELEMS];
__device__ __align__(16) __nv_bfloat16 g_ath[HS_ELEMS];
__device__ __align__(16) __nv_bfloat16 g_atl[HS_ELEMS];
__device__ __align__(16) __nv_bfloat16 g_wh [W_ELEMS];
__device__ __align__(16) __nv_bfloat16 g_wl [W_ELEMS];

#define WQ_OFF 0
#define WK_OFF (HID_ * HID_)
#define WV_OFF (WK_OFF + 512 * HID_)
#define WO_OFF (WV_OFF + 512 * HID_)

// =================== fp32 -> bf16 hi/lo split (elementwise, x4 vec) ================
__global__ void split_bf16(const float* __restrict__ x, __nv_bfloat16* __restrict__ h,
                           __nv_bfloat16* __restrict__ l, int n4)
{
    int i = blockIdx.x * blockDim.x + threadIdx.x;
    if (i >= n4) return;
    float4 v = ((const float4*)x)[i];
    __nv_bfloat16 h0 = __float2bfloat16(v.x), h1 = __float2bfloat16(v.y);
    __nv_bfloat16 h2 = __float2bfloat16(v.z), h3 = __float2bfloat16(v.w);
    __nv_bfloat162* hp = (__nv_bfloat162*)h;
    hp[2 * i]     = __nv_bfloat162(h0, h1);
    hp[2 * i + 1] = __nv_bfloat162(h2, h3);
    __nv_bfloat162* lp = (__nv_bfloat162*)l;
    lp[2 * i]     = __nv_bfloat162(__float2bfloat16(v.x - __bfloat162float(h0)),
                                   __float2bfloat16(v.y - __bfloat162float(h1)));
    lp[2 * i + 1] = __nv_bfloat162(__float2bfloat16(v.z - __bfloat162float(h2)),
                                   __float2bfloat16(v.w - __bfloat162float(h3)));
}

// ===================== shared helpers for tensor-core kernels ======================
__device__ __forceinline__ uint32_t smem_u32g(const void* p)
{
    uint32_t a;
    asm("{ .reg .u64 t; cvta.to.shared.u64 t, %1; cvt.u32.u64 %0, t; }" : "=r"(a) : "l"(p));
    return a;
}

#define LDSM4(r, a) \
    asm volatile("ldmatrix.sync.aligned.m8n8.x4.shared.b16 {%0,%1,%2,%3}, [%4];" \
                 : "=r"((r)[0]), "=r"((r)[1]), "=r"((r)[2]), "=r"((r)[3]) : "r"(a))

#define CP_ASYNC16(dst, src) \
    asm volatile("cp.async.cg.shared.global [%0], [%1], 16;" :: "r"(dst), "l"(src) : "memory")
#define CP_COMMIT() asm volatile("cp.async.commit_group;" ::: "memory")
#define CP_WAIT(n)  asm volatile("cp.async.wait_group %0;" :: "n"(n) : "memory")

__device__ __forceinline__ void mma_bf16(float c[4], const uint32_t a[4], const uint32_t b[2])
{
    asm volatile("mma.sync.aligned.m16n8k16.row.col.f32.bf16.bf16.f32 "
                 "{%0,%1,%2,%3}, {%4,%5,%6,%7}, {%8,%9}, {%0,%1,%2,%3};"
                 : "+f"(c[0]), "+f"(c[1]), "+f"(c[2]), "+f"(c[3])
                 : "r"(a[0]), "r"(a[1]), "r"(a[2]), "r"(a[3]), "r"(b[0]), "r"(b[1]));
}

// cheap hi/lo split: hi = bf16-truncate (PRMT), lo = RN(residual) via one bf16x2 cvt
__device__ __forceinline__ void pack8(const float* f, uint4& hv, uint4& lv)
{
    uint32_t hw[4], lw[4];
#pragma unroll
    for (int e = 0; e < 4; e++) {
        const uint32_t u0 = __float_as_uint(f[2 * e]);
        const uint32_t u1 = __float_as_uint(f[2 * e + 1]);
        hw[e] = __byte_perm(u0, u1, 0x7632);
        const float t0 = __uint_as_float(u0 & 0xFFFF0000u);
        const float t1 = __uint_as_float(u1 & 0xFFFF0000u);
        const float r0 = f[2 * e] - t0;
        const float r1 = f[2 * e + 1] - t1;
        asm("cvt.rn.bf16x2.f32 %0, %1, %2;" : "=r"(lw[e]) : "f"(r1), "f"(r0));
    }
    hv = make_uint4(hw[0], hw[1], hw[2], hw[3]);
    lv = make_uint4(lw[0], lw[1], lw[2], lw[3]);
}

// ======== bf16 3-pass split GEMM: 128x128 tile, cp.async, ldmatrix =================
#define GK 2048
#define BK 32
#define NKT (GK / BK)
#define GBUF 32768
#define SMEM_GEMM (2 * GBUF)

__global__ __launch_bounds__(256, 2) void gemm_bf16x3(const __nv_bfloat16* __restrict__ Ah,
                                                      const __nv_bfloat16* __restrict__ Al,
                                                      const __nv_bfloat16* __restrict__ Bh,
                                                      const __nv_bfloat16* __restrict__ Bl,
                                                      float* __restrict__ C, int N)
{
    extern __shared__ char smc[];
    const uint32_t sb = smem_u32g(smc);
    const int tid  = threadIdx.x;
    const int warp = tid >> 5, lane = tid & 31;
    const int gid  = lane >> 2, tig = lane & 3;
    const int wm   = (warp & 1) * 64;
    const int wn   = (warp >> 1) * 32;
    const int rowA = blockIdx.y * 128;
    const int rowB = blockIdx.x * 128;

    const int r0s = tid >> 2,         s0s = tid & 3;
    const int r1s = (tid + 256) >> 2, s1s = tid & 3;
    const uint32_t so0 = (uint32_t)(r0s * 64 + ((s0s ^ ((r0s >> 1) & 3)) * 16));
    const uint32_t so1 = (uint32_t)(r1s * 64 + ((s1s ^ ((r1s >> 1) & 3)) * 16));

    const int swm   = ((lane & 7) >> 1) & 3;
    const int rlocA = (lane & 7) + (((lane >> 3) & 1) << 3);
    const int shA   = lane >> 4;
    const int rlocB = (lane & 7) + ((lane >> 4) << 3);
    const int shB   = (lane >> 3) & 1;

    float acc[4][4][4];
#pragma unroll
    for (int i = 0; i < 4; i++)
#pragma unroll
        for (int j = 0; j < 4; j++)
#pragma unroll
            for (int r = 0; r < 4; r++) acc[i][j][r] = 0.f;

    auto stage = [&](int kt, int b) {
        const uint32_t bb = sb + b * GBUF;
        const int kb = kt * BK;
        CP_ASYNC16(bb + so0,         (const char*)(Ah + (size_t)(rowA + r0s) * GK + kb + s0s * 8));
        CP_ASYNC16(bb + so1,         (const char*)(Ah + (size_t)(rowA + r1s) * GK + kb + s1s * 8));
        CP_ASYNC16(bb + 8192  + so0, (const char*)(Al + (size_t)(rowA + r0s) * GK + kb + s0s * 8));
        CP_ASYNC16(bb + 8192  + so1, (const char*)(Al + (size_t)(rowA + r1s) * GK + kb + s1s * 8));
        CP_ASYNC16(bb + 16384 + so0, (const char*)(Bh + (size_t)(rowB + r0s) * GK + kb + s0s * 8));
        CP_ASYNC16(bb + 16384 + so1, (const char*)(Bh + (size_t)(rowB + r1s) * GK + kb + s1s * 8));
        CP_ASYNC16(bb + 24576 + so0, (const char*)(Bl + (size_t)(rowB + r0s) * GK + kb + s0s * 8));
        CP_ASYNC16(bb + 24576 + so1, (const char*)(Bl + (size_t)(rowB + r1s) * GK + kb + s1s * 8));
        CP_COMMIT();
    };

    stage(0, 0);

    for (int kt = 0; kt < NKT; kt++) {
        if (kt + 1 < NKT) {
            stage(kt + 1, (kt + 1) & 1);
            CP_WAIT(1);
        } else {
            CP_WAIT(0);
        }
        __syncthreads();

        const uint32_t base = sb + (kt & 1) * GBUF;
#pragma unroll
        for (int kb = 0; kb < 2; kb++) {
            uint32_t ah[4][4], al[4][4];
#pragma unroll
            for (int tm = 0; tm < 4; tm++) {
                const int r = wm + tm * 16 + rlocA;
                const uint32_t off = (uint32_t)(r * 64 + (((2 * kb + shA) ^ swm) * 16));
                LDSM4(ah[tm], base + off);
                LDSM4(al[tm], base + 8192 + off);
            }
            uint32_t bhf[2][4], blf[2][4];
#pragma unroll
            for (int p = 0; p < 2; p++) {
                const int r = wn + p * 16 + rlocB;
                const uint32_t off = (uint32_t)(r * 64 + (((2 * kb + shB) ^ swm) * 16));
                LDSM4(bhf[p], base + 16384 + off);
                LDSM4(blf[p], base + 24576 + off);
            }
#pragma unroll
            for (int tm = 0; tm < 4; tm++)
#pragma unroll
                for (int tn = 0; tn < 4; tn++) {
                    const uint32_t* bh2 = &bhf[tn >> 1][(tn & 1) * 2];
                    const uint32_t* bl2 = &blf[tn >> 1][(tn & 1) * 2];
                    mma_bf16(acc[tm][tn], ah[tm], bh2);
                    mma_bf16(acc[tm][tn], ah[tm], bl2);
                    mma_bf16(acc[tm][tn], al[tm], bh2);
                }
        }
        __syncthreads();
    }

#pragma unroll
    for (int tm = 0; tm < 4; tm++) {
        const size_t r0 = (size_t)rowA + wm + tm * 16 + gid;
#pragma unroll
        for (int tn = 0; tn < 4; tn++) {
            const int cn = rowB + wn + tn * 8 + tig * 2;
            *(float2*)(C + r0 * N + cn)       = make_float2(acc[tm][tn][0], acc[tm][tn][1]);
            *(float2*)(C + (r0 + 8) * N + cn) = make_float2(acc[tm][tn][2], acc[tm][tn][3]);
        }
    }
}

__device__ void atomicMaxFloat(float* addr, float val)
{
    int* ia = (int*)addr;
    int old = *ia;
    while (__int_as_float(old) < val) {
        int assumed = old;
        old = atomicCAS(ia, assumed, __float_as_int(val));
        if (old == assumed) break;
    }
}

__global__ void init_stab_kernel(float* stab)
{
    if (threadIdx.x < B_SZ * NKV) stab[threadIdx.x] = -3.4e38f;
}

// ---------------- prep proj: build pre-swizzled bf16 hi/lo tile image --------------
// image layout: Bh chunk0 [0,16K), Bh chunk1 [16K,32K), Bl chunk0 [32K,48K), Bl chunk1 [48K,64K)
__global__ void prep_proj(const float* __restrict__ proj, char* __restrict__ img)
{
    const int t = blockIdx.x * blockDim.x + threadIdx.x;   // 2048 threads
    const int row = t >> 3, g = t & 7;
    const int chunk = g >> 2, slot = g & 3;
    float f[8];
    *(float4*)&f[0] = *(const float4*)(proj + row * 64 + g * 8);
    *(float4*)&f[4] = *(const float4*)(proj + row * 64 + g * 8 + 4);
    uint4 hv, lv;
    pack8(f, hv, lv);
    const uint32_t off = (uint32_t)(row * 64 + ((slot ^ ((row >> 1) & 3)) * 16));
    *(uint4*)(img + chunk * 16384 + off)         = hv;
    *(uint4*)(img + 32768 + chunk * 16384 + off) = lv;
}

// ---------------- tensor-core favor xp (q+k heads, RoPE fused) ---------------------
// grid (S/64, NH+NKV, B), 256 threads.  M=64 tokens, N=256 feats, K=64 (bf16x3).
#define FXP_ASF   65536
#define FXP_A     (FXP_ASF + 17408)
#define FXP_SQS   (FXP_A + 16384)
#define FXP_RED   (FXP_SQS + 256)
#define SMEM_FXP  (FXP_RED + 1024)

__global__ __launch_bounds__(256, 1) void favor_xp_tc(const float* __restrict__ x,
                                                      const float* __restrict__ cosp,
                                                      const float* __restrict__ sinp,
                                                      const char* __restrict__ projimg,
                                                      float* __restrict__ xpk,
                                                      __nv_bfloat16* __restrict__ pqh,
                                                      __nv_bfloat16* __restrict__ pql,
                                                      float* __restrict__ sqk,
                                                      float* __restrict__ stab)
{
    extern __shared__ char smc[];
    const uint32_t sb = smem_u32g(smc);
    float* Asf = (float*)(smc + FXP_ASF);
    float* sqs = (float*)(smc + FXP_SQS);
    float* red = (float*)(smc + FXP_RED);

    const float DN = 0.35355339059327373f;
    const int blk = blockIdx.x, hy = blockIdx.y, b = blockIdx.z;
    const bool isq = (hy < NH);
    const int h = isq ? hy : hy - NH;
    const int xcol = isq ? (h * 64) : (2048 + h * 64);
    const int s0 = blk * 64;
    const int tid = threadIdx.x;
    const int warp = tid >> 5, lane = tid & 31;
    const int gid = lane >> 2, tig = lane & 3;

    // 1. cp.async proj image (64KB)
#pragma unroll
    for (int i = 0; i < 16; i++) {
        const uint32_t off = (uint32_t)(tid * 16 + i * 4096);
        CP_ASYNC16(sb + off, projimg + off);
    }
    CP_COMMIT();

    // 2. stage x * DN (64 tokens x 64)
#pragma unroll
    for (int r = 0; r < 4; r++) {
        int l = tid + r * 256;
        int tok = l >> 4, q4 = (l & 15) << 2;
        float4 vv = *(const float4*)(x + (size_t)(b * S_LEN + s0 + tok) * QKVW + xcol + q4);
        Asf[tok * 68 + q4 + 0] = vv.x * DN;
        Asf[tok * 68 + q4 + 1] = vv.y * DN;
        Asf[tok * 68 + q4 + 2] = vv.z * DN;
        Asf[tok * 68 + q4 + 3] = vv.w * DN;
    }
    __syncthreads();

    // 3. RoPE in smem (64 tok x 32 pairs)
#pragma unroll
    for (int r = 0; r < 8; r++) {
        int idx = tid + r * 256;
        int tok = idx >> 5, p = idx & 31;
        const size_t crow = (size_t)(b * S_LEN + s0 + tok) * 64;
        const float c1 = cosp[crow + p],      sn1 = sinp[crow + p];
        const float c2 = cosp[crow + 32 + p], sn2 = sinp[crow + 32 + p];
        float a  = Asf[tok * 68 + p];
        float b2 = Asf[tok * 68 + p + 32];
        Asf[tok * 68 + p]      = a * c1 - b2 * sn1;
        Asf[tok * 68 + p + 32] = b2 * c2 + a * sn2;
    }
    __syncthreads();

    // 4. sq + A conversion to bf16 chunks
    if (tid < 64) {
        float ssum = 0.f;
#pragma unroll
        for (int d = 0; d < 64; d++) { float vv = Asf[tid * 68 + d]; ssum += vv * vv; }
        sqs[tid] = 0.5f * ssum;
        if (!isq) sqk[((size_t)(b * NKV + h)) * S_LEN + s0 + tid] = 0.5f * ssum;
    }
#pragma unroll
    for (int r = 0; r < 2; r++) {
        int s = tid + r * 256;
        int row = s >> 3, g = s & 7;
        int chunk = g >> 2, slot = g & 3;
        float f[8];
        *(float4*)&f[0] = *(const float4*)(Asf + row * 68 + g * 8);
        *(float4*)&f[4] = *(const float4*)(Asf + row * 68 + g * 8 + 4);
        uint4 hv, lv;
        pack8(f, hv, lv);
        const uint32_t off = (uint32_t)(row * 64 + ((slot ^ ((row >> 1) & 3)) * 16));
        *(uint4*)(smc + FXP_A + chunk * 4096 + off)        = hv;
        *(uint4*)(smc + FXP_A + 8192 + chunk * 4096 + off) = lv;
    }
    CP_WAIT(0);
    __syncthreads();

    // 5. mma: 64 x 256 x 64, 4 k-steps of 16
    const int wm = (warp & 1) * 32;
    const int wn = (warp >> 1) * 64;
    const int swm   = ((lane & 7) >> 1) & 3;
    const int rlocA = (lane & 7) + (((lane >> 3) & 1) << 3);
    const int shA   = lane >> 4;
    const int rlocB = (lane & 7) + ((lane >> 4) << 3);
    const int shB   = (lane >> 3) & 1;

    float acc[2][8][4];
#pragma unroll
    for (int i = 0; i < 2; i++)
#pragma unroll
        for (int j = 0; j < 8; j++)
#pragma unroll
            for (int r = 0; r < 4; r++) acc[i][j][r] = 0.f;

#pragma unroll
    for (int ks = 0; ks < 4; ks++) {
        const int chunk = ks >> 1, kb = ks & 1;
        const uint32_t aBase = sb + FXP_A + chunk * 4096;
        const uint32_t bBase = sb + chunk * 16384;
        uint32_t ah[2][4], al[2][4];
#pragma unroll
        for (int tm = 0; tm < 2; tm++) {
            const int r = wm + tm * 16 + rlocA;
            const uint32_t off = (uint32_t)(r * 64 + (((2 * kb + shA) ^ swm) * 16));
            LDSM4(ah[tm], aBase + off);
            LDSM4(al[tm], aBase + 8192 + off);
        }
        uint32_t bhf[4][4], blf[4][4];
#pragma unroll
        for (int p = 0; p < 4; p++) {
            const int r = wn + p * 16 + rlocB;
            const uint32_t off = (uint32_t)(r * 64 + (((2 * kb + shB) ^ swm) * 16));
            LDSM4(bhf[p], bBase + off);
            LDSM4(blf[p], bBase + 32768 + off);
        }
#pragma unroll
        for (int tm = 0; tm < 2; tm++)
#pragma unroll
            for (int tn = 0; tn < 8; tn++) {
                const uint32_t* bh2 = &bhf[tn >> 1][(tn & 1) * 2];
                const uint32_t* bl2 = &blf[tn >> 1][(tn & 1) * 2];
                mma_bf16(acc[tm][tn], ah[tm], bh2);
                mma_bf16(acc[tm][tn], ah[tm], bl2);
                mma_bf16(acc[tm][tn], al[tm], bh2);
            }
    }

    // 6. epilogue
    if (isq) {
        // per-row max over 256 cols: warp-local (64 cols) -> smem -> combine
#pragma unroll
        for (int tm = 0; tm < 2; tm++) {
            float m0 = -3.4e38f, m1 = -3.4e38f;
#pragma unroll
            for (int tn = 0; tn < 8; tn++) {
                m0 = fmaxf(m0, fmaxf(acc[tm][tn][0], acc[tm][tn][1]));
                m1 = fmaxf(m1, fmaxf(acc[tm][tn][2], acc[tm][tn][3]));
            }
#pragma unroll
            for (int o = 1; o <= 2; o <<= 1) {
                m0 = fmaxf(m0, __shfl_xor_sync(0xffffffffu, m0, o));
                m1 = fmaxf(m1, __shfl_xor_sync(0xffffffffu, m1, o));
            }
            if (tig == 0) {
                red[(wm + tm * 16 + gid) * 4 + (warp >> 1)]     = m0;
                red[(wm + tm * 16 + gid + 8) * 4 + (warp >> 1)] = m1;
            }
        }
        __syncthreads();
        const size_t rowbase = (size_t)(b * NH + h) * S_LEN + s0;
#pragma unroll
        for (int tm = 0; tm < 2; tm++) {
            const int r0 = wm + tm * 16 + gid, r1 = r0 + 8;
            const float m0 = fmaxf(fmaxf(red[r0 * 4], red[r0 * 4 + 1]),
                                   fmaxf(red[r0 * 4 + 2], red[r0 * 4 + 3]));
            const float m1 = fmaxf(fmaxf(red[r1 * 4], red[r1 * 4 + 1]),
                                   fmaxf(red[r1 * 4 + 2], red[r1 * 4 + 3]));
            const float s0v = sqs[r0] + m0, s1v = sqs[r1] + m1;
#pragma unroll
            for (int tn = 0; tn < 8; tn++) {
                const int col = wn + tn * 8 + tig * 2;
                float e0 = (__expf(acc[tm][tn][0] - s0v) + 1e-6f) * 0.0625f;
                float e1 = (__expf(acc[tm][tn][1] - s0v) + 1e-6f) * 0.0625f;
                float e2 = (__expf(acc[tm][tn][2] - s1v) + 1e-6f) * 0.0625f;
                float e3 = (__expf(acc[tm][tn][3] - s1v) + 1e-6f) * 0.0625f;
                uint32_t u0 = __float_as_uint(e0), u1 = __float_as_uint(e1);
                uint32_t h01 = __byte_perm(u0, u1, 0x7632), l01;
                float q0 = e0 - __uint_as_float(u0 & 0xFFFF0000u);
                float q1 = e1 - __uint_as_float(u1 & 0xFFFF0000u);
                asm("cvt.rn.bf16x2.f32 %0, %1, %2;" : "=r"(l01) : "f"(q1), "f"(q0));
                uint32_t u2 = __float_as_uint(e2), u3 = __float_as_uint(e3);
                uint32_t h23 = __byte_perm(u2, u3, 0x7632), l23;
                float q2 = e2 - __uint_as_float(u2 & 0xFFFF0000u);
                float q3 = e3 - __uint_as_float(u3 & 0xFFFF0000u);
                asm("cvt.rn.bf16x2.f32 %0, %1, %2;" : "=r"(l23) : "f"(q3), "f"(q2));
                *(uint32_t*)(pqh + (rowbase + r0) * M_FEAT + col) = h01;
                *(uint32_t*)(pql + (rowbase + r0) * M_FEAT + col) = l01;
                *(uint32_t*)(pqh + (rowbase + r1) * M_FEAT + col) = h23;
                *(uint32_t*)(pql + (rowbase + r1) * M_FEAT + col) = l23;
            }
        }
    } else {
        const size_t rowbase = (size_t)(b * NKV + h) * S_LEN + s0;
        float mx = -3.4e38f;
#pragma unroll
        for (int tm = 0; tm < 2; tm++) {
            const int r0 = wm + tm * 16 + gid, r1 = r0 + 8;
#pragma unroll
            for (int tn = 0; tn < 8; tn++) {
                const int col = wn + tn * 8 + tig * 2;
                *(float2*)(xpk + (rowbase + r0) * M_FEAT + col) =
                    make_float2(acc[tm][tn][0], acc[tm][tn][1]);
                *(float2*)(xpk + (rowbase + r1) * M_FEAT + col) =
                    make_float2(acc[tm][tn][2], acc[tm][tn][3]);
                mx = fmaxf(mx, fmaxf(fmaxf(acc[tm][tn][0], acc[tm][tn][1]),
                                     fmaxf(acc[tm][tn][2], acc[tm][tn][3])));
            }
        }
        red[tid] = mx;
        __syncthreads();
        for (int st = 128; st > 0; st >>= 1) {
            if (tid < st) red[tid] = fmaxf(red[tid], red[tid + st]);
            __syncthreads();
        }
        if (tid == 0) atomicMaxFloat(&stab[b * NKV + h], red[0]);
    }
}

// ------- per-chunk kv/kz with fused k-exp + phi_k hi/lo output. grid (NC,NKV,B) -----
__global__ __launch_bounds__(256) void kv_chunk(const float* __restrict__ xpk,
                                                const float* __restrict__ sqk,
                                                const float* __restrict__ stab,
                                                __nv_bfloat16* __restrict__ pkh,
                                                __nv_bfloat16* __restrict__ pkl,
                                                const float* __restrict__ qkv,
                                                float* __restrict__ kv,
                                                float* __restrict__ kz)
{
    __shared__ float ps[16][256];
    __shared__ float vs[16][64];
    const int c = blockIdx.x, h = blockIdx.y, b = blockIdx.z;
    const int tid = threadIdx.x;
    const float stabv = stab[b * NKV + h];
    float acc[64];
#pragma unroll
    for (int d = 0; d < 64; d++) acc[d] = 0.f;
    float accz = 0.f;
    const size_t prow = (size_t)(b * NKV + h) * S_LEN + c * CHUNK;
    const size_t vrow = (size_t)b * S_LEN + c * CHUNK;

    for (int i0 = 0; i0 < CHUNK; i0 += 16) {
#pragma unroll
        for (int ii = 0; ii < 16; ii++) {
            const size_t idx = (prow + i0 + ii) * M_FEAT + tid;
            const float sqv = sqk[prow + i0 + ii];
            const float v = (__expf(xpk[idx] - sqv - stabv) + 1e-6f) * 0.0625f;
            ps[ii][tid] = v;
            const uint32_t u = __float_as_uint(v);
            const float t = __uint_as_float(u & 0xFFFF0000u);
            pkh[idx] = __ushort_as_bfloat16((unsigned short)(u >> 16));
            pkl[idx] = __float2bfloat16(v - t);
        }
#pragma unroll
        for (int j = 0; j < 4; j++) {
            int l = tid + j * 256;
            int ii = l >> 6, d = l & 63;
            vs[ii][d] = qkv[(vrow + i0 + ii) * QKVW + 2560 + h * 64 + d];
        }
        __syncthreads();
#pragma unroll
        for (int ii = 0; ii < 16; ii++) {
            float a = ps[ii][tid];
            accz += a;
#pragma unroll
            for (int d4 = 0; d4 < 64; d4 += 4) {
                float4 vv = *(const float4*)&vs[ii][d4];
                acc[d4 + 0] += a * vv.x; acc[d4 + 1] += a * vv.y;
                acc[d4 + 2] += a * vv.z; acc[d4 + 3] += a * vv.w;
            }
        }
        __syncthreads();
    }
    const size_t ob = (((size_t)(b * NKV + h) * NC + c) * M_FEAT + tid) * D_HEAD;
#pragma unroll
    for (int d4 = 0; d4 < 64; d4 += 4)
        *(float4*)(kv + ob + d4) = make_float4(acc[d4], acc[d4 + 1], acc[d4 + 2], acc[d4 + 3]);
    kz[((size_t)(b * NKV + h) * NC + c) * M_FEAT + tid] = accz;
}

// ---------------- exclusive prefix over chunk axis, in place ----------------------
__global__ void cumsum_k(float* __restrict__ kv, float* __restrict__ kz)
{
    const int tid = blockIdx.x * blockDim.x + threadIdx.x;
    const int KVSZ = M_FEAT * D_HEAD;
    if (tid < B_SZ * NKV * KVSZ) {
        int bh = tid / KVSZ, md = tid % KVSZ;
        float run = 0.f;
        for (int c = 0; c < NC; c++) {
            size_t idx = ((size_t)bh * NC + c) * KVSZ + md;
            float t = kv[idx]; kv[idx] = run; run += t;
        }
    } else {
        int t2 = tid - B_SZ * NKV * KVSZ;
        if (t2 < B_SZ * NKV * M_FEAT) {
            int bh = t2 / M_FEAT, m = t2 % M_FEAT;
            float run = 0.f;
            for (int c = 0; c < NC; c++) {
                size_t idx = ((size_t)bh * NC + c) * M_FEAT + m;
                float tz = kz[idx]; kz[idx] = run; run += tz;
            }
        }
    }
}

// ============ tensor-core chunked causal linear attention. grid (NC, NH, B) ========
#define SPITCH 132
#define SMEM_ATTN (128 * SPITCH * 4 + 4 * 8192 + 512)

__global__ __launch_bounds__(256, 1) void attn_tc(
    const __nv_bfloat16* __restrict__ pqh, const __nv_bfloat16* __restrict__ pql,
    const __nv_bfloat16* __restrict__ pkh, const __nv_bfloat16* __restrict__ pkl,
    const float* __restrict__ qkv, const float* __restrict__ kvpre,
    const float* __restrict__ kzpre,
    __nv_bfloat16* __restrict__ ath, __nv_bfloat16* __restrict__ atl)
{
    extern __shared__ float sm[];
    float* Ss = sm;
    char* Ah = (char*)(sm + 128 * SPITCH);
    char* Al = Ah + 8192;
    char* Bh = Al + 8192;
    char* Bl = Bh + 8192;
    float* Zs = (float*)(Bl + 8192);

    const uint32_t sbAh = smem_u32g(Ah), sbAl = smem_u32g(Al);
    const uint32_t sbBh = smem_u32g(Bh), sbBl = smem_u32g(Bl);

    const int c = blockIdx.x, h = blockIdx.y, b = blockIdx.z;
    const int kvh = h >> 2;
    const int tid = threadIdx.x;
    const int warp = tid >> 5, lane = tid & 31;
    const int gid = lane >> 2, tig = lane & 3;

    const size_t qbase  = (size_t)(b * NH + h) * S_LEN + c * CHUNK;
    const size_t kbase  = (size_t)(b * NKV + kvh) * S_LEN + c * CHUNK;
    const size_t vrow0  = (size_t)b * S_LEN + c * CHUNK;
    const size_t kvbase = ((size_t)(b * NKV + kvh) * NC + c) * (size_t)(M_FEAT * D_HEAD);
    const size_t kzbase = ((size_t)(b * NKV + kvh) * NC + c) * M_FEAT;

    const int strow = tid & 127;
    const int s0 = tid >> 7;

    const int swm   = ((lane & 7) >> 1) & 3;
    const int rlocA = (lane & 7) + (((lane >> 3) & 1) << 3);
    const int shA   = lane >> 4;
    const int rlocB = (lane & 7) + ((lane >> 4) << 3);
    const int shB   = (lane >> 3) & 1;

    // ======================= Phase 1: scores =======================
    {
        const int wm = (warp & 1) * 64, wn = (warp >> 1) * 32;
        float acc[4][4][4];
#pragma unroll
        for (int i = 0; i < 4; i++)
#pragma unroll
            for (int j = 0; j < 4; j++)
#pragma unroll
                for (int r = 0; r < 4; r++) acc[i][j][r] = 0.f;

        for (int m0 = 0; m0 < M_FEAT; m0 += 32) {
#pragma unroll
            for (int si = 0; si < 2; si++) {
                const int s = s0 + si * 2;
                const uint32_t off = (uint32_t)(strow * 64 + ((s ^ ((strow >> 1) & 3)) * 16));
                const size_t ia = (qbase + strow) * M_FEAT + m0 + s * 8;
                *(uint4*)(Ah + off) = *(const uint4*)(pqh + ia);
                *(uint4*)(Al + off) = *(const uint4*)(pql + ia);
                const size_t ib = (kbase + strow) * M_FEAT + m0 + s * 8;
                *(uint4*)(Bh + off) = *(const uint4*)(pkh + ib);
                *(uint4*)(Bl + off) = *(const uint4*)(pkl + ib);
            }
            __syncthreads();
#pragma unroll
            for (int kb = 0; kb < 2; kb++) {
                uint32_t ah[4][4], al[4][4];
#pragma unroll
                for (int tm = 0; tm < 4; tm++) {
                    const int r = wm + tm * 16 + rlocA;
                    const uint32_t off = (uint32_t)(r * 64 + (((2 * kb + shA) ^ swm) * 16));
                    LDSM4(ah[tm], sbAh + off);
                    LDSM4(al[tm], sbAl + off);
                }
                uint32_t bhf[2][4], blf[2][4];
#pragma unroll
                for (int p = 0; p < 2; p++) {
                    const int r = wn + p * 16 + rlocB;
                    const uint32_t off = (uint32_t)(r * 64 + (((2 * kb + shB) ^ swm) * 16));
                    LDSM4(bhf[p], sbBh + off);
                    LDSM4(blf[p], sbBl + off);
                }
#pragma unroll
                for (int tm = 0; tm < 4; tm++)
#pragma unroll
                    for (int tn = 0; tn < 4; tn++) {
                        const uint32_t* bh2 = &bhf[tn >> 1][(tn & 1) * 2];
                        const uint32_t* bl2 = &blf[tn >> 1][(tn & 1) * 2];
                        mma_bf16(acc[tm][tn], ah[tm], bh2);
                        mma_bf16(acc[tm][tn], ah[tm], bl2);
                        mma_bf16(acc[tm][tn], al[tm], bh2);
                    }
            }
            __syncthreads();
        }
#pragma unroll
        for (int tm = 0; tm < 4; tm++) {
            const int r0 = wm + tm * 16 + gid;
            const int r1 = r0 + 8;
#pragma unroll
            for (int tn = 0; tn < 4; tn++) {
                const int col = wn + tn * 8 + tig * 2;
                Ss[r0 * SPITCH + col]     = (col     <= r0) ? acc[tm][tn][0] : 0.f;
                Ss[r0 * SPITCH + col + 1] = (col + 1 <= r0) ? acc[tm][tn][1] : 0.f;
                Ss[r1 * SPITCH + col]     = (col     <= r1) ? acc[tm][tn][2] : 0.f;
                Ss[r1 * SPITCH + col + 1] = (col + 1 <= r1) ? acc[tm][tn][3] : 0.f;
            }
        }
    }
    __syncthreads();

    // ======================= Phase 2: inter+intra (+z col 64) =======================
    const int wm2 = (warp & 3) * 32, wn2 = (warp >> 2) * 40;
    float acc2[2][5][4];
#pragma unroll
    for (int i = 0; i < 2; i++)
#pragma unroll
        for (int j = 0; j < 5; j++)
#pragma unroll
            for (int r = 0; r < 4; r++) acc2[i][j][r] = 0.f;

    for (int cc = 0; cc < 12; cc++) {
#pragma unroll
        for (int si = 0; si < 2; si++) {
            const int s = s0 + si * 2;
            const uint32_t off = (uint32_t)(strow * 64 + ((s ^ ((strow >> 1) & 3)) * 16));
            if (cc < 8) {
                const size_t ia = (qbase + strow) * M_FEAT + cc * 32 + s * 8;
                *(uint4*)(Ah + off) = *(const uint4*)(pqh + ia);
                *(uint4*)(Al + off) = *(const uint4*)(pql + ia);
            } else {
                float f[8];
                const float* pa = Ss + strow * SPITCH + (cc - 8) * 32 + s * 8;
                *(float4*)&f[0] = *(const float4*)pa;
                *(float4*)&f[4] = *(const float4*)(pa + 4);
                uint4 hv, lv;
                pack8(f, hv, lv);
                *(uint4*)(Ah + off) = hv;
                *(uint4*)(Al + off) = lv;
            }

            if (strow < 96) {
                float g[8];
                if (strow < 64) {
                    if (cc < 8) {
#pragma unroll
                        for (int e = 0; e < 8; e++)
                            g[e] = kvpre[kvbase + (size_t)(cc * 32 + s * 8 + e) * 64 + strow];
                    } else {
#pragma unroll
                        for (int e = 0; e < 8; e++)
                            g[e] = qkv[(vrow0 + (cc - 8) * 32 + s * 8 + e) * QKVW + 2560 + kvh * 64 + strow];
                    }
                } else if (strow == 64) {
                    if (cc < 8) {
#pragma unroll
                        for (int e = 0; e < 8; e++)
                            g[e] = kzpre[kzbase + cc * 32 + s * 8 + e];
                    } else {
#pragma unroll
                        for (int e = 0; e < 8; e++) g[e] = 1.f;
                    }
                } else {
#pragma unroll
                    for (int e = 0; e < 8; e++) g[e] = 0.f;
                }
                uint4 hv, lv;
                pack8(g, hv, lv);
                *(uint4*)(Bh + off) = hv;
                *(uint4*)(Bl + off) = lv;
            }
        }
        __syncthreads();
#pragma unroll
        for (int kb = 0; kb < 2; kb++) {
            uint32_t ah2[2][4], al2[2][4], bh2[3][4], bl2[3][4];
#pragma unroll
            for (int tm = 0; tm < 2; tm++) {
                const int r = wm2 + tm * 16 + rlocA;
                const uint32_t off = (uint32_t)(r * 64 + (((2 * kb + shA) ^ swm) * 16));
                LDSM4(ah2[tm], sbAh + off);
                LDSM4(al2[tm], sbAl + off);
            }
#pragma unroll
            for (int p = 0; p < 3; p++) {
                const int r = wn2 + p * 16 + rlocB;
                const uint32_t off = (uint32_t)(r * 64 + (((2 * kb + shB) ^ swm) * 16));
                LDSM4(bh2[p], sbBh + off);
                LDSM4(bl2[p], sbBl + off);
            }
#pragma unroll
            for (int tm = 0; tm < 2; tm++)
#pragma unroll
                for (int tn = 0; tn < 5; tn++) {
                    const uint32_t* bh_ = &bh2[tn >> 1][(tn & 1) * 2];
                    const uint32_t* bl_ = &bl2[tn >> 1][(tn & 1) * 2];
                    mma_bf16(acc2[tm][tn], ah2[tm], bh_);
                    mma_bf16(acc2[tm][tn], ah2[tm], bl_);
                    mma_bf16(acc2[tm][tn], al2[tm], bh_);
                }
        }
        __syncthreads();
    }

    if ((warp >> 2) == 1 && tig == 0) {
#pragma unroll
        for (int tm = 0; tm < 2; tm++) {
            const int r = wm2 + tm * 16 + gid;
            Zs[r]     = acc2[tm][3][0];
            Zs[r + 8] = acc2[tm][3][2];
        }
    }
    __syncthreads();

#pragma unroll
    for (int tm = 0; tm < 2; tm++) {
        const int r = wm2 + tm * 16 + gid;
        const float d0 = 1.f / (Zs[r] + 1e-6f);
        const float d1 = 1.f / (Zs[r + 8] + 1e-6f);
#pragma unroll
        for (int tn = 0; tn < 5; tn++) {
            const int col = wn2 + tn * 8 + tig * 2;
            if (col < 64) {
                const size_t ro = ((size_t)b * S_LEN + c * CHUNK + r) * (NH * D_HEAD) + h * 64 + col;
                const size_t ro8 = ro + 8 * (NH * D_HEAD);
                float o0 = acc2[tm][tn][0] * d0, o1 = acc2[tm][tn][1] * d0;
                float o2 = acc2[tm][tn][2] * d1, o3 = acc2[tm][tn][3] * d1;
                __nv_bfloat16 h0 = __float2bfloat16(o0), h1 = __float2bfloat16(o1);
                __nv_bfloat16 h2 = __float2bfloat16(o2), h3 = __float2bfloat16(o3);
                *(__nv_bfloat162*)(ath + ro)  = __nv_bfloat162(h0, h1);
                *(__nv_bfloat162*)(ath + ro8) = __nv_bfloat162(h2, h3);
                *(__nv_bfloat162*)(atl + ro)  =
                    __nv_bfloat162(__float2bfloat16(o0 - __bfloat162float(h0)),
                                   __float2bfloat16(o1 - __bfloat162float(h1)));
                *(__nv_bfloat162*)(atl + ro8) =
                    __nv_bfloat162(__float2bfloat16(o2 - __bfloat162float(h2)),
                                   __float2bfloat16(o3 - __bfloat162float(h3)));
            }
        }
    }
}

// ----------------------------------- launch ---------------------------------------
extern "C" void kernel_launch(void* const* d_in, const int* in_sizes, int n_in,
                              void* d_out, int out_size)
{
    const float* hs   = (const float*)d_in[0];
    const float* cosp = (const float*)d_in[1];
    const float* sinp = (const float*)d_in[2];
    const float* Wq   = (const float*)d_in[3];
    const float* Wk   = (const float*)d_in[4];
    const float* Wv   = (const float*)d_in[5];
    const float* Wo   = (const float*)d_in[6];
    const float* proj = (const float*)d_in[7];
    float* out = (float*)d_out;

    float *qkvp, *xpkp, *sqkp, *stabp, *kvp, *kzp;
    cudaGetSymbolAddress((void**)&qkvp,  g_qkv);
    cudaGetSymbolAddress((void**)&xpkp,  g_xpk);
    cudaGetSymbolAddress((void**)&sqkp,  g_sqk);
    cudaGetSymbolAddress((void**)&stabp, g_stab);
    cudaGetSymbolAddress((void**)&kvp,   g_kv);
    cudaGetSymbolAddress((void**)&kzp,   g_kz);
    char* pimg;
    cudaGetSymbolAddress((void**)&pimg, g_projimg);

    __nv_bfloat16 *pqh, *pql, *pkh, *pkl, *hsh, *hsl, *ath, *atl, *wh, *wl;
    cudaGetSymbolAddress((void**)&pqh, g_pqh);
    cudaGetSymbolAddress((void**)&pql, g_pql);
    cudaGetSymbolAddress((void**)&pkh, g_pkh);
    cudaGetSymbolAddress((void**)&pkl, g_pkl);
    cudaGetSymbolAddress((void**)&hsh, g_hsh);
    cudaGetSymbolAddress((void**)&hsl, g_hsl);
    cudaGetSymbolAddress((void**)&ath, g_ath);
    cudaGetSymbolAddress((void**)&atl, g_atl);
    cudaGetSymbolAddress((void**)&wh,  g_wh);
    cudaGetSymbolAddress((void**)&wl,  g_wl);

    cudaFuncSetAttribute(gemm_bf16x3, cudaFuncAttributeMaxDynamicSharedMemorySize, SMEM_GEMM);
    cudaFuncSetAttribute(attn_tc, cudaFuncAttributeMaxDynamicSharedMemorySize, SMEM_ATTN);
    cudaFuncSetAttribute(favor_xp_tc, cudaFuncAttributeMaxDynamicSharedMemorySize, SMEM_FXP);

    // ---- splits + proj image ----
    split_bf16<<<(HS_ELEMS / 4 + 255) / 256, 256>>>(hs, hsh, hsl, HS_ELEMS / 4);
    split_bf16<<<(HID_ * HID_ / 4 + 255) / 256, 256>>>(Wq, wh + WQ_OFF, wl + WQ_OFF, HID_ * HID_ / 4);
    split_bf16<<<(512 * HID_ / 4 + 255) / 256, 256>>>(Wk, wh + WK_OFF, wl + WK_OFF, 512 * HID_ / 4);
    split_bf16<<<(512 * HID_ / 4 + 255) / 256, 256>>>(Wv, wh + WV_OFF, wl + WV_OFF, 512 * HID_ / 4);
    split_bf16<<<(HID_ * HID_ / 4 + 255) / 256, 256>>>(Wo, wh + WO_OFF, wl + WO_OFF, HID_ * HID_ / 4);
    prep_proj<<<8, 256>>>(proj, pimg);

    // ---- fused QKV projection ----
    gemm_bf16x3<<<dim3(QKVW / 128, 32), 256, SMEM_GEMM>>>(hsh, hsl, wh, wl, qkvp, QKVW);

    // ---- favor features on tensor cores (q+k merged, RoPE fused) ----
    init_stab_kernel<<<1, 32>>>(stabp);
    favor_xp_tc<<<dim3(S_LEN / 64, NH + NKV, B_SZ), 256, SMEM_FXP>>>(
        qkvp, cosp, sinp, pimg, xpkp, pqh, pql, sqkp, stabp);

    // ---- chunked linear attention ----
    kv_chunk<<<dim3(NC, NKV, B_SZ), 256>>>(xpkp, sqkp, stabp, pkh, pkl, qkvp, kvp, kzp);
    cumsum_k<<<(B_SZ * NKV * (M_FEAT * D_HEAD + M_FEAT) + 255) / 256, 256>>>(kvp, kzp);
    attn_tc<<<dim3(NC, NH, B_SZ), 256, SMEM_ATTN>>>(pqh, pql, pkh, pkl, qkvp, kvp, kzp, ath, atl);

    // ---- output projection ----
    gemm_bf16x3<<<dim3(16, 32), 256, SMEM_GEMM>>>(ath, atl, wh + WO_OFF, wl + WO_OFF, out, 2048);
}

// round 15
// speedup vs baseline: 1.8550x; 1.0232x over previous
#include <cuda_runtime.h>
#include <cuda_bf16.h>
#include <math.h>
#include <stdint.h>

#define B_SZ   2
#define S_LEN  2048
#define HID_   2048
#define NH     32
#define NKV    8
#define D_HEAD 64
#define M_FEAT 256
#define NC     16
#define CHUNK  128
#define QKVW   3072

// ---------------- scratch (device globals; no allocations allowed) ----------------
__device__ float g_qkv [(size_t)B_SZ * S_LEN * QKVW];
__device__ float g_xpk [(size_t)B_SZ * NKV * S_LEN * M_FEAT];
__device__ float g_sqk [B_SZ * NKV * S_LEN];
__device__ float g_stab[B_SZ * NKV];
__device__ float g_kv  [B_SZ * NKV * NC * M_FEAT * D_HEAD];
__device__ float g_kz  [B_SZ * NKV * NC * M_FEAT];
__device__ __align__(16) char g_projimg[65536];

#define PHIQ_E ((size_t)B_SZ * NH  * S_LEN * M_FEAT)
#define PHIK_E ((size_t)B_SZ * NKV * S_LEN * M_FEAT)
#define HS_ELEMS  (B_SZ * S_LEN * HID_)
#define W_ELEMS   (QKVW * HID_ + HID_ * HID_)
__device__ __align__(16) __nv_bfloat16 g_pqh[PHIQ_E];
__device__ __align__(16) __nv_bfloat16 g_pql[PHIQ_E];
__device__ __align__(16) __nv_bfloat16 g_pkh[PHIK_E];
__device__ __align__(16) __nv_bfloat16 g_pkl[PHIK_E];
__device__ __align__(16) __nv_bfloat16 g_hsh[HS_ELEMS];
__device__ __align__(16) __nv_bfloat16 g_hsl[HS_ELEMS];
__device__ __align__(16) __nv_bfloat16 g_ath[HS_ELEMS];
__device__ __align__(16) __nv_bfloat16 g_atl[HS_ELEMS];
__device__ __align__(16) __nv_bfloat16 g_wh [W_ELEMS];
__device__ __align__(16) __nv_bfloat16 g_wl [W_ELEMS];

#define WQ_OFF 0
#define WK_OFF (HID_ * HID_)
#define WV_OFF (WK_OFF + 512 * HID_)
#define WO_OFF (WV_OFF + 512 * HID_)

// =================== fp32 -> bf16 hi/lo split (elementwise, x4 vec) ================
__global__ void split_bf16(const float* __restrict__ x, __nv_bfloat16* __restrict__ h,
                           __nv_bfloat16* __restrict__ l, int n4)
{
    int i = blockIdx.x * blockDim.x + threadIdx.x;
    if (i >= n4) return;
    float4 v = ((const float4*)x)[i];
    __nv_bfloat16 h0 = __float2bfloat16(v.x), h1 = __float2bfloat16(v.y);
    __nv_bfloat16 h2 = __float2bfloat16(v.z), h3 = __float2bfloat16(v.w);
    __nv_bfloat162* hp = (__nv_bfloat162*)h;
    hp[2 * i]     = __nv_bfloat162(h0, h1);
    hp[2 * i + 1] = __nv_bfloat162(h2, h3);
    __nv_bfloat162* lp = (__nv_bfloat162*)l;
    lp[2 * i]     = __nv_bfloat162(__float2bfloat16(v.x - __bfloat162float(h0)),
                                   __float2bfloat16(v.y - __bfloat162float(h1)));
    lp[2 * i + 1] = __nv_bfloat162(__float2bfloat16(v.z - __bfloat162float(h2)),
                                   __float2bfloat16(v.w - __bfloat162float(h3)));
}

// ===================== shared helpers for tensor-core kernels ======================
__device__ __forceinline__ uint32_t smem_u32g(const void* p)
{
    uint32_t a;
    asm("{ .reg .u64 t; cvta.to.shared.u64 t, %1; cvt.u32.u64 %0, t; }" : "=r"(a) : "l"(p));
    return a;
}

#define LDSM4(r, a) \
    asm volatile("ldmatrix.sync.aligned.m8n8.x4.shared.b16 {%0,%1,%2,%3}, [%4];" \
                 : "=r"((r)[0]), "=r"((r)[1]), "=r"((r)[2]), "=r"((r)[3]) : "r"(a))

#define CP_ASYNC16(dst, src) \
    asm volatile("cp.async.cg.shared.global [%0], [%1], 16;" :: "r"(dst), "l"(src) : "memory")
#define CP_COMMIT() asm volatile("cp.async.commit_group;" ::: "memory")
#define CP_WAIT(n)  asm volatile("cp.async.wait_group %0;" :: "n"(n) : "memory")

__device__ __forceinline__ void mma_bf16(float c[4], const uint32_t a[4], const uint32_t b[2])
{
    asm volatile("mma.sync.aligned.m16n8k16.row.col.f32.bf16.bf16.f32 "
                 "{%0,%1,%2,%3}, {%4,%5,%6,%7}, {%8,%9}, {%0,%1,%2,%3};"
                 : "+f"(c[0]), "+f"(c[1]), "+f"(c[2]), "+f"(c[3])
                 : "r"(a[0]), "r"(a[1]), "r"(a[2]), "r"(a[3]), "r"(b[0]), "r"(b[1]));
}

// cheap hi/lo split: hi = bf16-truncate (PRMT), lo = RN(residual) via one bf16x2 cvt
__device__ __forceinline__ void pack8(const float* f, uint4& hv, uint4& lv)
{
    uint32_t hw[4], lw[4];
#pragma unroll
    for (int e = 0; e < 4; e++) {
        const uint32_t u0 = __float_as_uint(f[2 * e]);
        const uint32_t u1 = __float_as_uint(f[2 * e + 1]);
        hw[e] = __byte_perm(u0, u1, 0x7632);
        const float t0 = __uint_as_float(u0 & 0xFFFF0000u);
        const float t1 = __uint_as_float(u1 & 0xFFFF0000u);
        const float r0 = f[2 * e] - t0;
        const float r1 = f[2 * e + 1] - t1;
        asm("cvt.rn.bf16x2.f32 %0, %1, %2;" : "=r"(lw[e]) : "f"(r1), "f"(r0));
    }
    hv = make_uint4(hw[0], hw[1], hw[2], hw[3]);
    lv = make_uint4(lw[0], lw[1], lw[2], lw[3]);
}

// ======== bf16 3-pass split GEMM: 128x128 tile, cp.async, ldmatrix =================
#define GK 2048
#define BK 32
#define NKT (GK / BK)
#define GBUF 32768
#define SMEM_GEMM (2 * GBUF)

__global__ __launch_bounds__(256, 2) void gemm_bf16x3(const __nv_bfloat16* __restrict__ Ah,
                                                      const __nv_bfloat16* __restrict__ Al,
                                                      const __nv_bfloat16* __restrict__ Bh,
                                                      const __nv_bfloat16* __restrict__ Bl,
                                                      float* __restrict__ C, int N)
{
    extern __shared__ char smc[];
    const uint32_t sb = smem_u32g(smc);
    const int tid  = threadIdx.x;
    const int warp = tid >> 5, lane = tid & 31;
    const int gid  = lane >> 2, tig = lane & 3;
    const int wm   = (warp & 1) * 64;
    const int wn   = (warp >> 1) * 32;
    const int rowA = blockIdx.y * 128;
    const int rowB = blockIdx.x * 128;

    const int r0s = tid >> 2,         s0s = tid & 3;
    const int r1s = (tid + 256) >> 2, s1s = tid & 3;
    const uint32_t so0 = (uint32_t)(r0s * 64 + ((s0s ^ ((r0s >> 1) & 3)) * 16));
    const uint32_t so1 = (uint32_t)(r1s * 64 + ((s1s ^ ((r1s >> 1) & 3)) * 16));

    const int swm   = ((lane & 7) >> 1) & 3;
    const int rlocA = (lane & 7) + (((lane >> 3) & 1) << 3);
    const int shA   = lane >> 4;
    const int rlocB = (lane & 7) + ((lane >> 4) << 3);
    const int shB   = (lane >> 3) & 1;

    float acc[4][4][4];
#pragma unroll
    for (int i = 0; i < 4; i++)
#pragma unroll
        for (int j = 0; j < 4; j++)
#pragma unroll
            for (int r = 0; r < 4; r++) acc[i][j][r] = 0.f;

    auto stage = [&](int kt, int b) {
        const uint32_t bb = sb + b * GBUF;
        const int kb = kt * BK;
        CP_ASYNC16(bb + so0,         (const char*)(Ah + (size_t)(rowA + r0s) * GK + kb + s0s * 8));
        CP_ASYNC16(bb + so1,         (const char*)(Ah + (size_t)(rowA + r1s) * GK + kb + s1s * 8));
        CP_ASYNC16(bb + 8192  + so0, (const char*)(Al + (size_t)(rowA + r0s) * GK + kb + s0s * 8));
        CP_ASYNC16(bb + 8192  + so1, (const char*)(Al + (size_t)(rowA + r1s) * GK + kb + s1s * 8));
        CP_ASYNC16(bb + 16384 + so0, (const char*)(Bh + (size_t)(rowB + r0s) * GK + kb + s0s * 8));
        CP_ASYNC16(bb + 16384 + so1, (const char*)(Bh + (size_t)(rowB + r1s) * GK + kb + s1s * 8));
        CP_ASYNC16(bb + 24576 + so0, (const char*)(Bl + (size_t)(rowB + r0s) * GK + kb + s0s * 8));
        CP_ASYNC16(bb + 24576 + so1, (const char*)(Bl + (size_t)(rowB + r1s) * GK + kb + s1s * 8));
        CP_COMMIT();
    };

    stage(0, 0);

    for (int kt = 0; kt < NKT; kt++) {
        if (kt + 1 < NKT) {
            stage(kt + 1, (kt + 1) & 1);
            CP_WAIT(1);
        } else {
            CP_WAIT(0);
        }
        __syncthreads();

        const uint32_t base = sb + (kt & 1) * GBUF;
#pragma unroll
        for (int kb = 0; kb < 2; kb++) {
            uint32_t ah[4][4], al[4][4];
#pragma unroll
            for (int tm = 0; tm < 4; tm++) {
                const int r = wm + tm * 16 + rlocA;
                const uint32_t off = (uint32_t)(r * 64 + (((2 * kb + shA) ^ swm) * 16));
                LDSM4(ah[tm], base + off);
                LDSM4(al[tm], base + 8192 + off);
            }
            uint32_t bhf[2][4], blf[2][4];
#pragma unroll
            for (int p = 0; p < 2; p++) {
                const int r = wn + p * 16 + rlocB;
                const uint32_t off = (uint32_t)(r * 64 + (((2 * kb + shB) ^ swm) * 16));
                LDSM4(bhf[p], base + 16384 + off);
                LDSM4(blf[p], base + 24576 + off);
            }
#pragma unroll
            for (int tm = 0; tm < 4; tm++)
#pragma unroll
                for (int tn = 0; tn < 4; tn++) {
                    const uint32_t* bh2 = &bhf[tn >> 1][(tn & 1) * 2];
                    const uint32_t* bl2 = &blf[tn >> 1][(tn & 1) * 2];
                    mma_bf16(acc[tm][tn], ah[tm], bh2);
                    mma_bf16(acc[tm][tn], ah[tm], bl2);
                    mma_bf16(acc[tm][tn], al[tm], bh2);
                }
        }
        __syncthreads();
    }

#pragma unroll
    for (int tm = 0; tm < 4; tm++) {
        const size_t r0 = (size_t)rowA + wm + tm * 16 + gid;
#pragma unroll
        for (int tn = 0; tn < 4; tn++) {
            const int cn = rowB + wn + tn * 8 + tig * 2;
            *(float2*)(C + r0 * N + cn)       = make_float2(acc[tm][tn][0], acc[tm][tn][1]);
            *(float2*)(C + (r0 + 8) * N + cn) = make_float2(acc[tm][tn][2], acc[tm][tn][3]);
        }
    }
}

__device__ void atomicMaxFloat(float* addr, float val)
{
    int* ia = (int*)addr;
    int old = *ia;
    while (__int_as_float(old) < val) {
        int assumed = old;
        old = atomicCAS(ia, assumed, __float_as_int(val));
        if (old == assumed) break;
    }
}

__global__ void init_stab_kernel(float* stab)
{
    if (threadIdx.x < B_SZ * NKV) stab[threadIdx.x] = -3.4e38f;
}

// ---------------- prep proj: build pre-swizzled bf16 hi/lo tile image --------------
__global__ void prep_proj(const float* __restrict__ proj, char* __restrict__ img)
{
    const int t = blockIdx.x * blockDim.x + threadIdx.x;
    const int row = t >> 3, g = t & 7;
    const int chunk = g >> 2, slot = g & 3;
    float f[8];
    *(float4*)&f[0] = *(const float4*)(proj + row * 64 + g * 8);
    *(float4*)&f[4] = *(const float4*)(proj + row * 64 + g * 8 + 4);
    uint4 hv, lv;
    pack8(f, hv, lv);
    const uint32_t off = (uint32_t)(row * 64 + ((slot ^ ((row >> 1) & 3)) * 16));
    *(uint4*)(img + chunk * 16384 + off)         = hv;
    *(uint4*)(img + 32768 + chunk * 16384 + off) = lv;
}

// ---------------- tensor-core favor xp (q+k heads, RoPE fused) ---------------------
#define FXP_ASF   65536
#define FXP_A     (FXP_ASF + 17408)
#define FXP_SQS   (FXP_A + 16384)
#define FXP_RED   (FXP_SQS + 256)
#define SMEM_FXP  (FXP_RED + 1024)

__global__ __launch_bounds__(256, 1) void favor_xp_tc(const float* __restrict__ x,
                                                      const float* __restrict__ cosp,
                                                      const float* __restrict__ sinp,
                                                      const char* __restrict__ projimg,
                                                      float* __restrict__ xpk,
                                                      __nv_bfloat16* __restrict__ pqh,
                                                      __nv_bfloat16* __restrict__ pql,
                                                      float* __restrict__ sqk,
                                                      float* __restrict__ stab)
{
    extern __shared__ char smc[];
    const uint32_t sb = smem_u32g(smc);
    float* Asf = (float*)(smc + FXP_ASF);
    float* sqs = (float*)(smc + FXP_SQS);
    float* red = (float*)(smc + FXP_RED);

    const float DN = 0.35355339059327373f;
    const int blk = blockIdx.x, hy = blockIdx.y, b = blockIdx.z;
    const bool isq = (hy < NH);
    const int h = isq ? hy : hy - NH;
    const int xcol = isq ? (h * 64) : (2048 + h * 64);
    const int s0 = blk * 64;
    const int tid = threadIdx.x;
    const int warp = tid >> 5, lane = tid & 31;
    const int gid = lane >> 2, tig = lane & 3;

#pragma unroll
    for (int i = 0; i < 16; i++) {
        const uint32_t off = (uint32_t)(tid * 16 + i * 4096);
        CP_ASYNC16(sb + off, projimg + off);
    }
    CP_COMMIT();

#pragma unroll
    for (int r = 0; r < 4; r++) {
        int l = tid + r * 256;
        int tok = l >> 4, q4 = (l & 15) << 2;
        float4 vv = *(const float4*)(x + (size_t)(b * S_LEN + s0 + tok) * QKVW + xcol + q4);
        Asf[tok * 68 + q4 + 0] = vv.x * DN;
        Asf[tok * 68 + q4 + 1] = vv.y * DN;
        Asf[tok * 68 + q4 + 2] = vv.z * DN;
        Asf[tok * 68 + q4 + 3] = vv.w * DN;
    }
    __syncthreads();

#pragma unroll
    for (int r = 0; r < 8; r++) {
        int idx = tid + r * 256;
        int tok = idx >> 5, p = idx & 31;
        const size_t crow = (size_t)(b * S_LEN + s0 + tok) * 64;
        const float c1 = cosp[crow + p],      sn1 = sinp[crow + p];
        const float c2 = cosp[crow + 32 + p], sn2 = sinp[crow + 32 + p];
        float a  = Asf[tok * 68 + p];
        float b2 = Asf[tok * 68 + p + 32];
        Asf[tok * 68 + p]      = a * c1 - b2 * sn1;
        Asf[tok * 68 + p + 32] = b2 * c2 + a * sn2;
    }
    __syncthreads();

    if (tid < 64) {
        float ssum = 0.f;
#pragma unroll
        for (int d = 0; d < 64; d++) { float vv = Asf[tid * 68 + d]; ssum += vv * vv; }
        sqs[tid] = 0.5f * ssum;
        if (!isq) sqk[((size_t)(b * NKV + h)) * S_LEN + s0 + tid] = 0.5f * ssum;
    }
#pragma unroll
    for (int r = 0; r < 2; r++) {
        int s = tid + r * 256;
        int row = s >> 3, g = s & 7;
        int chunk = g >> 2, slot = g & 3;
        float f[8];
        *(float4*)&f[0] = *(const float4*)(Asf + row * 68 + g * 8);
        *(float4*)&f[4] = *(const float4*)(Asf + row * 68 + g * 8 + 4);
        uint4 hv, lv;
        pack8(f, hv, lv);
        const uint32_t off = (uint32_t)(row * 64 + ((slot ^ ((row >> 1) & 3)) * 16));
        *(uint4*)(smc + FXP_A + chunk * 4096 + off)        = hv;
        *(uint4*)(smc + FXP_A + 8192 + chunk * 4096 + off) = lv;
    }
    CP_WAIT(0);
    __syncthreads();

    const int wm = (warp & 1) * 32;
    const int wn = (warp >> 1) * 64;
    const int swm   = ((lane & 7) >> 1) & 3;
    const int rlocA = (lane & 7) + (((lane >> 3) & 1) << 3);
    const int shA   = lane >> 4;
    const int rlocB = (lane & 7) + ((lane >> 4) << 3);
    const int shB   = (lane >> 3) & 1;

    float acc[2][8][4];
#pragma unroll
    for (int i = 0; i < 2; i++)
#pragma unroll
        for (int j = 0; j < 8; j++)
#pragma unroll
            for (int r = 0; r < 4; r++) acc[i][j][r] = 0.f;

#pragma unroll
    for (int ks = 0; ks < 4; ks++) {
        const int chunk = ks >> 1, kb = ks & 1;
        const uint32_t aBase = sb + FXP_A + chunk * 4096;
        const uint32_t bBase = sb + chunk * 16384;
        uint32_t ah[2][4], al[2][4];
#pragma unroll
        for (int tm = 0; tm < 2; tm++) {
            const int r = wm + tm * 16 + rlocA;
            const uint32_t off = (uint32_t)(r * 64 + (((2 * kb + shA) ^ swm) * 16));
            LDSM4(ah[tm], aBase + off);
            LDSM4(al[tm], aBase + 8192 + off);
        }
        uint32_t bhf[4][4], blf[4][4];
#pragma unroll
        for (int p = 0; p < 4; p++) {
            const int r = wn + p * 16 + rlocB;
            const uint32_t off = (uint32_t)(r * 64 + (((2 * kb + shB) ^ swm) * 16));
            LDSM4(bhf[p], bBase + off);
            LDSM4(blf[p], bBase + 32768 + off);
        }
#pragma unroll
        for (int tm = 0; tm < 2; tm++)
#pragma unroll
            for (int tn = 0; tn < 8; tn++) {
                const uint32_t* bh2 = &bhf[tn >> 1][(tn & 1) * 2];
                const uint32_t* bl2 = &blf[tn >> 1][(tn & 1) * 2];
                mma_bf16(acc[tm][tn], ah[tm], bh2);
                mma_bf16(acc[tm][tn], ah[tm], bl2);
                mma_bf16(acc[tm][tn], al[tm], bh2);
            }
    }

    if (isq) {
#pragma unroll
        for (int tm = 0; tm < 2; tm++) {
            float m0 = -3.4e38f, m1 = -3.4e38f;
#pragma unroll
            for (int tn = 0; tn < 8; tn++) {
                m0 = fmaxf(m0, fmaxf(acc[tm][tn][0], acc[tm][tn][1]));
                m1 = fmaxf(m1, fmaxf(acc[tm][tn][2], acc[tm][tn][3]));
            }
#pragma unroll
            for (int o = 1; o <= 2; o <<= 1) {
                m0 = fmaxf(m0, __shfl_xor_sync(0xffffffffu, m0, o));
                m1 = fmaxf(m1, __shfl_xor_sync(0xffffffffu, m1, o));
            }
            if (tig == 0) {
                red[(wm + tm * 16 + gid) * 4 + (warp >> 1)]     = m0;
                red[(wm + tm * 16 + gid + 8) * 4 + (warp >> 1)] = m1;
            }
        }
        __syncthreads();
        const size_t rowbase = (size_t)(b * NH + h) * S_LEN + s0;
#pragma unroll
        for (int tm = 0; tm < 2; tm++) {
            const int r0 = wm + tm * 16 + gid, r1 = r0 + 8;
            const float m0 = fmaxf(fmaxf(red[r0 * 4], red[r0 * 4 + 1]),
                                   fmaxf(red[r0 * 4 + 2], red[r0 * 4 + 3]));
            const float m1 = fmaxf(fmaxf(red[r1 * 4], red[r1 * 4 + 1]),
                                   fmaxf(red[r1 * 4 + 2], red[r1 * 4 + 3]));
            const float s0v = sqs[r0] + m0, s1v = sqs[r1] + m1;
#pragma unroll
            for (int tn = 0; tn < 8; tn++) {
                const int col = wn + tn * 8 + tig * 2;
                float e0 = (__expf(acc[tm][tn][0] - s0v) + 1e-6f) * 0.0625f;
                float e1 = (__expf(acc[tm][tn][1] - s0v) + 1e-6f) * 0.0625f;
                float e2 = (__expf(acc[tm][tn][2] - s1v) + 1e-6f) * 0.0625f;
                float e3 = (__expf(acc[tm][tn][3] - s1v) + 1e-6f) * 0.0625f;
                uint32_t u0 = __float_as_uint(e0), u1 = __float_as_uint(e1);
                uint32_t h01 = __byte_perm(u0, u1, 0x7632), l01;
                float q0 = e0 - __uint_as_float(u0 & 0xFFFF0000u);
                float q1 = e1 - __uint_as_float(u1 & 0xFFFF0000u);
                asm("cvt.rn.bf16x2.f32 %0, %1, %2;" : "=r"(l01) : "f"(q1), "f"(q0));
                uint32_t u2 = __float_as_uint(e2), u3 = __float_as_uint(e3);
                uint32_t h23 = __byte_perm(u2, u3, 0x7632), l23;
                float q2 = e2 - __uint_as_float(u2 & 0xFFFF0000u);
                float q3 = e3 - __uint_as_float(u3 & 0xFFFF0000u);
                asm("cvt.rn.bf16x2.f32 %0, %1, %2;" : "=r"(l23) : "f"(q3), "f"(q2));
                *(uint32_t*)(pqh + (rowbase + r0) * M_FEAT + col) = h01;
                *(uint32_t*)(pql + (rowbase + r0) * M_FEAT + col) = l01;
                *(uint32_t*)(pqh + (rowbase + r1) * M_FEAT + col) = h23;
                *(uint32_t*)(pql + (rowbase + r1) * M_FEAT + col) = l23;
            }
        }
    } else {
        const size_t rowbase = (size_t)(b * NKV + h) * S_LEN + s0;
        float mx = -3.4e38f;
#pragma unroll
        for (int tm = 0; tm < 2; tm++) {
            const int r0 = wm + tm * 16 + gid, r1 = r0 + 8;
#pragma unroll
            for (int tn = 0; tn < 8; tn++) {
                const int col = wn + tn * 8 + tig * 2;
                *(float2*)(xpk + (rowbase + r0) * M_FEAT + col) =
                    make_float2(acc[tm][tn][0], acc[tm][tn][1]);
                *(float2*)(xpk + (rowbase + r1) * M_FEAT + col) =
                    make_float2(acc[tm][tn][2], acc[tm][tn][3]);
                mx = fmaxf(mx, fmaxf(fmaxf(acc[tm][tn][0], acc[tm][tn][1]),
                                     fmaxf(acc[tm][tn][2], acc[tm][tn][3])));
            }
        }
        red[tid] = mx;
        __syncthreads();
        for (int st = 128; st > 0; st >>= 1) {
            if (tid < st) red[tid] = fmaxf(red[tid], red[tid + st]);
            __syncthreads();
        }
        if (tid == 0) atomicMaxFloat(&stab[b * NKV + h], red[0]);
    }
}

// ------- per-chunk kv/kz with fused k-exp + phi_k hi/lo output. grid (NC,NKV,B) -----
__global__ __launch_bounds__(256) void kv_chunk(const float* __restrict__ xpk,
                                                const float* __restrict__ sqk,
                                                const float* __restrict__ stab,
                                                __nv_bfloat16* __restrict__ pkh,
                                                __nv_bfloat16* __restrict__ pkl,
                                                const float* __restrict__ qkv,
                                                float* __restrict__ kv,
                                                float* __restrict__ kz)
{
    __shared__ float ps[16][256];
    __shared__ float vs[16][64];
    const int c = blockIdx.x, h = blockIdx.y, b = blockIdx.z;
    const int tid = threadIdx.x;
    const float stabv = stab[b * NKV + h];
    float acc[64];
#pragma unroll
    for (int d = 0; d < 64; d++) acc[d] = 0.f;
    float accz = 0.f;
    const size_t prow = (size_t)(b * NKV + h) * S_LEN + c * CHUNK;
    const size_t vrow = (size_t)b * S_LEN + c * CHUNK;

    for (int i0 = 0; i0 < CHUNK; i0 += 16) {
#pragma unroll
        for (int ii = 0; ii < 16; ii++) {
            const size_t idx = (prow + i0 + ii) * M_FEAT + tid;
            const float sqv = sqk[prow + i0 + ii];
            const float v = (__expf(xpk[idx] - sqv - stabv) + 1e-6f) * 0.0625f;
            ps[ii][tid] = v;
            const uint32_t u = __float_as_uint(v);
            const float t = __uint_as_float(u & 0xFFFF0000u);
            pkh[idx] = __ushort_as_bfloat16((unsigned short)(u >> 16));
            pkl[idx] = __float2bfloat16(v - t);
        }
#pragma unroll
        for (int j = 0; j < 4; j++) {
            int l = tid + j * 256;
            int ii = l >> 6, d = l & 63;
            vs[ii][d] = qkv[(vrow + i0 + ii) * QKVW + 2560 + h * 64 + d];
        }
        __syncthreads();
#pragma unroll
        for (int ii = 0; ii < 16; ii++) {
            float a = ps[ii][tid];
            accz += a;
#pragma unroll
            for (int d4 = 0; d4 < 64; d4 += 4) {
                float4 vv = *(const float4*)&vs[ii][d4];
                acc[d4 + 0] += a * vv.x; acc[d4 + 1] += a * vv.y;
                acc[d4 + 2] += a * vv.z; acc[d4 + 3] += a * vv.w;
            }
        }
        __syncthreads();
    }
    const size_t ob = (((size_t)(b * NKV + h) * NC + c) * M_FEAT + tid) * D_HEAD;
#pragma unroll
    for (int d4 = 0; d4 < 64; d4 += 4)
        *(float4*)(kv + ob + d4) = make_float4(acc[d4], acc[d4 + 1], acc[d4 + 2], acc[d4 + 3]);
    kz[((size_t)(b * NKV + h) * NC + c) * M_FEAT + tid] = accz;
}

// ---------------- exclusive prefix over chunk axis, in place ----------------------
__global__ void cumsum_k(float* __restrict__ kv, float* __restrict__ kz)
{
    const int tid = blockIdx.x * blockDim.x + threadIdx.x;
    const int KVSZ = M_FEAT * D_HEAD;
    if (tid < B_SZ * NKV * KVSZ) {
        int bh = tid / KVSZ, md = tid % KVSZ;
        float run = 0.f;
        for (int c = 0; c < NC; c++) {
            size_t idx = ((size_t)bh * NC + c) * KVSZ + md;
            float t = kv[idx]; kv[idx] = run; run += t;
        }
    } else {
        int t2 = tid - B_SZ * NKV * KVSZ;
        if (t2 < B_SZ * NKV * M_FEAT) {
            int bh = t2 / M_FEAT, m = t2 % M_FEAT;
            float run = 0.f;
            for (int c = 0; c < NC; c++) {
                size_t idx = ((size_t)bh * NC + c) * M_FEAT + m;
                float tz = kz[idx]; kz[idx] = run; run += tz;
            }
        }
    }
}

// ============ tensor-core chunked causal linear attention. grid (NC, NH, B) ========
// smem: Ss fp32 [0, 67584) | AB0 [67584, +32K) | AB1 [+32K) | Zs
#define SPITCH 132
#define ATT_AB0 (128 * SPITCH * 4)
#define ATT_AB1 (ATT_AB0 + 32768)
#define ATT_ZS  (ATT_AB1 + 32768)
#define SMEM_ATTN (ATT_ZS + 512)

__global__ __launch_bounds__(256, 1) void attn_tc(
    const __nv_bfloat16* __restrict__ pqh, const __nv_bfloat16* __restrict__ pql,
    const __nv_bfloat16* __restrict__ pkh, const __nv_bfloat16* __restrict__ pkl,
    const float* __restrict__ qkv, const float* __restrict__ kvpre,
    const float* __restrict__ kzpre,
    __nv_bfloat16* __restrict__ ath, __nv_bfloat16* __restrict__ atl)
{
    extern __shared__ float sm[];
    char* smcb = (char*)sm;
    float* Ss = sm;
    float* Zs = (float*)(smcb + ATT_ZS);
    const uint32_t sbase = smem_u32g(smcb);
    const uint32_t ab0 = sbase + ATT_AB0;
    const uint32_t ab1 = sbase + ATT_AB1;

    const int c = blockIdx.x, h = blockIdx.y, b = blockIdx.z;
    const int kvh = h >> 2;
    const int tid = threadIdx.x;
    const int warp = tid >> 5, lane = tid & 31;
    const int gid = lane >> 2, tig = lane & 3;

    const size_t qbase  = (size_t)(b * NH + h) * S_LEN + c * CHUNK;
    const size_t kbase  = (size_t)(b * NKV + kvh) * S_LEN + c * CHUNK;
    const size_t vrow0  = (size_t)b * S_LEN + c * CHUNK;
    const size_t kvbase = ((size_t)(b * NKV + kvh) * NC + c) * (size_t)(M_FEAT * D_HEAD);
    const size_t kzbase = ((size_t)(b * NKV + kvh) * NC + c) * M_FEAT;

    const int strow = tid & 127;
    const int s0 = tid >> 7;

    const int swm   = ((lane & 7) >> 1) & 3;
    const int rlocA = (lane & 7) + (((lane >> 3) & 1) << 3);
    const int shA   = lane >> 4;
    const int rlocB = (lane & 7) + ((lane >> 4) << 3);
    const int shB   = (lane >> 3) & 1;

    // ======================= Phase 1: scores (cp.async double-buffered) ============
    {
        const int wm = (warp & 1) * 64, wn = (warp >> 1) * 32;
        float acc[4][4][4];
#pragma unroll
        for (int i = 0; i < 4; i++)
#pragma unroll
            for (int j = 0; j < 4; j++)
#pragma unroll
                for (int r = 0; r < 4; r++) acc[i][j][r] = 0.f;

        auto stage1 = [&](int m0, uint32_t bb) {
#pragma unroll
            for (int si = 0; si < 2; si++) {
                const int s = s0 + si * 2;
                const uint32_t off = (uint32_t)(strow * 64 + ((s ^ ((strow >> 1) & 3)) * 16));
                const size_t ia = (qbase + strow) * M_FEAT + m0 + s * 8;
                const size_t ib = (kbase + strow) * M_FEAT + m0 + s * 8;
                CP_ASYNC16(bb + off,         (const char*)(pqh + ia));
                CP_ASYNC16(bb + 8192  + off, (const char*)(pql + ia));
                CP_ASYNC16(bb + 16384 + off, (const char*)(pkh + ib));
                CP_ASYNC16(bb + 24576 + off, (const char*)(pkl + ib));
            }
            CP_COMMIT();
        };

        stage1(0, ab0);
        for (int t = 0; t < 8; t++) {
            if (t + 1 < 8) {
                stage1((t + 1) * 32, (t + 1) & 1 ? ab1 : ab0);
                CP_WAIT(1);
            } else {
                CP_WAIT(0);
            }
            __syncthreads();
            const uint32_t bb = (t & 1) ? ab1 : ab0;
#pragma unroll
            for (int kb = 0; kb < 2; kb++) {
                uint32_t ah[4][4], al[4][4];
#pragma unroll
                for (int tm = 0; tm < 4; tm++) {
                    const int r = wm + tm * 16 + rlocA;
                    const uint32_t off = (uint32_t)(r * 64 + (((2 * kb + shA) ^ swm) * 16));
                    LDSM4(ah[tm], bb + off);
                    LDSM4(al[tm], bb + 8192 + off);
                }
                uint32_t bhf[2][4], blf[2][4];
#pragma unroll
                for (int p = 0; p < 2; p++) {
                    const int r = wn + p * 16 + rlocB;
                    const uint32_t off = (uint32_t)(r * 64 + (((2 * kb + shB) ^ swm) * 16));
                    LDSM4(bhf[p], bb + 16384 + off);
                    LDSM4(blf[p], bb + 24576 + off);
                }
#pragma unroll
                for (int tm = 0; tm < 4; tm++)
#pragma unroll
                    for (int tn = 0; tn < 4; tn++) {
                        const uint32_t* bh2 = &bhf[tn >> 1][(tn & 1) * 2];
                        const uint32_t* bl2 = &blf[tn >> 1][(tn & 1) * 2];
                        mma_bf16(acc[tm][tn], ah[tm], bh2);
                        mma_bf16(acc[tm][tn], ah[tm], bl2);
                        mma_bf16(acc[tm][tn], al[tm], bh2);
                    }
            }
            __syncthreads();
        }
#pragma unroll
        for (int tm = 0; tm < 4; tm++) {
            const int r0 = wm + tm * 16 + gid;
            const int r1 = r0 + 8;
#pragma unroll
            for (int tn = 0; tn < 4; tn++) {
                const int col = wn + tn * 8 + tig * 2;
                Ss[r0 * SPITCH + col]     = (col     <= r0) ? acc[tm][tn][0] : 0.f;
                Ss[r0 * SPITCH + col + 1] = (col + 1 <= r0) ? acc[tm][tn][1] : 0.f;
                Ss[r1 * SPITCH + col]     = (col     <= r1) ? acc[tm][tn][2] : 0.f;
                Ss[r1 * SPITCH + col + 1] = (col + 1 <= r1) ? acc[tm][tn][3] : 0.f;
            }
        }
    }
    __syncthreads();

    // ======================= Phase 2: inter+intra (+z col 64) =======================
    char* Ah = smcb + ATT_AB0;
    char* Al = Ah + 8192;
    char* Bh = Al + 8192;
    char* Bl = Bh + 8192;
    const uint32_t sbAh = ab0, sbAl = ab0 + 8192, sbBh = ab0 + 16384, sbBl = ab0 + 24576;

    const int wm2 = (warp & 3) * 32, wn2 = (warp >> 2) * 40;
    float acc2[2][5][4];
#pragma unroll
    for (int i = 0; i < 2; i++)
#pragma unroll
        for (int j = 0; j < 5; j++)
#pragma unroll
            for (int r = 0; r < 4; r++) acc2[i][j][r] = 0.f;

    for (int cc = 0; cc < 12; cc++) {
#pragma unroll
        for (int si = 0; si < 2; si++) {
            const int s = s0 + si * 2;
            const uint32_t off = (uint32_t)(strow * 64 + ((s ^ ((strow >> 1) & 3)) * 16));
            if (cc < 8) {
                const size_t ia = (qbase + strow) * M_FEAT + cc * 32 + s * 8;
                *(uint4*)(Ah + off) = *(const uint4*)(pqh + ia);
                *(uint4*)(Al + off) = *(const uint4*)(pql + ia);
            } else {
                float f[8];
                const float* pa = Ss + strow * SPITCH + (cc - 8) * 32 + s * 8;
                *(float4*)&f[0] = *(const float4*)pa;
                *(float4*)&f[4] = *(const float4*)(pa + 4);
                uint4 hv, lv;
                pack8(f, hv, lv);
                *(uint4*)(Ah + off) = hv;
                *(uint4*)(Al + off) = lv;
            }

            if (strow < 96) {
                float g[8];
                if (strow < 64) {
                    if (cc < 8) {
#pragma unroll
                        for (int e = 0; e < 8; e++)
                            g[e] = kvpre[kvbase + (size_t)(cc * 32 + s * 8 + e) * 64 + strow];
                    } else {
#pragma unroll
                        for (int e = 0; e < 8; e++)
                            g[e] = qkv[(vrow0 + (cc - 8) * 32 + s * 8 + e) * QKVW + 2560 + kvh * 64 + strow];
                    }
                } else if (strow == 64) {
                    if (cc < 8) {
#pragma unroll
                        for (int e = 0; e < 8; e++)
                            g[e] = kzpre[kzbase + cc * 32 + s * 8 + e];
                    } else {
#pragma unroll
                        for (int e = 0; e < 8; e++) g[e] = 1.f;
                    }
                } else {
#pragma unroll
                    for (int e = 0; e < 8; e++) g[e] = 0.f;
                }
                uint4 hv, lv;
                pack8(g, hv, lv);
                *(uint4*)(Bh + off) = hv;
                *(uint4*)(Bl + off) = lv;
            }
        }
        __syncthreads();
#pragma unroll
        for (int kb = 0; kb < 2; kb++) {
            uint32_t ah2[2][4], al2[2][4], bh2[3][4], bl2[3][4];
#pragma unroll
            for (int tm = 0; tm < 2; tm++) {
                const int r = wm2 + tm * 16 + rlocA;
                const uint32_t off = (uint32_t)(r * 64 + (((2 * kb + shA) ^ swm) * 16));
                LDSM4(ah2[tm], sbAh + off);
                LDSM4(al2[tm], sbAl + off);
            }
#pragma unroll
            for (int p = 0; p < 3; p++) {
                const int r = wn2 + p * 16 + rlocB;
                const uint32_t off = (uint32_t)(r * 64 + (((2 * kb + shB) ^ swm) * 16));
                LDSM4(bh2[p], sbBh + off);
                LDSM4(bl2[p], sbBl + off);
            }
#pragma unroll
            for (int tm = 0; tm < 2; tm++)
#pragma unroll
                for (int tn = 0; tn < 5; tn++) {
                    const uint32_t* bh_ = &bh2[tn >> 1][(tn & 1) * 2];
                    const uint32_t* bl_ = &bl2[tn >> 1][(tn & 1) * 2];
                    mma_bf16(acc2[tm][tn], ah2[tm], bh_);
                    mma_bf16(acc2[tm][tn], ah2[tm], bl_);
                    mma_bf16(acc2[tm][tn], al2[tm], bh_);
                }
        }
        __syncthreads();
    }

    if ((warp >> 2) == 1 && tig == 0) {
#pragma unroll
        for (int tm = 0; tm < 2; tm++) {
            const int r = wm2 + tm * 16 + gid;
            Zs[r]     = acc2[tm][3][0];
            Zs[r + 8] = acc2[tm][3][2];
        }
    }
    __syncthreads();

#pragma unroll
    for (int tm = 0; tm < 2; tm++) {
        const int r = wm2 + tm * 16 + gid;
        const float d0 = 1.f / (Zs[r] + 1e-6f);
        const float d1 = 1.f / (Zs[r + 8] + 1e-6f);
#pragma unroll
        for (int tn = 0; tn < 5; tn++) {
            const int col = wn2 + tn * 8 + tig * 2;
            if (col < 64) {
                const size_t ro = ((size_t)b * S_LEN + c * CHUNK + r) * (NH * D_HEAD) + h * 64 + col;
                const size_t ro8 = ro + 8 * (NH * D_HEAD);
                float o0 = acc2[tm][tn][0] * d0, o1 = acc2[tm][tn][1] * d0;
                float o2 = acc2[tm][tn][2] * d1, o3 = acc2[tm][tn][3] * d1;
                __nv_bfloat16 h0 = __float2bfloat16(o0), h1 = __float2bfloat16(o1);
                __nv_bfloat16 h2 = __float2bfloat16(o2), h3 = __float2bfloat16(o3);
                *(__nv_bfloat162*)(ath + ro)  = __nv_bfloat162(h0, h1);
                *(__nv_bfloat162*)(ath + ro8) = __nv_bfloat162(h2, h3);
                *(__nv_bfloat162*)(atl + ro)  =
                    __nv_bfloat162(__float2bfloat16(o0 - __bfloat162float(h0)),
                                   __float2bfloat16(o1 - __bfloat162float(h1)));
                *(__nv_bfloat162*)(atl + ro8) =
                    __nv_bfloat162(__float2bfloat16(o2 - __bfloat162float(h2)),
                                   __float2bfloat16(o3 - __bfloat162float(h3)));
            }
        }
    }
}

// ----------------------------------- launch ---------------------------------------
extern "C" void kernel_launch(void* const* d_in, const int* in_sizes, int n_in,
                              void* d_out, int out_size)
{
    const float* hs   = (const float*)d_in[0];
    const float* cosp = (const float*)d_in[1];
    const float* sinp = (const float*)d_in[2];
    const float* Wq   = (const float*)d_in[3];
    const float* Wk   = (const float*)d_in[4];
    const float* Wv   = (const float*)d_in[5];
    const float* Wo   = (const float*)d_in[6];
    const float* proj = (const float*)d_in[7];
    float* out = (float*)d_out;

    float *qkvp, *xpkp, *sqkp, *stabp, *kvp, *kzp;
    cudaGetSymbolAddress((void**)&qkvp,  g_qkv);
    cudaGetSymbolAddress((void**)&xpkp,  g_xpk);
    cudaGetSymbolAddress((void**)&sqkp,  g_sqk);
    cudaGetSymbolAddress((void**)&stabp, g_stab);
    cudaGetSymbolAddress((void**)&kvp,   g_kv);
    cudaGetSymbolAddress((void**)&kzp,   g_kz);
    char* pimg;
    cudaGetSymbolAddress((void**)&pimg, g_projimg);

    __nv_bfloat16 *pqh, *pql, *pkh, *pkl, *hsh, *hsl, *ath, *atl, *wh, *wl;
    cudaGetSymbolAddress((void**)&pqh, g_pqh);
    cudaGetSymbolAddress((void**)&pql, g_pql);
    cudaGetSymbolAddress((void**)&pkh, g_pkh);
    cudaGetSymbolAddress((void**)&pkl, g_pkl);
    cudaGetSymbolAddress((void**)&hsh, g_hsh);
    cudaGetSymbolAddress((void**)&hsl, g_hsl);
    cudaGetSymbolAddress((void**)&ath, g_ath);
    cudaGetSymbolAddress((void**)&atl, g_atl);
    cudaGetSymbolAddress((void**)&wh,  g_wh);
    cudaGetSymbolAddress((void**)&wl,  g_wl);

    cudaFuncSetAttribute(gemm_bf16x3, cudaFuncAttributeMaxDynamicSharedMemorySize, SMEM_GEMM);
    cudaFuncSetAttribute(attn_tc, cudaFuncAttributeMaxDynamicSharedMemorySize, SMEM_ATTN);
    cudaFuncSetAttribute(favor_xp_tc, cudaFuncAttributeMaxDynamicSharedMemorySize, SMEM_FXP);

    // ---- splits + proj image ----
    split_bf16<<<(HS_ELEMS / 4 + 255) / 256, 256>>>(hs, hsh, hsl, HS_ELEMS / 4);
    split_bf16<<<(HID_ * HID_ / 4 + 255) / 256, 256>>>(Wq, wh + WQ_OFF, wl + WQ_OFF, HID_ * HID_ / 4);
    split_bf16<<<(512 * HID_ / 4 + 255) / 256, 256>>>(Wk, wh + WK_OFF, wl + WK_OFF, 512 * HID_ / 4);
    split_bf16<<<(512 * HID_ / 4 + 255) / 256, 256>>>(Wv, wh + WV_OFF, wl + WV_OFF, 512 * HID_ / 4);
    split_bf16<<<(HID_ * HID_ / 4 + 255) / 256, 256>>>(Wo, wh + WO_OFF, wl + WO_OFF, HID_ * HID_ / 4);
    prep_proj<<<8, 256>>>(proj, pimg);

    // ---- fused QKV projection ----
    gemm_bf16x3<<<dim3(QKVW / 128, 32), 256, SMEM_GEMM>>>(hsh, hsl, wh, wl, qkvp, QKVW);

    // ---- favor features on tensor cores (q+k merged, RoPE fused) ----
    init_stab_kernel<<<1, 32>>>(stabp);
    favor_xp_tc<<<dim3(S_LEN / 64, NH + NKV, B_SZ), 256, SMEM_FXP>>>(
        qkvp, cosp, sinp, pimg, xpkp, pqh, pql, sqkp, stabp);

    // ---- chunked linear attention ----
    kv_chunk<<<dim3(NC, NKV, B_SZ), 256>>>(xpkp, sqkp, stabp, pkh, pkl, qkvp, kvp, kzp);
    cumsum_k<<<(B_SZ * NKV * (M_FEAT * D_HEAD + M_FEAT) + 255) / 256, 256>>>(kvp, kzp);
    attn_tc<<<dim3(NC, NH, B_SZ), 256, SMEM_ATTN>>>(pqh, pql, pkh, pkl, qkvp, kvp, kzp, ath, atl);

    // ---- output projection ----
    gemm_bf16x3<<<dim3(16, 32), 256, SMEM_GEMM>>>(ath, atl, wh + WO_OFF, wl + WO_OFF, out, 2048);
}

// round 16
// speedup vs baseline: 1.9689x; 1.0614x over previous
#include <cuda_runtime.h>
#include <cuda_bf16.h>
#include <math.h>
#include <stdint.h>

#define B_SZ   2
#define S_LEN  2048
#define HID_   2048
#define NH     32
#define NKV    8
#define D_HEAD 64
#define M_FEAT 256
#define NC     16
#define CHUNK  128
#define QKVW   3072

// ---------------- scratch (device globals; no allocations allowed) ----------------
__device__ float g_qkv [(size_t)B_SZ * S_LEN * QKVW];
__device__ float g_xpk [(size_t)B_SZ * NKV * S_LEN * M_FEAT];
__device__ float g_sqk [B_SZ * NKV * S_LEN];
__device__ float g_stab[B_SZ * NKV];
__device__ float g_kv  [B_SZ * NKV * NC * M_FEAT * D_HEAD];
__device__ float g_kz  [B_SZ * NKV * NC * M_FEAT];
__device__ __align__(16) char g_projimg[65536];

#define PHIQ_E ((size_t)B_SZ * NH  * S_LEN * M_FEAT)
#define PHIK_E ((size_t)B_SZ * NKV * S_LEN * M_FEAT)
#define HS_ELEMS  (B_SZ * S_LEN * HID_)
#define W_ELEMS   (QKVW * HID_ + HID_ * HID_)
__device__ __align__(16) __nv_bfloat16 g_pqh[PHIQ_E];
__device__ __align__(16) __nv_bfloat16 g_pql[PHIQ_E];
__device__ __align__(16) __nv_bfloat16 g_pkh[PHIK_E];
__device__ __align__(16) __nv_bfloat16 g_pkl[PHIK_E];
__device__ __align__(16) __nv_bfloat16 g_hsh[HS_ELEMS];
__device__ __align__(16) __nv_bfloat16 g_hsl[HS_ELEMS];
__device__ __align__(16) __nv_bfloat16 g_ath[HS_ELEMS];
__device__ __align__(16) __nv_bfloat16 g_atl[HS_ELEMS];
__device__ __align__(16) __nv_bfloat16 g_wh [W_ELEMS];
__device__ __align__(16) __nv_bfloat16 g_wl [W_ELEMS];

#define WQ_OFF 0
#define WK_OFF (HID_ * HID_)
#define WV_OFF (WK_OFF + 512 * HID_)
#define WO_OFF (WV_OFF + 512 * HID_)

// =================== fp32 -> bf16 hi/lo split (elementwise, x4 vec) ================
__global__ void split_bf16(const float* __restrict__ x, __nv_bfloat16* __restrict__ h,
                           __nv_bfloat16* __restrict__ l, int n4)
{
    int i = blockIdx.x * blockDim.x + threadIdx.x;
    if (i >= n4) return;
    float4 v = ((const float4*)x)[i];
    __nv_bfloat16 h0 = __float2bfloat16(v.x), h1 = __float2bfloat16(v.y);
    __nv_bfloat16 h2 = __float2bfloat16(v.z), h3 = __float2bfloat16(v.w);
    __nv_bfloat162* hp = (__nv_bfloat162*)h;
    hp[2 * i]     = __nv_bfloat162(h0, h1);
    hp[2 * i + 1] = __nv_bfloat162(h2, h3);
    __nv_bfloat162* lp = (__nv_bfloat162*)l;
    lp[2 * i]     = __nv_bfloat162(__float2bfloat16(v.x - __bfloat162float(h0)),
                                   __float2bfloat16(v.y - __bfloat162float(h1)));
    lp[2 * i + 1] = __nv_bfloat162(__float2bfloat16(v.z - __bfloat162float(h2)),
                                   __float2bfloat16(v.w - __bfloat162float(h3)));
}

// ===================== shared helpers for tensor-core kernels ======================
__device__ __forceinline__ uint32_t smem_u32g(const void* p)
{
    uint32_t a;
    asm("{ .reg .u64 t; cvta.to.shared.u64 t, %1; cvt.u32.u64 %0, t; }" : "=r"(a) : "l"(p));
    return a;
}

#define LDSM4(r, a) \
    asm volatile("ldmatrix.sync.aligned.m8n8.x4.shared.b16 {%0,%1,%2,%3}, [%4];" \
                 : "=r"((r)[0]), "=r"((r)[1]), "=r"((r)[2]), "=r"((r)[3]) : "r"(a))

#define CP_ASYNC16(dst, src) \
    asm volatile("cp.async.cg.shared.global [%0], [%1], 16;" :: "r"(dst), "l"(src) : "memory")
#define CP_COMMIT() asm volatile("cp.async.commit_group;" ::: "memory")
#define CP_WAIT(n)  asm volatile("cp.async.wait_group %0;" :: "n"(n) : "memory")

__device__ __forceinline__ void mma_bf16(float c[4], const uint32_t a[4], const uint32_t b[2])
{
    asm volatile("mma.sync.aligned.m16n8k16.row.col.f32.bf16.bf16.f32 "
                 "{%0,%1,%2,%3}, {%4,%5,%6,%7}, {%8,%9}, {%0,%1,%2,%3};"
                 : "+f"(c[0]), "+f"(c[1]), "+f"(c[2]), "+f"(c[3])
                 : "r"(a[0]), "r"(a[1]), "r"(a[2]), "r"(a[3]), "r"(b[0]), "r"(b[1]));
}

// cheap hi/lo split: hi = bf16-truncate (PRMT), lo = RN(residual) via one bf16x2 cvt
__device__ __forceinline__ void pack8(const float* f, uint4& hv, uint4& lv)
{
    uint32_t hw[4], lw[4];
#pragma unroll
    for (int e = 0; e < 4; e++) {
        const uint32_t u0 = __float_as_uint(f[2 * e]);
        const uint32_t u1 = __float_as_uint(f[2 * e + 1]);
        hw[e] = __byte_perm(u0, u1, 0x7632);
        const float t0 = __uint_as_float(u0 & 0xFFFF0000u);
        const float t1 = __uint_as_float(u1 & 0xFFFF0000u);
        const float r0 = f[2 * e] - t0;
        const float r1 = f[2 * e + 1] - t1;
        asm("cvt.rn.bf16x2.f32 %0, %1, %2;" : "=r"(lw[e]) : "f"(r1), "f"(r0));
    }
    hv = make_uint4(hw[0], hw[1], hw[2], hw[3]);
    lv = make_uint4(lw[0], lw[1], lw[2], lw[3]);
}

// ======== bf16 3-pass split GEMM: 128x128 tile, cp.async, ldmatrix =================
#define GK 2048
#define BK 32
#define NKT (GK / BK)
#define GBUF 32768
#define SMEM_GEMM (2 * GBUF)

__global__ __launch_bounds__(256, 2) void gemm_bf16x3(const __nv_bfloat16* __restrict__ Ah,
                                                      const __nv_bfloat16* __restrict__ Al,
                                                      const __nv_bfloat16* __restrict__ Bh,
                                                      const __nv_bfloat16* __restrict__ Bl,
                                                      float* __restrict__ C, int N)
{
    extern __shared__ char smc[];
    const uint32_t sb = smem_u32g(smc);
    const int tid  = threadIdx.x;
    const int warp = tid >> 5, lane = tid & 31;
    const int gid  = lane >> 2, tig = lane & 3;
    const int wm   = (warp & 1) * 64;
    const int wn   = (warp >> 1) * 32;
    const int rowA = blockIdx.y * 128;
    const int rowB = blockIdx.x * 128;

    const int r0s = tid >> 2,         s0s = tid & 3;
    const int r1s = (tid + 256) >> 2, s1s = tid & 3;
    const uint32_t so0 = (uint32_t)(r0s * 64 + ((s0s ^ ((r0s >> 1) & 3)) * 16));
    const uint32_t so1 = (uint32_t)(r1s * 64 + ((s1s ^ ((r1s >> 1) & 3)) * 16));

    const int swm   = ((lane & 7) >> 1) & 3;
    const int rlocA = (lane & 7) + (((lane >> 3) & 1) << 3);
    const int shA   = lane >> 4;
    const int rlocB = (lane & 7) + ((lane >> 4) << 3);
    const int shB   = (lane >> 3) & 1;

    float acc[4][4][4];
#pragma unroll
    for (int i = 0; i < 4; i++)
#pragma unroll
        for (int j = 0; j < 4; j++)
#pragma unroll
            for (int r = 0; r < 4; r++) acc[i][j][r] = 0.f;

    auto stage = [&](int kt, int b) {
        const uint32_t bb = sb + b * GBUF;
        const int kb = kt * BK;
        CP_ASYNC16(bb + so0,         (const char*)(Ah + (size_t)(rowA + r0s) * GK + kb + s0s * 8));
        CP_ASYNC16(bb + so1,         (const char*)(Ah + (size_t)(rowA + r1s) * GK + kb + s1s * 8));
        CP_ASYNC16(bb + 8192  + so0, (const char*)(Al + (size_t)(rowA + r0s) * GK + kb + s0s * 8));
        CP_ASYNC16(bb + 8192  + so1, (const char*)(Al + (size_t)(rowA + r1s) * GK + kb + s1s * 8));
        CP_ASYNC16(bb + 16384 + so0, (const char*)(Bh + (size_t)(rowB + r0s) * GK + kb + s0s * 8));
        CP_ASYNC16(bb + 16384 + so1, (const char*)(Bh + (size_t)(rowB + r1s) * GK + kb + s1s * 8));
        CP_ASYNC16(bb + 24576 + so0, (const char*)(Bl + (size_t)(rowB + r0s) * GK + kb + s0s * 8));
        CP_ASYNC16(bb + 24576 + so1, (const char*)(Bl + (size_t)(rowB + r1s) * GK + kb + s1s * 8));
        CP_COMMIT();
    };

    stage(0, 0);

    for (int kt = 0; kt < NKT; kt++) {
        if (kt + 1 < NKT) {
            stage(kt + 1, (kt + 1) & 1);
            CP_WAIT(1);
        } else {
            CP_WAIT(0);
        }
        __syncthreads();

        const uint32_t base = sb + (kt & 1) * GBUF;
#pragma unroll
        for (int kb = 0; kb < 2; kb++) {
            uint32_t ah[4][4], al[4][4];
#pragma unroll
            for (int tm = 0; tm < 4; tm++) {
                const int r = wm + tm * 16 + rlocA;
                const uint32_t off = (uint32_t)(r * 64 + (((2 * kb + shA) ^ swm) * 16));
                LDSM4(ah[tm], base + off);
                LDSM4(al[tm], base + 8192 + off);
            }
            uint32_t bhf[2][4], blf[2][4];
#pragma unroll
            for (int p = 0; p < 2; p++) {
                const int r = wn + p * 16 + rlocB;
                const uint32_t off = (uint32_t)(r * 64 + (((2 * kb + shB) ^ swm) * 16));
                LDSM4(bhf[p], base + 16384 + off);
                LDSM4(blf[p], base + 24576 + off);
            }
#pragma unroll
            for (int tm = 0; tm < 4; tm++)
#pragma unroll
                for (int tn = 0; tn < 4; tn++) {
                    const uint32_t* bh2 = &bhf[tn >> 1][(tn & 1) * 2];
                    const uint32_t* bl2 = &blf[tn >> 1][(tn & 1) * 2];
                    mma_bf16(acc[tm][tn], ah[tm], bh2);
                    mma_bf16(acc[tm][tn], ah[tm], bl2);
                    mma_bf16(acc[tm][tn], al[tm], bh2);
                }
        }
        __syncthreads();
    }

#pragma unroll
    for (int tm = 0; tm < 4; tm++) {
        const size_t r0 = (size_t)rowA + wm + tm * 16 + gid;
#pragma unroll
        for (int tn = 0; tn < 4; tn++) {
            const int cn = rowB + wn + tn * 8 + tig * 2;
            *(float2*)(C + r0 * N + cn)       = make_float2(acc[tm][tn][0], acc[tm][tn][1]);
            *(float2*)(C + (r0 + 8) * N + cn) = make_float2(acc[tm][tn][2], acc[tm][tn][3]);
        }
    }
}

__device__ void atomicMaxFloat(float* addr, float val)
{
    int* ia = (int*)addr;
    int old = *ia;
    while (__int_as_float(old) < val) {
        int assumed = old;
        old = atomicCAS(ia, assumed, __float_as_int(val));
        if (old == assumed) break;
    }
}

__global__ void init_stab_kernel(float* stab)
{
    if (threadIdx.x < B_SZ * NKV) stab[threadIdx.x] = -3.4e38f;
}

// ---------------- prep proj: build pre-swizzled bf16 hi/lo tile image --------------
__global__ void prep_proj(const float* __restrict__ proj, char* __restrict__ img)
{
    const int t = blockIdx.x * blockDim.x + threadIdx.x;
    const int row = t >> 3, g = t & 7;
    const int chunk = g >> 2, slot = g & 3;
    float f[8];
    *(float4*)&f[0] = *(const float4*)(proj + row * 64 + g * 8);
    *(float4*)&f[4] = *(const float4*)(proj + row * 64 + g * 8 + 4);
    uint4 hv, lv;
    pack8(f, hv, lv);
    const uint32_t off = (uint32_t)(row * 64 + ((slot ^ ((row >> 1) & 3)) * 16));
    *(uint4*)(img + chunk * 16384 + off)         = hv;
    *(uint4*)(img + 32768 + chunk * 16384 + off) = lv;
}

// ---------------- tensor-core favor xp (q+k heads, RoPE fused) ---------------------
#define FXP_ASF   65536
#define FXP_A     (FXP_ASF + 17408)
#define FXP_SQS   (FXP_A + 16384)
#define FXP_RED   (FXP_SQS + 256)
#define SMEM_FXP  (FXP_RED + 1024)

__global__ __launch_bounds__(256, 1) void favor_xp_tc(const float* __restrict__ x,
                                                      const float* __restrict__ cosp,
                                                      const float* __restrict__ sinp,
                                                      const char* __restrict__ projimg,
                                                      float* __restrict__ xpk,
                                                      __nv_bfloat16* __restrict__ pqh,
                                                      __nv_bfloat16* __restrict__ pql,
                                                      float* __restrict__ sqk,
                                                      float* __restrict__ stab)
{
    extern __shared__ char smc[];
    const uint32_t sb = smem_u32g(smc);
    float* Asf = (float*)(smc + FXP_ASF);
    float* sqs = (float*)(smc + FXP_SQS);
    float* red = (float*)(smc + FXP_RED);

    const float DN = 0.35355339059327373f;
    const int blk = blockIdx.x, hy = blockIdx.y, b = blockIdx.z;
    const bool isq = (hy < NH);
    const int h = isq ? hy : hy - NH;
    const int xcol = isq ? (h * 64) : (2048 + h * 64);
    const int s0 = blk * 64;
    const int tid = threadIdx.x;
    const int warp = tid >> 5, lane = tid & 31;
    const int gid = lane >> 2, tig = lane & 3;

#pragma unroll
    for (int i = 0; i < 16; i++) {
        const uint32_t off = (uint32_t)(tid * 16 + i * 4096);
        CP_ASYNC16(sb + off, projimg + off);
    }
    CP_COMMIT();

#pragma unroll
    for (int r = 0; r < 4; r++) {
        int l = tid + r * 256;
        int tok = l >> 4, q4 = (l & 15) << 2;
        float4 vv = *(const float4*)(x + (size_t)(b * S_LEN + s0 + tok) * QKVW + xcol + q4);
        Asf[tok * 68 + q4 + 0] = vv.x * DN;
        Asf[tok * 68 + q4 + 1] = vv.y * DN;
        Asf[tok * 68 + q4 + 2] = vv.z * DN;
        Asf[tok * 68 + q4 + 3] = vv.w * DN;
    }
    __syncthreads();

#pragma unroll
    for (int r = 0; r < 8; r++) {
        int idx = tid + r * 256;
        int tok = idx >> 5, p = idx & 31;
        const size_t crow = (size_t)(b * S_LEN + s0 + tok) * 64;
        const float c1 = cosp[crow + p],      sn1 = sinp[crow + p];
        const float c2 = cosp[crow + 32 + p], sn2 = sinp[crow + 32 + p];
        float a  = Asf[tok * 68 + p];
        float b2 = Asf[tok * 68 + p + 32];
        Asf[tok * 68 + p]      = a * c1 - b2 * sn1;
        Asf[tok * 68 + p + 32] = b2 * c2 + a * sn2;
    }
    __syncthreads();

    if (tid < 64) {
        float ssum = 0.f;
#pragma unroll
        for (int d = 0; d < 64; d++) { float vv = Asf[tid * 68 + d]; ssum += vv * vv; }
        sqs[tid] = 0.5f * ssum;
        if (!isq) sqk[((size_t)(b * NKV + h)) * S_LEN + s0 + tid] = 0.5f * ssum;
    }
#pragma unroll
    for (int r = 0; r < 2; r++) {
        int s = tid + r * 256;
        int row = s >> 3, g = s & 7;
        int chunk = g >> 2, slot = g & 3;
        float f[8];
        *(float4*)&f[0] = *(const float4*)(Asf + row * 68 + g * 8);
        *(float4*)&f[4] = *(const float4*)(Asf + row * 68 + g * 8 + 4);
        uint4 hv, lv;
        pack8(f, hv, lv);
        const uint32_t off = (uint32_t)(row * 64 + ((slot ^ ((row >> 1) & 3)) * 16));
        *(uint4*)(smc + FXP_A + chunk * 4096 + off)        = hv;
        *(uint4*)(smc + FXP_A + 8192 + chunk * 4096 + off) = lv;
    }
    CP_WAIT(0);
    __syncthreads();

    const int wm = (warp & 1) * 32;
    const int wn = (warp >> 1) * 64;
    const int swm   = ((lane & 7) >> 1) & 3;
    const int rlocA = (lane & 7) + (((lane >> 3) & 1) << 3);
    const int shA   = lane >> 4;
    const int rlocB = (lane & 7) + ((lane >> 4) << 3);
    const int shB   = (lane >> 3) & 1;

    float acc[2][8][4];
#pragma unroll
    for (int i = 0; i < 2; i++)
#pragma unroll
        for (int j = 0; j < 8; j++)
#pragma unroll
            for (int r = 0; r < 4; r++) acc[i][j][r] = 0.f;

#pragma unroll
    for (int ks = 0; ks < 4; ks++) {
        const int chunk = ks >> 1, kb = ks & 1;
        const uint32_t aBase = sb + FXP_A + chunk * 4096;
        const uint32_t bBase = sb + chunk * 16384;
        uint32_t ah[2][4], al[2][4];
#pragma unroll
        for (int tm = 0; tm < 2; tm++) {
            const int r = wm + tm * 16 + rlocA;
            const uint32_t off = (uint32_t)(r * 64 + (((2 * kb + shA) ^ swm) * 16));
            LDSM4(ah[tm], aBase + off);
            LDSM4(al[tm], aBase + 8192 + off);
        }
        uint32_t bhf[4][4], blf[4][4];
#pragma unroll
        for (int p = 0; p < 4; p++) {
            const int r = wn + p * 16 + rlocB;
            const uint32_t off = (uint32_t)(r * 64 + (((2 * kb + shB) ^ swm) * 16));
            LDSM4(bhf[p], bBase + off);
            LDSM4(blf[p], bBase + 32768 + off);
        }
#pragma unroll
        for (int tm = 0; tm < 2; tm++)
#pragma unroll
            for (int tn = 0; tn < 8; tn++) {
                const uint32_t* bh2 = &bhf[tn >> 1][(tn & 1) * 2];
                const uint32_t* bl2 = &blf[tn >> 1][(tn & 1) * 2];
                mma_bf16(acc[tm][tn], ah[tm], bh2);
                mma_bf16(acc[tm][tn], ah[tm], bl2);
                mma_bf16(acc[tm][tn], al[tm], bh2);
            }
    }

    if (isq) {
#pragma unroll
        for (int tm = 0; tm < 2; tm++) {
            float m0 = -3.4e38f, m1 = -3.4e38f;
#pragma unroll
            for (int tn = 0; tn < 8; tn++) {
                m0 = fmaxf(m0, fmaxf(acc[tm][tn][0], acc[tm][tn][1]));
                m1 = fmaxf(m1, fmaxf(acc[tm][tn][2], acc[tm][tn][3]));
            }
#pragma unroll
            for (int o = 1; o <= 2; o <<= 1) {
                m0 = fmaxf(m0, __shfl_xor_sync(0xffffffffu, m0, o));
                m1 = fmaxf(m1, __shfl_xor_sync(0xffffffffu, m1, o));
            }
            if (tig == 0) {
                red[(wm + tm * 16 + gid) * 4 + (warp >> 1)]     = m0;
                red[(wm + tm * 16 + gid + 8) * 4 + (warp >> 1)] = m1;
            }
        }
        __syncthreads();
        const size_t rowbase = (size_t)(b * NH + h) * S_LEN + s0;
#pragma unroll
        for (int tm = 0; tm < 2; tm++) {
            const int r0 = wm + tm * 16 + gid, r1 = r0 + 8;
            const float m0 = fmaxf(fmaxf(red[r0 * 4], red[r0 * 4 + 1]),
                                   fmaxf(red[r0 * 4 + 2], red[r0 * 4 + 3]));
            const float m1 = fmaxf(fmaxf(red[r1 * 4], red[r1 * 4 + 1]),
                                   fmaxf(red[r1 * 4 + 2], red[r1 * 4 + 3]));
            const float s0v = sqs[r0] + m0, s1v = sqs[r1] + m1;
#pragma unroll
            for (int tn = 0; tn < 8; tn++) {
                const int col = wn + tn * 8 + tig * 2;
                float e0 = (__expf(acc[tm][tn][0] - s0v) + 1e-6f) * 0.0625f;
                float e1 = (__expf(acc[tm][tn][1] - s0v) + 1e-6f) * 0.0625f;
                float e2 = (__expf(acc[tm][tn][2] - s1v) + 1e-6f) * 0.0625f;
                float e3 = (__expf(acc[tm][tn][3] - s1v) + 1e-6f) * 0.0625f;
                uint32_t u0 = __float_as_uint(e0), u1 = __float_as_uint(e1);
                uint32_t h01 = __byte_perm(u0, u1, 0x7632), l01;
                float q0 = e0 - __uint_as_float(u0 & 0xFFFF0000u);
                float q1 = e1 - __uint_as_float(u1 & 0xFFFF0000u);
                asm("cvt.rn.bf16x2.f32 %0, %1, %2;" : "=r"(l01) : "f"(q1), "f"(q0));
                uint32_t u2 = __float_as_uint(e2), u3 = __float_as_uint(e3);
                uint32_t h23 = __byte_perm(u2, u3, 0x7632), l23;
                float q2 = e2 - __uint_as_float(u2 & 0xFFFF0000u);
                float q3 = e3 - __uint_as_float(u3 & 0xFFFF0000u);
                asm("cvt.rn.bf16x2.f32 %0, %1, %2;" : "=r"(l23) : "f"(q3), "f"(q2));
                *(uint32_t*)(pqh + (rowbase + r0) * M_FEAT + col) = h01;
                *(uint32_t*)(pql + (rowbase + r0) * M_FEAT + col) = l01;
                *(uint32_t*)(pqh + (rowbase + r1) * M_FEAT + col) = h23;
                *(uint32_t*)(pql + (rowbase + r1) * M_FEAT + col) = l23;
            }
        }
    } else {
        const size_t rowbase = (size_t)(b * NKV + h) * S_LEN + s0;
        float mx = -3.4e38f;
#pragma unroll
        for (int tm = 0; tm < 2; tm++) {
            const int r0 = wm + tm * 16 + gid, r1 = r0 + 8;
#pragma unroll
            for (int tn = 0; tn < 8; tn++) {
                const int col = wn + tn * 8 + tig * 2;
                *(float2*)(xpk + (rowbase + r0) * M_FEAT + col) =
                    make_float2(acc[tm][tn][0], acc[tm][tn][1]);
                *(float2*)(xpk + (rowbase + r1) * M_FEAT + col) =
                    make_float2(acc[tm][tn][2], acc[tm][tn][3]);
                mx = fmaxf(mx, fmaxf(fmaxf(acc[tm][tn][0], acc[tm][tn][1]),
                                     fmaxf(acc[tm][tn][2], acc[tm][tn][3])));
            }
        }
        red[tid] = mx;
        __syncthreads();
        for (int st = 128; st > 0; st >>= 1) {
            if (tid < st) red[tid] = fmaxf(red[tid], red[tid + st]);
            __syncthreads();
        }
        if (tid == 0) atomicMaxFloat(&stab[b * NKV + h], red[0]);
    }
}

// ------- per-chunk kv/kz with fused k-exp + phi_k hi/lo output. grid (NC,NKV,B) -----
__global__ __launch_bounds__(256) void kv_chunk(const float* __restrict__ xpk,
                                                const float* __restrict__ sqk,
                                                const float* __restrict__ stab,
                                                __nv_bfloat16* __restrict__ pkh,
                                                __nv_bfloat16* __restrict__ pkl,
                                                const float* __restrict__ qkv,
                                                float* __restrict__ kv,
                                                float* __restrict__ kz)
{
    __shared__ float ps[16][256];
    __shared__ float vs[16][64];
    const int c = blockIdx.x, h = blockIdx.y, b = blockIdx.z;
    const int tid = threadIdx.x;
    const float stabv = stab[b * NKV + h];
    float acc[64];
#pragma unroll
    for (int d = 0; d < 64; d++) acc[d] = 0.f;
    float accz = 0.f;
    const size_t prow = (size_t)(b * NKV + h) * S_LEN + c * CHUNK;
    const size_t vrow = (size_t)b * S_LEN + c * CHUNK;

    for (int i0 = 0; i0 < CHUNK; i0 += 16) {
#pragma unroll
        for (int ii = 0; ii < 16; ii++) {
            const size_t idx = (prow + i0 + ii) * M_FEAT + tid;
            const float sqv = sqk[prow + i0 + ii];
            const float v = (__expf(xpk[idx] - sqv - stabv) + 1e-6f) * 0.0625f;
            ps[ii][tid] = v;
            const uint32_t u = __float_as_uint(v);
            const float t = __uint_as_float(u & 0xFFFF0000u);
            pkh[idx] = __ushort_as_bfloat16((unsigned short)(u >> 16));
            pkl[idx] = __float2bfloat16(v - t);
        }
#pragma unroll
        for (int j = 0; j < 4; j++) {
            int l = tid + j * 256;
            int ii = l >> 6, d = l & 63;
            vs[ii][d] = qkv[(vrow + i0 + ii) * QKVW + 2560 + h * 64 + d];
        }
        __syncthreads();
#pragma unroll
        for (int ii = 0; ii < 16; ii++) {
            float a = ps[ii][tid];
            accz += a;
#pragma unroll
            for (int d4 = 0; d4 < 64; d4 += 4) {
                float4 vv = *(const float4*)&vs[ii][d4];
                acc[d4 + 0] += a * vv.x; acc[d4 + 1] += a * vv.y;
                acc[d4 + 2] += a * vv.z; acc[d4 + 3] += a * vv.w;
            }
        }
        __syncthreads();
    }
    const size_t ob = (((size_t)(b * NKV + h) * NC + c) * M_FEAT + tid) * D_HEAD;
#pragma unroll
    for (int d4 = 0; d4 < 64; d4 += 4)
        *(float4*)(kv + ob + d4) = make_float4(acc[d4], acc[d4 + 1], acc[d4 + 2], acc[d4 + 3]);
    kz[((size_t)(b * NKV + h) * NC + c) * M_FEAT + tid] = accz;
}

// ---------------- exclusive prefix over chunk axis, in place ----------------------
__global__ void cumsum_k(float* __restrict__ kv, float* __restrict__ kz)
{
    const int tid = blockIdx.x * blockDim.x + threadIdx.x;
    const int KVSZ = M_FEAT * D_HEAD;
    if (tid < B_SZ * NKV * KVSZ) {
        int bh = tid / KVSZ, md = tid % KVSZ;
        float run = 0.f;
        for (int c = 0; c < NC; c++) {
            size_t idx = ((size_t)bh * NC + c) * KVSZ + md;
            float t = kv[idx]; kv[idx] = run; run += t;
        }
    } else {
        int t2 = tid - B_SZ * NKV * KVSZ;
        if (t2 < B_SZ * NKV * M_FEAT) {
            int bh = t2 / M_FEAT, m = t2 % M_FEAT;
            float run = 0.f;
            for (int c = 0; c < NC; c++) {
                size_t idx = ((size_t)bh * NC + c) * M_FEAT + m;
                float tz = kz[idx]; kz[idx] = run; run += tz;
            }
        }
    }
}

// ============ tensor-core chunked causal linear attention. grid (NC, NH, B) ========
// smem: Ss fp32 [0, 67584) | AB0 [67584, +32K) | AB1 [+32K) | Zs
#define SPITCH 132
#define ATT_AB0 (128 * SPITCH * 4)
#define ATT_AB1 (ATT_AB0 + 32768)
#define ATT_ZS  (ATT_AB1 + 32768)
#define SMEM_ATTN (ATT_ZS + 512)

__global__ __launch_bounds__(256, 1) void attn_tc(
    const __nv_bfloat16* __restrict__ pqh, const __nv_bfloat16* __restrict__ pql,
    const __nv_bfloat16* __restrict__ pkh, const __nv_bfloat16* __restrict__ pkl,
    const float* __restrict__ qkv, const float* __restrict__ kvpre,
    const float* __restrict__ kzpre,
    __nv_bfloat16* __restrict__ ath, __nv_bfloat16* __restrict__ atl)
{
    extern __shared__ float sm[];
    char* smcb = (char*)sm;
    float* Ss = sm;
    float* Zs = (float*)(smcb + ATT_ZS);
    const uint32_t sbase = smem_u32g(smcb);
    const uint32_t ab0 = sbase + ATT_AB0;
    const uint32_t ab1 = sbase + ATT_AB1;

    const int c = blockIdx.x, h = blockIdx.y, b = blockIdx.z;
    const int kvh = h >> 2;
    const int tid = threadIdx.x;
    const int warp = tid >> 5, lane = tid & 31;
    const int gid = lane >> 2, tig = lane & 3;

    const size_t qbase  = (size_t)(b * NH + h) * S_LEN + c * CHUNK;
    const size_t kbase  = (size_t)(b * NKV + kvh) * S_LEN + c * CHUNK;
    const size_t vrow0  = (size_t)b * S_LEN + c * CHUNK;
    const size_t kvbase = ((size_t)(b * NKV + kvh) * NC + c) * (size_t)(M_FEAT * D_HEAD);
    const size_t kzbase = ((size_t)(b * NKV + kvh) * NC + c) * M_FEAT;

    const int strow = tid & 127;
    const int s0 = tid >> 7;

    const int swm   = ((lane & 7) >> 1) & 3;
    const int rlocA = (lane & 7) + (((lane >> 3) & 1) << 3);
    const int shA   = lane >> 4;
    const int rlocB = (lane & 7) + ((lane >> 4) << 3);
    const int shB   = (lane >> 3) & 1;

    // ======================= Phase 1: scores (cp.async double-buffered) ============
    {
        const int wm = (warp & 1) * 64, wn = (warp >> 1) * 32;
        float acc[4][4][4];
#pragma unroll
        for (int i = 0; i < 4; i++)
#pragma unroll
            for (int j = 0; j < 4; j++)
#pragma unroll
                for (int r = 0; r < 4; r++) acc[i][j][r] = 0.f;

        auto stage1 = [&](int m0, uint32_t bb) {
#pragma unroll
            for (int si = 0; si < 2; si++) {
                const int s = s0 + si * 2;
                const uint32_t off = (uint32_t)(strow * 64 + ((s ^ ((strow >> 1) & 3)) * 16));
                const size_t ia = (qbase + strow) * M_FEAT + m0 + s * 8;
                const size_t ib = (kbase + strow) * M_FEAT + m0 + s * 8;
                CP_ASYNC16(bb + off,         (const char*)(pqh + ia));
                CP_ASYNC16(bb + 8192  + off, (const char*)(pql + ia));
                CP_ASYNC16(bb + 16384 + off, (const char*)(pkh + ib));
                CP_ASYNC16(bb + 24576 + off, (const char*)(pkl + ib));
            }
            CP_COMMIT();
        };

        stage1(0, ab0);
        for (int t = 0; t < 8; t++) {
            if (t + 1 < 8) {
                stage1((t + 1) * 32, (t + 1) & 1 ? ab1 : ab0);
                CP_WAIT(1);
            } else {
                CP_WAIT(0);
            }
            __syncthreads();
            const uint32_t bb = (t & 1) ? ab1 : ab0;
#pragma unroll
            for (int kb = 0; kb < 2; kb++) {
                uint32_t ah[4][4], al[4][4];
#pragma unroll
                for (int tm = 0; tm < 4; tm++) {
                    const int r = wm + tm * 16 + rlocA;
                    const uint32_t off = (uint32_t)(r * 64 + (((2 * kb + shA) ^ swm) * 16));
                    LDSM4(ah[tm], bb + off);
                    LDSM4(al[tm], bb + 8192 + off);
                }
                uint32_t bhf[2][4], blf[2][4];
#pragma unroll
                for (int p = 0; p < 2; p++) {
                    const int r = wn + p * 16 + rlocB;
                    const uint32_t off = (uint32_t)(r * 64 + (((2 * kb + shB) ^ swm) * 16));
                    LDSM4(bhf[p], bb + 16384 + off);
                    LDSM4(blf[p], bb + 24576 + off);
                }
#pragma unroll
                for (int tm = 0; tm < 4; tm++)
#pragma unroll
                    for (int tn = 0; tn < 4; tn++) {
                        const uint32_t* bh2 = &bhf[tn >> 1][(tn & 1) * 2];
                        const uint32_t* bl2 = &blf[tn >> 1][(tn & 1) * 2];
                        mma_bf16(acc[tm][tn], ah[tm], bh2);
                        mma_bf16(acc[tm][tn], ah[tm], bl2);
                        mma_bf16(acc[tm][tn], al[tm], bh2);
                    }
            }
            __syncthreads();
        }
#pragma unroll
        for (int tm = 0; tm < 4; tm++) {
            const int r0 = wm + tm * 16 + gid;
            const int r1 = r0 + 8;
#pragma unroll
            for (int tn = 0; tn < 4; tn++) {
                const int col = wn + tn * 8 + tig * 2;
                Ss[r0 * SPITCH + col]     = (col     <= r0) ? acc[tm][tn][0] : 0.f;
                Ss[r0 * SPITCH + col + 1] = (col + 1 <= r0) ? acc[tm][tn][1] : 0.f;
                Ss[r1 * SPITCH + col]     = (col     <= r1) ? acc[tm][tn][2] : 0.f;
                Ss[r1 * SPITCH + col + 1] = (col + 1 <= r1) ? acc[tm][tn][3] : 0.f;
            }
        }
    }
    __syncthreads();

    // ======== Phase 2: inter+intra (+z col 64), register-prefetch pipelined ========
    const int wm2 = (warp & 3) * 32, wn2 = (warp >> 2) * 40;
    float acc2[2][5][4];
#pragma unroll
    for (int i = 0; i < 2; i++)
#pragma unroll
        for (int j = 0; j < 5; j++)
#pragma unroll
            for (int r = 0; r < 4; r++) acc2[i][j][r] = 0.f;

    uint4 pA[4];          // cc<8: [si*2]=pqh, [si*2+1]=pql
    float gB[2][8];       // B-side gather values

    auto p2_prefetch = [&](int cc) {
#pragma unroll
        for (int si = 0; si < 2; si++) {
            const int s = s0 + si * 2;
            if (cc < 8) {
                const size_t ia = (qbase + strow) * M_FEAT + cc * 32 + s * 8;
                pA[si * 2]     = *(const uint4*)(pqh + ia);
                pA[si * 2 + 1] = *(const uint4*)(pql + ia);
            }
            if (strow < 96) {
                if (strow < 64) {
                    if (cc < 8) {
#pragma unroll
                        for (int e = 0; e < 8; e++)
                            gB[si][e] = kvpre[kvbase + (size_t)(cc * 32 + s * 8 + e) * 64 + strow];
                    } else {
#pragma unroll
                        for (int e = 0; e < 8; e++)
                            gB[si][e] = qkv[(vrow0 + (cc - 8) * 32 + s * 8 + e) * QKVW + 2560 + kvh * 64 + strow];
                    }
                } else if (strow == 64) {
                    if (cc < 8) {
#pragma unroll
                        for (int e = 0; e < 8; e++)
                            gB[si][e] = kzpre[kzbase + cc * 32 + s * 8 + e];
                    } else {
#pragma unroll
                        for (int e = 0; e < 8; e++) gB[si][e] = 1.f;
                    }
                } else {
#pragma unroll
                    for (int e = 0; e < 8; e++) gB[si][e] = 0.f;
                }
            }
        }
    };
    auto p2_commit = [&](int cc, char* bufc) {
#pragma unroll
        for (int si = 0; si < 2; si++) {
            const int s = s0 + si * 2;
            const uint32_t off = (uint32_t)(strow * 64 + ((s ^ ((strow >> 1) & 3)) * 16));
            if (cc < 8) {
                *(uint4*)(bufc + off)        = pA[si * 2];
                *(uint4*)(bufc + 8192 + off) = pA[si * 2 + 1];
            } else {
                float f[8];
                const float* pa = Ss + strow * SPITCH + (cc - 8) * 32 + s * 8;
                *(float4*)&f[0] = *(const float4*)pa;
                *(float4*)&f[4] = *(const float4*)(pa + 4);
                uint4 hv, lv;
                pack8(f, hv, lv);
                *(uint4*)(bufc + off)        = hv;
                *(uint4*)(bufc + 8192 + off) = lv;
            }
            if (strow < 96) {
                uint4 hv, lv;
                pack8(gB[si], hv, lv);
                *(uint4*)(bufc + 16384 + off) = hv;
                *(uint4*)(bufc + 24576 + off) = lv;
            }
        }
    };

    p2_prefetch(0);
    for (int cc = 0; cc < 12; cc++) {
        char* bufc = smcb + ((cc & 1) ? ATT_AB1 : ATT_AB0);
        const uint32_t bb = (cc & 1) ? ab1 : ab0;
        p2_commit(cc, bufc);
        if (cc + 1 < 12) p2_prefetch(cc + 1);
        __syncthreads();
#pragma unroll
        for (int kb = 0; kb < 2; kb++) {
            uint32_t ah2[2][4], al2[2][4], bh2[3][4], bl2[3][4];
#pragma unroll
            for (int tm = 0; tm < 2; tm++) {
                const int r = wm2 + tm * 16 + rlocA;
                const uint32_t off = (uint32_t)(r * 64 + (((2 * kb + shA) ^ swm) * 16));
                LDSM4(ah2[tm], bb + off);
                LDSM4(al2[tm], bb + 8192 + off);
            }
#pragma unroll
            for (int p = 0; p < 3; p++) {
                const int r = wn2 + p * 16 + rlocB;
                const uint32_t off = (uint32_t)(r * 64 + (((2 * kb + shB) ^ swm) * 16));
                LDSM4(bh2[p], bb + 16384 + off);
                LDSM4(bl2[p], bb + 24576 + off);
            }
#pragma unroll
            for (int tm = 0; tm < 2; tm++)
#pragma unroll
                for (int tn = 0; tn < 5; tn++) {
                    const uint32_t* bh_ = &bh2[tn >> 1][(tn & 1) * 2];
                    const uint32_t* bl_ = &bl2[tn >> 1][(tn & 1) * 2];
                    mma_bf16(acc2[tm][tn], ah2[tm], bh_);
                    mma_bf16(acc2[tm][tn], ah2[tm], bl_);
                    mma_bf16(acc2[tm][tn], al2[tm], bh_);
                }
        }
    }
    __syncthreads();

    if ((warp >> 2) == 1 && tig == 0) {
#pragma unroll
        for (int tm = 0; tm < 2; tm++) {
            const int r = wm2 + tm * 16 + gid;
            Zs[r]     = acc2[tm][3][0];
            Zs[r + 8] = acc2[tm][3][2];
        }
    }
    __syncthreads();

#pragma unroll
    for (int tm = 0; tm < 2; tm++) {
        const int r = wm2 + tm * 16 + gid;
        const float d0 = 1.f / (Zs[r] + 1e-6f);
        const float d1 = 1.f / (Zs[r + 8] + 1e-6f);
#pragma unroll
        for (int tn = 0; tn < 5; tn++) {
            const int col = wn2 + tn * 8 + tig * 2;
            if (col < 64) {
                const size_t ro = ((size_t)b * S_LEN + c * CHUNK + r) * (NH * D_HEAD) + h * 64 + col;
                const size_t ro8 = ro + 8 * (NH * D_HEAD);
                float o0 = acc2[tm][tn][0] * d0, o1 = acc2[tm][tn][1] * d0;
                float o2 = acc2[tm][tn][2] * d1, o3 = acc2[tm][tn][3] * d1;
                __nv_bfloat16 h0 = __float2bfloat16(o0), h1 = __float2bfloat16(o1);
                __nv_bfloat16 h2 = __float2bfloat16(o2), h3 = __float2bfloat16(o3);
                *(__nv_bfloat162*)(ath + ro)  = __nv_bfloat162(h0, h1);
                *(__nv_bfloat162*)(ath + ro8) = __nv_bfloat162(h2, h3);
                *(__nv_bfloat162*)(atl + ro)  =
                    __nv_bfloat162(__float2bfloat16(o0 - __bfloat162float(h0)),
                                   __float2bfloat16(o1 - __bfloat162float(h1)));
                *(__nv_bfloat162*)(atl + ro8) =
                    __nv_bfloat162(__float2bfloat16(o2 - __bfloat162float(h2)),
                                   __float2bfloat16(o3 - __bfloat162float(h3)));
            }
        }
    }
}

// ----------------------------------- launch ---------------------------------------
extern "C" void kernel_launch(void* const* d_in, const int* in_sizes, int n_in,
                              void* d_out, int out_size)
{
    const float* hs   = (const float*)d_in[0];
    const float* cosp = (const float*)d_in[1];
    const float* sinp = (const float*)d_in[2];
    const float* Wq   = (const float*)d_in[3];
    const float* Wk   = (const float*)d_in[4];
    const float* Wv   = (const float*)d_in[5];
    const float* Wo   = (const float*)d_in[6];
    const float* proj = (const float*)d_in[7];
    float* out = (float*)d_out;

    float *qkvp, *xpkp, *sqkp, *stabp, *kvp, *kzp;
    cudaGetSymbolAddress((void**)&qkvp,  g_qkv);
    cudaGetSymbolAddress((void**)&xpkp,  g_xpk);
    cudaGetSymbolAddress((void**)&sqkp,  g_sqk);
    cudaGetSymbolAddress((void**)&stabp, g_stab);
    cudaGetSymbolAddress((void**)&kvp,   g_kv);
    cudaGetSymbolAddress((void**)&kzp,   g_kz);
    char* pimg;
    cudaGetSymbolAddress((void**)&pimg, g_projimg);

    __nv_bfloat16 *pqh, *pql, *pkh, *pkl, *hsh, *hsl, *ath, *atl, *wh, *wl;
    cudaGetSymbolAddress((void**)&pqh, g_pqh);
    cudaGetSymbolAddress((void**)&pql, g_pql);
    cudaGetSymbolAddress((void**)&pkh, g_pkh);
    cudaGetSymbolAddress((void**)&pkl, g_pkl);
    cudaGetSymbolAddress((void**)&hsh, g_hsh);
    cudaGetSymbolAddress((void**)&hsl, g_hsl);
    cudaGetSymbolAddress((void**)&ath, g_ath);
    cudaGetSymbolAddress((void**)&atl, g_atl);
    cudaGetSymbolAddress((void**)&wh,  g_wh);
    cudaGetSymbolAddress((void**)&wl,  g_wl);

    cudaFuncSetAttribute(gemm_bf16x3, cudaFuncAttributeMaxDynamicSharedMemorySize, SMEM_GEMM);
    cudaFuncSetAttribute(attn_tc, cudaFuncAttributeMaxDynamicSharedMemorySize, SMEM_ATTN);
    cudaFuncSetAttribute(favor_xp_tc, cudaFuncAttributeMaxDynamicSharedMemorySize, SMEM_FXP);

    // ---- splits + proj image ----
    split_bf16<<<(HS_ELEMS / 4 + 255) / 256, 256>>>(hs, hsh, hsl, HS_ELEMS / 4);
    split_bf16<<<(HID_ * HID_ / 4 + 255) / 256, 256>>>(Wq, wh + WQ_OFF, wl + WQ_OFF, HID_ * HID_ / 4);
    split_bf16<<<(512 * HID_ / 4 + 255) / 256, 256>>>(Wk, wh + WK_OFF, wl + WK_OFF, 512 * HID_ / 4);
    split_bf16<<<(512 * HID_ / 4 + 255) / 256, 256>>>(Wv, wh + WV_OFF, wl + WV_OFF, 512 * HID_ / 4);
    split_bf16<<<(HID_ * HID_ / 4 + 255) / 256, 256>>>(Wo, wh + WO_OFF, wl + WO_OFF, HID_ * HID_ / 4);
    prep_proj<<<8, 256>>>(proj, pimg);

    // ---- fused QKV projection ----
    gemm_bf16x3<<<dim3(QKVW / 128, 32), 256, SMEM_GEMM>>>(hsh, hsl, wh, wl, qkvp, QKVW);

    // ---- favor features on tensor cores (q+k merged, RoPE fused) ----
    init_stab_kernel<<<1, 32>>>(stabp);
    favor_xp_tc<<<dim3(S_LEN / 64, NH + NKV, B_SZ), 256, SMEM_FXP>>>(
        qkvp, cosp, sinp, pimg, xpkp, pqh, pql, sqkp, stabp);

    // ---- chunked linear attention ----
    kv_chunk<<<dim3(NC, NKV, B_SZ), 256>>>(xpkp, sqkp, stabp, pkh, pkl, qkvp, kvp, kzp);
    cumsum_k<<<(B_SZ * NKV * (M_FEAT * D_HEAD + M_FEAT) + 255) / 256, 256>>>(kvp, kzp);
    attn_tc<<<dim3(NC, NH, B_SZ), 256, SMEM_ATTN>>>(pqh, pql, pkh, pkl, qkvp, kvp, kzp, ath, atl);

    // ---- output projection ----
    gemm_bf16x3<<<dim3(16, 32), 256, SMEM_GEMM>>>(ath, atl, wh + WO_OFF, wl + WO_OFF, out, 2048);
}

// round 17
// speedup vs baseline: 2.0039x; 1.0178x over previous
#include <cuda_runtime.h>
#include <cuda_bf16.h>
#include <math.h>
#include <stdint.h>

#define B_SZ   2
#define S_LEN  2048
#define HID_   2048
#define NH     32
#define NKV    8
#define D_HEAD 64
#define M_FEAT 256
#define NC     16
#define CHUNK  128
#define QKVW   3072

// ---------------- scratch (device globals; no allocations allowed) ----------------
__device__ float g_qkv [(size_t)B_SZ * S_LEN * QKVW];
__device__ float g_xpk [(size_t)B_SZ * NKV * S_LEN * M_FEAT];
__device__ float g_sqk [B_SZ * NKV * S_LEN];
__device__ float g_stab[B_SZ * NKV];
__device__ float g_kv  [B_SZ * NKV * NC * M_FEAT * D_HEAD];
__device__ float g_kz  [B_SZ * NKV * NC * M_FEAT];
__device__ __align__(16) char g_projimg[65536];

#define PHIQ_E ((size_t)B_SZ * NH  * S_LEN * M_FEAT)
#define PHIK_E ((size_t)B_SZ * NKV * S_LEN * M_FEAT)
#define HS_ELEMS  (B_SZ * S_LEN * HID_)
#define W_ELEMS   (QKVW * HID_ + HID_ * HID_)
__device__ __align__(16) __nv_bfloat16 g_pqh[PHIQ_E];
__device__ __align__(16) __nv_bfloat16 g_pql[PHIQ_E];
__device__ __align__(16) __nv_bfloat16 g_pkh[PHIK_E];
__device__ __align__(16) __nv_bfloat16 g_pkl[PHIK_E];
__device__ __align__(16) __nv_bfloat16 g_hsh[HS_ELEMS];
__device__ __align__(16) __nv_bfloat16 g_hsl[HS_ELEMS];
__device__ __align__(16) __nv_bfloat16 g_ath[HS_ELEMS];
__device__ __align__(16) __nv_bfloat16 g_atl[HS_ELEMS];
__device__ __align__(16) __nv_bfloat16 g_wh [W_ELEMS];
__device__ __align__(16) __nv_bfloat16 g_wl [W_ELEMS];

#define WQ_OFF 0
#define WK_OFF (HID_ * HID_)
#define WV_OFF (WK_OFF + 512 * HID_)
#define WO_OFF (WV_OFF + 512 * HID_)

// =================== fp32 -> bf16 hi/lo split (elementwise, x4 vec) ================
__global__ void split_bf16(const float* __restrict__ x, __nv_bfloat16* __restrict__ h,
                           __nv_bfloat16* __restrict__ l, int n4)
{
    int i = blockIdx.x * blockDim.x + threadIdx.x;
    if (i >= n4) return;
    float4 v = ((const float4*)x)[i];
    __nv_bfloat16 h0 = __float2bfloat16(v.x), h1 = __float2bfloat16(v.y);
    __nv_bfloat16 h2 = __float2bfloat16(v.z), h3 = __float2bfloat16(v.w);
    __nv_bfloat162* hp = (__nv_bfloat162*)h;
    hp[2 * i]     = __nv_bfloat162(h0, h1);
    hp[2 * i + 1] = __nv_bfloat162(h2, h3);
    __nv_bfloat162* lp = (__nv_bfloat162*)l;
    lp[2 * i]     = __nv_bfloat162(__float2bfloat16(v.x - __bfloat162float(h0)),
                                   __float2bfloat16(v.y - __bfloat162float(h1)));
    lp[2 * i + 1] = __nv_bfloat162(__float2bfloat16(v.z - __bfloat162float(h2)),
                                   __float2bfloat16(v.w - __bfloat162float(h3)));
}

// ===================== shared helpers for tensor-core kernels ======================
__device__ __forceinline__ uint32_t smem_u32g(const void* p)
{
    uint32_t a;
    asm("{ .reg .u64 t; cvta.to.shared.u64 t, %1; cvt.u32.u64 %0, t; }" : "=r"(a) : "l"(p));
    return a;
}

#define LDSM4(r, a) \
    asm volatile("ldmatrix.sync.aligned.m8n8.x4.shared.b16 {%0,%1,%2,%3}, [%4];" \
                 : "=r"((r)[0]), "=r"((r)[1]), "=r"((r)[2]), "=r"((r)[3]) : "r"(a))

#define CP_ASYNC16(dst, src) \
    asm volatile("cp.async.cg.shared.global [%0], [%1], 16;" :: "r"(dst), "l"(src) : "memory")
#define CP_COMMIT() asm volatile("cp.async.commit_group;" ::: "memory")
#define CP_WAIT(n)  asm volatile("cp.async.wait_group %0;" :: "n"(n) : "memory")

__device__ __forceinline__ void mma_bf16(float c[4], const uint32_t a[4], const uint32_t b[2])
{
    asm volatile("mma.sync.aligned.m16n8k16.row.col.f32.bf16.bf16.f32 "
                 "{%0,%1,%2,%3}, {%4,%5,%6,%7}, {%8,%9}, {%0,%1,%2,%3};"
                 : "+f"(c[0]), "+f"(c[1]), "+f"(c[2]), "+f"(c[3])
                 : "r"(a[0]), "r"(a[1]), "r"(a[2]), "r"(a[3]), "r"(b[0]), "r"(b[1]));
}

// cheap hi/lo split: hi = bf16-truncate (PRMT), lo = RN(residual) via one bf16x2 cvt
__device__ __forceinline__ void pack8(const float* f, uint4& hv, uint4& lv)
{
    uint32_t hw[4], lw[4];
#pragma unroll
    for (int e = 0; e < 4; e++) {
        const uint32_t u0 = __float_as_uint(f[2 * e]);
        const uint32_t u1 = __float_as_uint(f[2 * e + 1]);
        hw[e] = __byte_perm(u0, u1, 0x7632);
        const float t0 = __uint_as_float(u0 & 0xFFFF0000u);
        const float t1 = __uint_as_float(u1 & 0xFFFF0000u);
        const float r0 = f[2 * e] - t0;
        const float r1 = f[2 * e + 1] - t1;
        asm("cvt.rn.bf16x2.f32 %0, %1, %2;" : "=r"(lw[e]) : "f"(r1), "f"(r0));
    }
    hv = make_uint4(hw[0], hw[1], hw[2], hw[3]);
    lv = make_uint4(lw[0], lw[1], lw[2], lw[3]);
}

// ======== bf16 3-pass split GEMM: 128x128 tile, 3-stage cp.async, ldmatrix =========
#define GK 2048
#define BK 32
#define NKT (GK / BK)
#define GBUF 32768
#define SMEM_GEMM (3 * GBUF)

__global__ __launch_bounds__(256, 2) void gemm_bf16x3(const __nv_bfloat16* __restrict__ Ah,
                                                      const __nv_bfloat16* __restrict__ Al,
                                                      const __nv_bfloat16* __restrict__ Bh,
                                                      const __nv_bfloat16* __restrict__ Bl,
                                                      float* __restrict__ C, int N)
{
    extern __shared__ char smc[];
    const uint32_t sb = smem_u32g(smc);
    const int tid  = threadIdx.x;
    const int warp = tid >> 5, lane = tid & 31;
    const int gid  = lane >> 2, tig = lane & 3;
    const int wm   = (warp & 1) * 64;
    const int wn   = (warp >> 1) * 32;
    const int rowA = blockIdx.y * 128;
    const int rowB = blockIdx.x * 128;

    const int r0s = tid >> 2,         s0s = tid & 3;
    const int r1s = (tid + 256) >> 2, s1s = tid & 3;
    const uint32_t so0 = (uint32_t)(r0s * 64 + ((s0s ^ ((r0s >> 1) & 3)) * 16));
    const uint32_t so1 = (uint32_t)(r1s * 64 + ((s1s ^ ((r1s >> 1) & 3)) * 16));

    const int swm   = ((lane & 7) >> 1) & 3;
    const int rlocA = (lane & 7) + (((lane >> 3) & 1) << 3);
    const int shA   = lane >> 4;
    const int rlocB = (lane & 7) + ((lane >> 4) << 3);
    const int shB   = (lane >> 3) & 1;

    float acc[4][4][4];
#pragma unroll
    for (int i = 0; i < 4; i++)
#pragma unroll
        for (int j = 0; j < 4; j++)
#pragma unroll
            for (int r = 0; r < 4; r++) acc[i][j][r] = 0.f;

    auto stage = [&](int kt, int b) {
        const uint32_t bb = sb + b * GBUF;
        const int kb = kt * BK;
        CP_ASYNC16(bb + so0,         (const char*)(Ah + (size_t)(rowA + r0s) * GK + kb + s0s * 8));
        CP_ASYNC16(bb + so1,         (const char*)(Ah + (size_t)(rowA + r1s) * GK + kb + s1s * 8));
        CP_ASYNC16(bb + 8192  + so0, (const char*)(Al + (size_t)(rowA + r0s) * GK + kb + s0s * 8));
        CP_ASYNC16(bb + 8192  + so1, (const char*)(Al + (size_t)(rowA + r1s) * GK + kb + s1s * 8));
        CP_ASYNC16(bb + 16384 + so0, (const char*)(Bh + (size_t)(rowB + r0s) * GK + kb + s0s * 8));
        CP_ASYNC16(bb + 16384 + so1, (const char*)(Bh + (size_t)(rowB + r1s) * GK + kb + s1s * 8));
        CP_ASYNC16(bb + 24576 + so0, (const char*)(Bl + (size_t)(rowB + r0s) * GK + kb + s0s * 8));
        CP_ASYNC16(bb + 24576 + so1, (const char*)(Bl + (size_t)(rowB + r1s) * GK + kb + s1s * 8));
        CP_COMMIT();
    };

    stage(0, 0);
    stage(1, 1);

    int bufc = 0;
    int stg  = 2 % 3;
    for (int kt = 0; kt < NKT; kt++) {
        if (kt + 2 < NKT) {
            stage(kt + 2, stg);
            stg = (stg + 1 == 3) ? 0 : stg + 1;
            CP_WAIT(2);
        } else if (kt + 1 < NKT) {
            CP_WAIT(1);
        } else {
            CP_WAIT(0);
        }
        __syncthreads();

        const uint32_t base = sb + bufc * GBUF;
#pragma unroll
        for (int kb = 0; kb < 2; kb++) {
            uint32_t ah[4][4], al[4][4];
#pragma unroll
            for (int tm = 0; tm < 4; tm++) {
                const int r = wm + tm * 16 + rlocA;
                const uint32_t off = (uint32_t)(r * 64 + (((2 * kb + shA) ^ swm) * 16));
                LDSM4(ah[tm], base + off);
                LDSM4(al[tm], base + 8192 + off);
            }
            uint32_t bhf[2][4], blf[2][4];
#pragma unroll
            for (int p = 0; p < 2; p++) {
                const int r = wn + p * 16 + rlocB;
                const uint32_t off = (uint32_t)(r * 64 + (((2 * kb + shB) ^ swm) * 16));
                LDSM4(bhf[p], base + 16384 + off);
                LDSM4(blf[p], base + 24576 + off);
            }
#pragma unroll
            for (int tm = 0; tm < 4; tm++)
#pragma unroll
                for (int tn = 0; tn < 4; tn++) {
                    const uint32_t* bh2 = &bhf[tn >> 1][(tn & 1) * 2];
                    const uint32_t* bl2 = &blf[tn >> 1][(tn & 1) * 2];
                    mma_bf16(acc[tm][tn], ah[tm], bh2);
                    mma_bf16(acc[tm][tn], ah[tm], bl2);
                    mma_bf16(acc[tm][tn], al[tm], bh2);
                }
        }
        __syncthreads();
        bufc = (bufc + 1 == 3) ? 0 : bufc + 1;
    }

#pragma unroll
    for (int tm = 0; tm < 4; tm++) {
        const size_t r0 = (size_t)rowA + wm + tm * 16 + gid;
#pragma unroll
        for (int tn = 0; tn < 4; tn++) {
            const int cn = rowB + wn + tn * 8 + tig * 2;
            *(float2*)(C + r0 * N + cn)       = make_float2(acc[tm][tn][0], acc[tm][tn][1]);
            *(float2*)(C + (r0 + 8) * N + cn) = make_float2(acc[tm][tn][2], acc[tm][tn][3]);
        }
    }
}

__device__ void atomicMaxFloat(float* addr, float val)
{
    int* ia = (int*)addr;
    int old = *ia;
    while (__int_as_float(old) < val) {
        int assumed = old;
        old = atomicCAS(ia, assumed, __float_as_int(val));
        if (old == assumed) break;
    }
}

__global__ void init_stab_kernel(float* stab)
{
    if (threadIdx.x < B_SZ * NKV) stab[threadIdx.x] = -3.4e38f;
}

// ---------------- prep proj: build pre-swizzled bf16 hi/lo tile image --------------
__global__ void prep_proj(const float* __restrict__ proj, char* __restrict__ img)
{
    const int t = blockIdx.x * blockDim.x + threadIdx.x;
    const int row = t >> 3, g = t & 7;
    const int chunk = g >> 2, slot = g & 3;
    float f[8];
    *(float4*)&f[0] = *(const float4*)(proj + row * 64 + g * 8);
    *(float4*)&f[4] = *(const float4*)(proj + row * 64 + g * 8 + 4);
    uint4 hv, lv;
    pack8(f, hv, lv);
    const uint32_t off = (uint32_t)(row * 64 + ((slot ^ ((row >> 1) & 3)) * 16));
    *(uint4*)(img + chunk * 16384 + off)         = hv;
    *(uint4*)(img + 32768 + chunk * 16384 + off) = lv;
}

// ---------------- tensor-core favor xp (q+k heads, RoPE fused) ---------------------
#define FXP_ASF   65536
#define FXP_A     (FXP_ASF + 17408)
#define FXP_SQS   (FXP_A + 16384)
#define FXP_RED   (FXP_SQS + 256)
#define SMEM_FXP  (FXP_RED + 1024)

__global__ __launch_bounds__(256, 1) void favor_xp_tc(const float* __restrict__ x,
                                                      const float* __restrict__ cosp,
                                                      const float* __restrict__ sinp,
                                                      const char* __restrict__ projimg,
                                                      float* __restrict__ xpk,
                                                      __nv_bfloat16* __restrict__ pqh,
                                                      __nv_bfloat16* __restrict__ pql,
                                                      float* __restrict__ sqk,
                                                      float* __restrict__ stab)
{
    extern __shared__ char smc[];
    const uint32_t sb = smem_u32g(smc);
    float* Asf = (float*)(smc + FXP_ASF);
    float* sqs = (float*)(smc + FXP_SQS);
    float* red = (float*)(smc + FXP_RED);

    const float DN = 0.35355339059327373f;
    const int blk = blockIdx.x, hy = blockIdx.y, b = blockIdx.z;
    const bool isq = (hy < NH);
    const int h = isq ? hy : hy - NH;
    const int xcol = isq ? (h * 64) : (2048 + h * 64);
    const int s0 = blk * 64;
    const int tid = threadIdx.x;
    const int warp = tid >> 5, lane = tid & 31;
    const int gid = lane >> 2, tig = lane & 3;

#pragma unroll
    for (int i = 0; i < 16; i++) {
        const uint32_t off = (uint32_t)(tid * 16 + i * 4096);
        CP_ASYNC16(sb + off, projimg + off);
    }
    CP_COMMIT();

#pragma unroll
    for (int r = 0; r < 4; r++) {
        int l = tid + r * 256;
        int tok = l >> 4, q4 = (l & 15) << 2;
        float4 vv = *(const float4*)(x + (size_t)(b * S_LEN + s0 + tok) * QKVW + xcol + q4);
        Asf[tok * 68 + q4 + 0] = vv.x * DN;
        Asf[tok * 68 + q4 + 1] = vv.y * DN;
        Asf[tok * 68 + q4 + 2] = vv.z * DN;
        Asf[tok * 68 + q4 + 3] = vv.w * DN;
    }
    __syncthreads();

#pragma unroll
    for (int r = 0; r < 8; r++) {
        int idx = tid + r * 256;
        int tok = idx >> 5, p = idx & 31;
        const size_t crow = (size_t)(b * S_LEN + s0 + tok) * 64;
        const float c1 = cosp[crow + p],      sn1 = sinp[crow + p];
        const float c2 = cosp[crow + 32 + p], sn2 = sinp[crow + 32 + p];
        float a  = Asf[tok * 68 + p];
        float b2 = Asf[tok * 68 + p + 32];
        Asf[tok * 68 + p]      = a * c1 - b2 * sn1;
        Asf[tok * 68 + p + 32] = b2 * c2 + a * sn2;
    }
    __syncthreads();

    if (tid < 64) {
        float ssum = 0.f;
#pragma unroll
        for (int d = 0; d < 64; d++) { float vv = Asf[tid * 68 + d]; ssum += vv * vv; }
        sqs[tid] = 0.5f * ssum;
        if (!isq) sqk[((size_t)(b * NKV + h)) * S_LEN + s0 + tid] = 0.5f * ssum;
    }
#pragma unroll
    for (int r = 0; r < 2; r++) {
        int s = tid + r * 256;
        int row = s >> 3, g = s & 7;
        int chunk = g >> 2, slot = g & 3;
        float f[8];
        *(float4*)&f[0] = *(const float4*)(Asf + row * 68 + g * 8);
        *(float4*)&f[4] = *(const float4*)(Asf + row * 68 + g * 8 + 4);
        uint4 hv, lv;
        pack8(f, hv, lv);
        const uint32_t off = (uint32_t)(row * 64 + ((slot ^ ((row >> 1) & 3)) * 16));
        *(uint4*)(smc + FXP_A + chunk * 4096 + off)        = hv;
        *(uint4*)(smc + FXP_A + 8192 + chunk * 4096 + off) = lv;
    }
    CP_WAIT(0);
    __syncthreads();

    const int wm = (warp & 1) * 32;
    const int wn = (warp >> 1) * 64;
    const int swm   = ((lane & 7) >> 1) & 3;
    const int rlocA = (lane & 7) + (((lane >> 3) & 1) << 3);
    const int shA   = lane >> 4;
    const int rlocB = (lane & 7) + ((lane >> 4) << 3);
    const int shB   = (lane >> 3) & 1;

    float acc[2][8][4];
#pragma unroll
    for (int i = 0; i < 2; i++)
#pragma unroll
        for (int j = 0; j < 8; j++)
#pragma unroll
            for (int r = 0; r < 4; r++) acc[i][j][r] = 0.f;

#pragma unroll
    for (int ks = 0; ks < 4; ks++) {
        const int chunk = ks >> 1, kb = ks & 1;
        const uint32_t aBase = sb + FXP_A + chunk * 4096;
        const uint32_t bBase = sb + chunk * 16384;
        uint32_t ah[2][4], al[2][4];
#pragma unroll
        for (int tm = 0; tm < 2; tm++) {
            const int r = wm + tm * 16 + rlocA;
            const uint32_t off = (uint32_t)(r * 64 + (((2 * kb + shA) ^ swm) * 16));
            LDSM4(ah[tm], aBase + off);
            LDSM4(al[tm], aBase + 8192 + off);
        }
        uint32_t bhf[4][4], blf[4][4];
#pragma unroll
        for (int p = 0; p < 4; p++) {
            const int r = wn + p * 16 + rlocB;
            const uint32_t off = (uint32_t)(r * 64 + (((2 * kb + shB) ^ swm) * 16));
            LDSM4(bhf[p], bBase + off);
            LDSM4(blf[p], bBase + 32768 + off);
        }
#pragma unroll
        for (int tm = 0; tm < 2; tm++)
#pragma unroll
            for (int tn = 0; tn < 8; tn++) {
                const uint32_t* bh2 = &bhf[tn >> 1][(tn & 1) * 2];
                const uint32_t* bl2 = &blf[tn >> 1][(tn & 1) * 2];
                mma_bf16(acc[tm][tn], ah[tm], bh2);
                mma_bf16(acc[tm][tn], ah[tm], bl2);
                mma_bf16(acc[tm][tn], al[tm], bh2);
            }
    }

    if (isq) {
#pragma unroll
        for (int tm = 0; tm < 2; tm++) {
            float m0 = -3.4e38f, m1 = -3.4e38f;
#pragma unroll
            for (int tn = 0; tn < 8; tn++) {
                m0 = fmaxf(m0, fmaxf(acc[tm][tn][0], acc[tm][tn][1]));
                m1 = fmaxf(m1, fmaxf(acc[tm][tn][2], acc[tm][tn][3]));
            }
#pragma unroll
            for (int o = 1; o <= 2; o <<= 1) {
                m0 = fmaxf(m0, __shfl_xor_sync(0xffffffffu, m0, o));
                m1 = fmaxf(m1, __shfl_xor_sync(0xffffffffu, m1, o));
            }
            if (tig == 0) {
                red[(wm + tm * 16 + gid) * 4 + (warp >> 1)]     = m0;
                red[(wm + tm * 16 + gid + 8) * 4 + (warp >> 1)] = m1;
            }
        }
        __syncthreads();
        const size_t rowbase = (size_t)(b * NH + h) * S_LEN + s0;
#pragma unroll
        for (int tm = 0; tm < 2; tm++) {
            const int r0 = wm + tm * 16 + gid, r1 = r0 + 8;
            const float m0 = fmaxf(fmaxf(red[r0 * 4], red[r0 * 4 + 1]),
                                   fmaxf(red[r0 * 4 + 2], red[r0 * 4 + 3]));
            const float m1 = fmaxf(fmaxf(red[r1 * 4], red[r1 * 4 + 1]),
                                   fmaxf(red[r1 * 4 + 2], red[r1 * 4 + 3]));
            const float s0v = sqs[r0] + m0, s1v = sqs[r1] + m1;
#pragma unroll
            for (int tn = 0; tn < 8; tn++) {
                const int col = wn + tn * 8 + tig * 2;
                float e0 = (__expf(acc[tm][tn][0] - s0v) + 1e-6f) * 0.0625f;
                float e1 = (__expf(acc[tm][tn][1] - s0v) + 1e-6f) * 0.0625f;
                float e2 = (__expf(acc[tm][tn][2] - s1v) + 1e-6f) * 0.0625f;
                float e3 = (__expf(acc[tm][tn][3] - s1v) + 1e-6f) * 0.0625f;
                uint32_t u0 = __float_as_uint(e0), u1 = __float_as_uint(e1);
                uint32_t h01 = __byte_perm(u0, u1, 0x7632), l01;
                float q0 = e0 - __uint_as_float(u0 & 0xFFFF0000u);
                float q1 = e1 - __uint_as_float(u1 & 0xFFFF0000u);
                asm("cvt.rn.bf16x2.f32 %0, %1, %2;" : "=r"(l01) : "f"(q1), "f"(q0));
                uint32_t u2 = __float_as_uint(e2), u3 = __float_as_uint(e3);
                uint32_t h23 = __byte_perm(u2, u3, 0x7632), l23;
                float q2 = e2 - __uint_as_float(u2 & 0xFFFF0000u);
                float q3 = e3 - __uint_as_float(u3 & 0xFFFF0000u);
                asm("cvt.rn.bf16x2.f32 %0, %1, %2;" : "=r"(l23) : "f"(q3), "f"(q2));
                *(uint32_t*)(pqh + (rowbase + r0) * M_FEAT + col) = h01;
                *(uint32_t*)(pql + (rowbase + r0) * M_FEAT + col) = l01;
                *(uint32_t*)(pqh + (rowbase + r1) * M_FEAT + col) = h23;
                *(uint32_t*)(pql + (rowbase + r1) * M_FEAT + col) = l23;
            }
        }
    } else {
        const size_t rowbase = (size_t)(b * NKV + h) * S_LEN + s0;
        float mx = -3.4e38f;
#pragma unroll
        for (int tm = 0; tm < 2; tm++) {
            const int r0 = wm + tm * 16 + gid, r1 = r0 + 8;
#pragma unroll
            for (int tn = 0; tn < 8; tn++) {
                const int col = wn + tn * 8 + tig * 2;
                *(float2*)(xpk + (rowbase + r0) * M_FEAT + col) =
                    make_float2(acc[tm][tn][0], acc[tm][tn][1]);
                *(float2*)(xpk + (rowbase + r1) * M_FEAT + col) =
                    make_float2(acc[tm][tn][2], acc[tm][tn][3]);
                mx = fmaxf(mx, fmaxf(fmaxf(acc[tm][tn][0], acc[tm][tn][1]),
                                     fmaxf(acc[tm][tn][2], acc[tm][tn][3])));
            }
        }
        red[tid] = mx;
        __syncthreads();
        for (int st = 128; st > 0; st >>= 1) {
            if (tid < st) red[tid] = fmaxf(red[tid], red[tid + st]);
            __syncthreads();
        }
        if (tid == 0) atomicMaxFloat(&stab[b * NKV + h], red[0]);
    }
}

// ------- per-chunk kv/kz with fused k-exp + phi_k hi/lo output. grid (NC,NKV,B) -----
__global__ __launch_bounds__(256) void kv_chunk(const float* __restrict__ xpk,
                                                const float* __restrict__ sqk,
                                                const float* __restrict__ stab,
                                                __nv_bfloat16* __restrict__ pkh,
                                                __nv_bfloat16* __restrict__ pkl,
                                                const float* __restrict__ qkv,
                                                float* __restrict__ kv,
                                                float* __restrict__ kz)
{
    __shared__ float ps[16][256];
    __shared__ float vs[16][64];
    const int c = blockIdx.x, h = blockIdx.y, b = blockIdx.z;
    const int tid = threadIdx.x;
    const float stabv = stab[b * NKV + h];
    float acc[64];
#pragma unroll
    for (int d = 0; d < 64; d++) acc[d] = 0.f;
    float accz = 0.f;
    const size_t prow = (size_t)(b * NKV + h) * S_LEN + c * CHUNK;
    const size_t vrow = (size_t)b * S_LEN + c * CHUNK;

    for (int i0 = 0; i0 < CHUNK; i0 += 16) {
#pragma unroll
        for (int ii = 0; ii < 16; ii++) {
            const size_t idx = (prow + i0 + ii) * M_FEAT + tid;
            const float sqv = sqk[prow + i0 + ii];
            const float v = (__expf(xpk[idx] - sqv - stabv) + 1e-6f) * 0.0625f;
            ps[ii][tid] = v;
            const uint32_t u = __float_as_uint(v);
            const float t = __uint_as_float(u & 0xFFFF0000u);
            pkh[idx] = __ushort_as_bfloat16((unsigned short)(u >> 16));
            pkl[idx] = __float2bfloat16(v - t);
        }
#pragma unroll
        for (int j = 0; j < 4; j++) {
            int l = tid + j * 256;
            int ii = l >> 6, d = l & 63;
            vs[ii][d] = qkv[(vrow + i0 + ii) * QKVW + 2560 + h * 64 + d];
        }
        __syncthreads();
#pragma unroll
        for (int ii = 0; ii < 16; ii++) {
            float a = ps[ii][tid];
            accz += a;
#pragma unroll
            for (int d4 = 0; d4 < 64; d4 += 4) {
                float4 vv = *(const float4*)&vs[ii][d4];
                acc[d4 + 0] += a * vv.x; acc[d4 + 1] += a * vv.y;
                acc[d4 + 2] += a * vv.z; acc[d4 + 3] += a * vv.w;
            }
        }
        __syncthreads();
    }
    const size_t ob = (((size_t)(b * NKV + h) * NC + c) * M_FEAT + tid) * D_HEAD;
#pragma unroll
    for (int d4 = 0; d4 < 64; d4 += 4)
        *(float4*)(kv + ob + d4) = make_float4(acc[d4], acc[d4 + 1], acc[d4 + 2], acc[d4 + 3]);
    kz[((size_t)(b * NKV + h) * NC + c) * M_FEAT + tid] = accz;
}

// ---------------- exclusive prefix over chunk axis, in place ----------------------
__global__ void cumsum_k(float* __restrict__ kv, float* __restrict__ kz)
{
    const int tid = blockIdx.x * blockDim.x + threadIdx.x;
    const int KVSZ = M_FEAT * D_HEAD;
    if (tid < B_SZ * NKV * KVSZ) {
        int bh = tid / KVSZ, md = tid % KVSZ;
        float run = 0.f;
        for (int c = 0; c < NC; c++) {
            size_t idx = ((size_t)bh * NC + c) * KVSZ + md;
            float t = kv[idx]; kv[idx] = run; run += t;
        }
    } else {
        int t2 = tid - B_SZ * NKV * KVSZ;
        if (t2 < B_SZ * NKV * M_FEAT) {
            int bh = t2 / M_FEAT, m = t2 % M_FEAT;
            float run = 0.f;
            for (int c = 0; c < NC; c++) {
                size_t idx = ((size_t)bh * NC + c) * M_FEAT + m;
                float tz = kz[idx]; kz[idx] = run; run += tz;
            }
        }
    }
}

// ============ tensor-core chunked causal linear attention. grid (NC, NH, B) ========
#define SPITCH 132
#define ATT_AB0 (128 * SPITCH * 4)
#define ATT_AB1 (ATT_AB0 + 32768)
#define ATT_ZS  (ATT_AB1 + 32768)
#define SMEM_ATTN (ATT_ZS + 512)

__global__ __launch_bounds__(256, 1) void attn_tc(
    const __nv_bfloat16* __restrict__ pqh, const __nv_bfloat16* __restrict__ pql,
    const __nv_bfloat16* __restrict__ pkh, const __nv_bfloat16* __restrict__ pkl,
    const float* __restrict__ qkv, const float* __restrict__ kvpre,
    const float* __restrict__ kzpre,
    __nv_bfloat16* __restrict__ ath, __nv_bfloat16* __restrict__ atl)
{
    extern __shared__ float sm[];
    char* smcb = (char*)sm;
    float* Ss = sm;
    float* Zs = (float*)(smcb + ATT_ZS);
    const uint32_t sbase = smem_u32g(smcb);
    const uint32_t ab0 = sbase + ATT_AB0;
    const uint32_t ab1 = sbase + ATT_AB1;

    const int c = blockIdx.x, h = blockIdx.y, b = blockIdx.z;
    const int kvh = h >> 2;
    const int tid = threadIdx.x;
    const int warp = tid >> 5, lane = tid & 31;
    const int gid = lane >> 2, tig = lane & 3;

    const size_t qbase  = (size_t)(b * NH + h) * S_LEN + c * CHUNK;
    const size_t kbase  = (size_t)(b * NKV + kvh) * S_LEN + c * CHUNK;
    const size_t vrow0  = (size_t)b * S_LEN + c * CHUNK;
    const size_t kvbase = ((size_t)(b * NKV + kvh) * NC + c) * (size_t)(M_FEAT * D_HEAD);
    const size_t kzbase = ((size_t)(b * NKV + kvh) * NC + c) * M_FEAT;

    const int strow = tid & 127;
    const int s0 = tid >> 7;

    const int swm   = ((lane & 7) >> 1) & 3;
    const int rlocA = (lane & 7) + (((lane >> 3) & 1) << 3);
    const int shA   = lane >> 4;
    const int rlocB = (lane & 7) + ((lane >> 4) << 3);
    const int shB   = (lane >> 3) & 1;

    // ======================= Phase 1: scores (cp.async double-buffered) ============
    {
        const int wm = (warp & 1) * 64, wn = (warp >> 1) * 32;
        const bool live1 = (wn < wm + 64);   // tiles with all cols > all rows are masked to 0
        float acc[4][4][4];
#pragma unroll
        for (int i = 0; i < 4; i++)
#pragma unroll
            for (int j = 0; j < 4; j++)
#pragma unroll
                for (int r = 0; r < 4; r++) acc[i][j][r] = 0.f;

        auto stage1 = [&](int m0, uint32_t bb) {
#pragma unroll
            for (int si = 0; si < 2; si++) {
                const int s = s0 + si * 2;
                const uint32_t off = (uint32_t)(strow * 64 + ((s ^ ((strow >> 1) & 3)) * 16));
                const size_t ia = (qbase + strow) * M_FEAT + m0 + s * 8;
                const size_t ib = (kbase + strow) * M_FEAT + m0 + s * 8;
                CP_ASYNC16(bb + off,         (const char*)(pqh + ia));
                CP_ASYNC16(bb + 8192  + off, (const char*)(pql + ia));
                CP_ASYNC16(bb + 16384 + off, (const char*)(pkh + ib));
                CP_ASYNC16(bb + 24576 + off, (const char*)(pkl + ib));
            }
            CP_COMMIT();
        };

        stage1(0, ab0);
        for (int t = 0; t < 8; t++) {
            if (t + 1 < 8) {
                stage1((t + 1) * 32, (t + 1) & 1 ? ab1 : ab0);
                CP_WAIT(1);
            } else {
                CP_WAIT(0);
            }
            __syncthreads();
            const uint32_t bb = (t & 1) ? ab1 : ab0;
            if (live1) {
#pragma unroll
                for (int kb = 0; kb < 2; kb++) {
                    uint32_t ah[4][4], al[4][4];
#pragma unroll
                    for (int tm = 0; tm < 4; tm++) {
                        const int r = wm + tm * 16 + rlocA;
                        const uint32_t off = (uint32_t)(r * 64 + (((2 * kb + shA) ^ swm) * 16));
                        LDSM4(ah[tm], bb + off);
                        LDSM4(al[tm], bb + 8192 + off);
                    }
                    uint32_t bhf[2][4], blf[2][4];
#pragma unroll
                    for (int p = 0; p < 2; p++) {
                        const int r = wn + p * 16 + rlocB;
                        const uint32_t off = (uint32_t)(r * 64 + (((2 * kb + shB) ^ swm) * 16));
                        LDSM4(bhf[p], bb + 16384 + off);
                        LDSM4(blf[p], bb + 24576 + off);
                    }
#pragma unroll
                    for (int tm = 0; tm < 4; tm++)
#pragma unroll
                        for (int tn = 0; tn < 4; tn++) {
                            const uint32_t* bh2 = &bhf[tn >> 1][(tn & 1) * 2];
                            const uint32_t* bl2 = &blf[tn >> 1][(tn & 1) * 2];
                            mma_bf16(acc[tm][tn], ah[tm], bh2);
                            mma_bf16(acc[tm][tn], ah[tm], bl2);
                            mma_bf16(acc[tm][tn], al[tm], bh2);
                        }
                }
            }
            __syncthreads();
        }
#pragma unroll
        for (int tm = 0; tm < 4; tm++) {
            const int r0 = wm + tm * 16 + gid;
            const int r1 = r0 + 8;
#pragma unroll
            for (int tn = 0; tn < 4; tn++) {
                const int col = wn + tn * 8 + tig * 2;
                Ss[r0 * SPITCH + col]     = (col     <= r0) ? acc[tm][tn][0] : 0.f;
                Ss[r0 * SPITCH + col + 1] = (col + 1 <= r0) ? acc[tm][tn][1] : 0.f;
                Ss[r1 * SPITCH + col]     = (col     <= r1) ? acc[tm][tn][2] : 0.f;
                Ss[r1 * SPITCH + col + 1] = (col + 1 <= r1) ? acc[tm][tn][3] : 0.f;
            }
        }
    }
    __syncthreads();

    // ======== Phase 2: inter+intra (+z col 64), register-prefetch pipelined ========
    const int wm2 = (warp & 3) * 32, wn2 = (warp >> 2) * 40;
    float acc2[2][5][4];
#pragma unroll
    for (int i = 0; i < 2; i++)
#pragma unroll
        for (int j = 0; j < 5; j++)
#pragma unroll
            for (int r = 0; r < 4; r++) acc2[i][j][r] = 0.f;

    uint4 pA[4];
    float gB[2][8];

    auto p2_prefetch = [&](int cc) {
#pragma unroll
        for (int si = 0; si < 2; si++) {
            const int s = s0 + si * 2;
            if (cc < 8) {
                const size_t ia = (qbase + strow) * M_FEAT + cc * 32 + s * 8;
                pA[si * 2]     = *(const uint4*)(pqh + ia);
                pA[si * 2 + 1] = *(const uint4*)(pql + ia);
            }
            if (strow < 96) {
                if (strow < 64) {
                    if (cc < 8) {
#pragma unroll
                        for (int e = 0; e < 8; e++)
                            gB[si][e] = kvpre[kvbase + (size_t)(cc * 32 + s * 8 + e) * 64 + strow];
                    } else {
#pragma unroll
                        for (int e = 0; e < 8; e++)
                            gB[si][e] = qkv[(vrow0 + (cc - 8) * 32 + s * 8 + e) * QKVW + 2560 + kvh * 64 + strow];
                    }
                } else if (strow == 64) {
                    if (cc < 8) {
#pragma unroll
                        for (int e = 0; e < 8; e++)
                            gB[si][e] = kzpre[kzbase + cc * 32 + s * 8 + e];
                    } else {
#pragma unroll
                        for (int e = 0; e < 8; e++) gB[si][e] = 1.f;
                    }
                } else {
#pragma unroll
                    for (int e = 0; e < 8; e++) gB[si][e] = 0.f;
                }
            }
        }
    };
    auto p2_commit = [&](int cc, char* bufc) {
#pragma unroll
        for (int si = 0; si < 2; si++) {
            const int s = s0 + si * 2;
            const uint32_t off = (uint32_t)(strow * 64 + ((s ^ ((strow >> 1) & 3)) * 16));
            if (cc < 8) {
                *(uint4*)(bufc + off)        = pA[si * 2];
                *(uint4*)(bufc + 8192 + off) = pA[si * 2 + 1];
            } else {
                float f[8];
                const float* pa = Ss + strow * SPITCH + (cc - 8) * 32 + s * 8;
                *(float4*)&f[0] = *(const float4*)pa;
                *(float4*)&f[4] = *(const float4*)(pa + 4);
                uint4 hv, lv;
                pack8(f, hv, lv);
                *(uint4*)(bufc + off)        = hv;
                *(uint4*)(bufc + 8192 + off) = lv;
            }
            if (strow < 96) {
                uint4 hv, lv;
                pack8(gB[si], hv, lv);
                *(uint4*)(bufc + 16384 + off) = hv;
                *(uint4*)(bufc + 24576 + off) = lv;
            }
        }
    };

    p2_prefetch(0);
    for (int cc = 0; cc < 12; cc++) {
        char* bufc = smcb + ((cc & 1) ? ATT_AB1 : ATT_AB0);
        const uint32_t bb = (cc & 1) ? ab1 : ab0;
        p2_commit(cc, bufc);
        if (cc + 1 < 12) p2_prefetch(cc + 1);
        __syncthreads();
#pragma unroll
        for (int kb = 0; kb < 2; kb++) {
            uint32_t ah2[2][4], al2[2][4], bh2[3][4], bl2[3][4];
#pragma unroll
            for (int tm = 0; tm < 2; tm++) {
                const int r = wm2 + tm * 16 + rlocA;
                const uint32_t off = (uint32_t)(r * 64 + (((2 * kb + shA) ^ swm) * 16));
                LDSM4(ah2[tm], bb + off);
                LDSM4(al2[tm], bb + 8192 + off);
            }
#pragma unroll
            for (int p = 0; p < 3; p++) {
                const int r = wn2 + p * 16 + rlocB;
                const uint32_t off = (uint32_t)(r * 64 + (((2 * kb + shB) ^ swm) * 16));
                LDSM4(bh2[p], bb + 16384 + off);
                LDSM4(bl2[p], bb + 24576 + off);
            }
#pragma unroll
            for (int tm = 0; tm < 2; tm++)
#pragma unroll
                for (int tn = 0; tn < 5; tn++) {
                    const uint32_t* bh_ = &bh2[tn >> 1][(tn & 1) * 2];
                    const uint32_t* bl_ = &bl2[tn >> 1][(tn & 1) * 2];
                    mma_bf16(acc2[tm][tn], ah2[tm], bh_);
                    mma_bf16(acc2[tm][tn], ah2[tm], bl_);
                    mma_bf16(acc2[tm][tn], al2[tm], bh_);
                }
        }
    }
    __syncthreads();

    if ((warp >> 2) == 1 && tig == 0) {
#pragma unroll
        for (int tm = 0; tm < 2; tm++) {
            const int r = wm2 + tm * 16 + gid;
            Zs[r]     = acc2[tm][3][0];
            Zs[r + 8] = acc2[tm][3][2];
        }
    }
    __syncthreads();

#pragma unroll
    for (int tm = 0; tm < 2; tm++) {
        const int r = wm2 + tm * 16 + gid;
        const float d0 = 1.f / (Zs[r] + 1e-6f);
        const float d1 = 1.f / (Zs[r + 8] + 1e-6f);
#pragma unroll
        for (int tn = 0; tn < 5; tn++) {
            const int col = wn2 + tn * 8 + tig * 2;
            if (col < 64) {
                const size_t ro = ((size_t)b * S_LEN + c * CHUNK + r) * (NH * D_HEAD) + h * 64 + col;
                const size_t ro8 = ro + 8 * (NH * D_HEAD);
                float o0 = acc2[tm][tn][0] * d0, o1 = acc2[tm][tn][1] * d0;
                float o2 = acc2[tm][tn][2] * d1, o3 = acc2[tm][tn][3] * d1;
                __nv_bfloat16 h0 = __float2bfloat16(o0), h1 = __float2bfloat16(o1);
                __nv_bfloat16 h2 = __float2bfloat16(o2), h3 = __float2bfloat16(o3);
                *(__nv_bfloat162*)(ath + ro)  = __nv_bfloat162(h0, h1);
                *(__nv_bfloat162*)(ath + ro8) = __nv_bfloat162(h2, h3);
                *(__nv_bfloat162*)(atl + ro)  =
                    __nv_bfloat162(__float2bfloat16(o0 - __bfloat162float(h0)),
                                   __float2bfloat16(o1 - __bfloat162float(h1)));
                *(__nv_bfloat162*)(atl + ro8) =
                    __nv_bfloat162(__float2bfloat16(o2 - __bfloat162float(h2)),
                                   __float2bfloat16(o3 - __bfloat162float(h3)));
            }
        }
    }
}

// ----------------------------------- launch ---------------------------------------
extern "C" void kernel_launch(void* const* d_in, const int* in_sizes, int n_in,
                              void* d_out, int out_size)
{
    const float* hs   = (const float*)d_in[0];
    const float* cosp = (const float*)d_in[1];
    const float* sinp = (const float*)d_in[2];
    const float* Wq   = (const float*)d_in[3];
    const float* Wk   = (const float*)d_in[4];
    const float* Wv   = (const float*)d_in[5];
    const float* Wo   = (const float*)d_in[6];
    const float* proj = (const float*)d_in[7];
    float* out = (float*)d_out;

    float *qkvp, *xpkp, *sqkp, *stabp, *kvp, *kzp;
    cudaGetSymbolAddress((void**)&qkvp,  g_qkv);
    cudaGetSymbolAddress((void**)&xpkp,  g_xpk);
    cudaGetSymbolAddress((void**)&sqkp,  g_sqk);
    cudaGetSymbolAddress((void**)&stabp, g_stab);
    cudaGetSymbolAddress((void**)&kvp,   g_kv);
    cudaGetSymbolAddress((void**)&kzp,   g_kz);
    char* pimg;
    cudaGetSymbolAddress((void**)&pimg, g_projimg);

    __nv_bfloat16 *pqh, *pql, *pkh, *pkl, *hsh, *hsl, *ath, *atl, *wh, *wl;
    cudaGetSymbolAddress((void**)&pqh, g_pqh);
    cudaGetSymbolAddress((void**)&pql, g_pql);
    cudaGetSymbolAddress((void**)&pkh, g_pkh);
    cudaGetSymbolAddress((void**)&pkl, g_pkl);
    cudaGetSymbolAddress((void**)&hsh, g_hsh);
    cudaGetSymbolAddress((void**)&hsl, g_hsl);
    cudaGetSymbolAddress((void**)&ath, g_ath);
    cudaGetSymbolAddress((void**)&atl, g_atl);
    cudaGetSymbolAddress((void**)&wh,  g_wh);
    cudaGetSymbolAddress((void**)&wl,  g_wl);

    cudaFuncSetAttribute(gemm_bf16x3, cudaFuncAttributeMaxDynamicSharedMemorySize, SMEM_GEMM);
    cudaFuncSetAttribute(attn_tc, cudaFuncAttributeMaxDynamicSharedMemorySize, SMEM_ATTN);
    cudaFuncSetAttribute(favor_xp_tc, cudaFuncAttributeMaxDynamicSharedMemorySize, SMEM_FXP);

    // ---- splits + proj image ----
    split_bf16<<<(HS_ELEMS / 4 + 255) / 256, 256>>>(hs, hsh, hsl, HS_ELEMS / 4);
    split_bf16<<<(HID_ * HID_ / 4 + 255) / 256, 256>>>(Wq, wh + WQ_OFF, wl + WQ_OFF, HID_ * HID_ / 4);
    split_bf16<<<(512 * HID_ / 4 + 255) / 256, 256>>>(Wk, wh + WK_OFF, wl + WK_OFF, 512 * HID_ / 4);
    split_bf16<<<(512 * HID_ / 4 + 255) / 256, 256>>>(Wv, wh + WV_OFF, wl + WV_OFF, 512 * HID_ / 4);
    split_bf16<<<(HID_ * HID_ / 4 + 255) / 256, 256>>>(Wo, wh + WO_OFF, wl + WO_OFF, HID_ * HID_ / 4);
    prep_proj<<<8, 256>>>(proj, pimg);

    // ---- fused QKV projection (3-stage pipeline) ----
    gemm_bf16x3<<<dim3(QKVW / 128, 32), 256, SMEM_GEMM>>>(hsh, hsl, wh, wl, qkvp, QKVW);

    // ---- favor features on tensor cores (q+k merged, RoPE fused) ----
    init_stab_kernel<<<1, 32>>>(stabp);
    favor_xp_tc<<<dim3(S_LEN / 64, NH + NKV, B_SZ), 256, SMEM_FXP>>>(
        qkvp, cosp, sinp, pimg, xpkp, pqh, pql, sqkp, stabp);

    // ---- chunked linear attention ----
    kv_chunk<<<dim3(NC, NKV, B_SZ), 256>>>(xpkp, sqkp, stabp, pkh, pkl, qkvp, kvp, kzp);
    cumsum_k<<<(B_SZ * NKV * (M_FEAT * D_HEAD + M_FEAT) + 255) / 256, 256>>>(kvp, kzp);
    attn_tc<<<dim3(NC, NH, B_SZ), 256, SMEM_ATTN>>>(pqh, pql, pkh, pkl, qkvp, kvp, kzp, ath, atl);

    // ---- output projection (3-stage pipeline) ----
    gemm_bf16x3<<<dim3(16, 32), 256, SMEM_GEMM>>>(ath, atl, wh + WO_OFF, wl + WO_OFF, out, 2048);
}